// round 10
// baseline (speedup 1.0000x reference)
#include <cuda_runtime.h>
#include <cuda_bf16.h>
#include <math.h>
#include <stdint.h>

#define DIMX 160
#define EPSF 1e-5f
#define INV_SQ3 0.57735026918962576451f
#define MAX_NODES 50000
#define MAX_ACT 200000

typedef unsigned long long u64;

// ---------- scratch ----------
__device__ float g_nf[MAX_NODES * DIMX];
__device__ float g_ms[MAX_ACT * 64];
__device__ float g_mv[MAX_ACT * 96];
__device__ float g_lat_in[MAX_ACT * 232];
__device__ __align__(16) __nv_bfloat16 g_hidh[(size_t)MAX_ACT * 256];
__device__ __align__(16) __nv_bfloat16 g_hidl[(size_t)MAX_ACT * 256];

__device__ __forceinline__ float wsum(float v) {
#pragma unroll
    for (int o = 16; o > 0; o >>= 1) v += __shfl_xor_sync(0xffffffffu, v, o);
    return v;
}
__device__ __forceinline__ float sigm(float x) { return 1.f / (1.f + expf(-x)); }
__device__ __forceinline__ void ffma2(u64& a, u64 x, u64 w) {
    asm("fma.rn.f32x2 %0, %1, %2, %0;" : "+l"(a) : "l"(x), "l"(w));
}
__device__ __forceinline__ float hadd2(u64 a) {
    return __uint_as_float((unsigned)a) + __uint_as_float((unsigned)(a >> 32));
}
__device__ __forceinline__ ulonglong2 ld2(const float* p) {
    return *reinterpret_cast<const ulonglong2*>(p);
}
__device__ __forceinline__ uint32_t s2u(const void* p) {
    uint32_t a;
    asm("{ .reg .u64 t; cvta.to.shared.u64 t, %1; cvt.u32.u64 %0, t; }" : "=r"(a) : "l"(p));
    return a;
}
__device__ __forceinline__ void mma16816(float* c, const uint32_t* a, const uint32_t* b) {
    asm volatile("mma.sync.aligned.m16n8k16.row.col.f32.bf16.bf16.f32 "
        "{%0,%1,%2,%3}, {%4,%5,%6,%7}, {%8,%9}, {%0,%1,%2,%3};"
        : "+f"(c[0]), "+f"(c[1]), "+f"(c[2]), "+f"(c[3])
        : "r"(a[0]), "r"(a[1]), "r"(a[2]), "r"(a[3]), "r"(b[0]), "r"(b[1]));
}
__device__ __forceinline__ void ldsm4(uint32_t* r, uint32_t a) {
    asm volatile("ldmatrix.sync.aligned.m8n8.x4.shared.b16 {%0,%1,%2,%3}, [%4];"
        : "=r"(r[0]), "=r"(r[1]), "=r"(r[2]), "=r"(r[3]) : "r"(a));
}
__device__ __forceinline__ void ldsm4t(uint32_t* r, uint32_t a) {
    asm volatile("ldmatrix.sync.aligned.m8n8.x4.trans.shared.b16 {%0,%1,%2,%3}, [%4];"
        : "=r"(r[0]), "=r"(r[1]), "=r"(r[2]), "=r"(r[3]) : "r"(a));
}
__device__ __forceinline__ void split2(float v0, float v1, uint32_t& hi, uint32_t& lo) {
    float h0 = __bfloat162float(__float2bfloat16(v0));
    float h1 = __bfloat162float(__float2bfloat16(v1));
    asm("cvt.rn.bf16x2.f32 %0, %1, %2;" : "=r"(hi) : "f"(v1), "f"(v0));
    float r0 = v0 - h0, r1 = v1 - h1;
    asm("cvt.rn.bf16x2.f32 %0, %1, %2;" : "=r"(lo) : "f"(r1), "f"(r0));
}

// ===================== K1: node SLN =====================
__global__ void k_node_norm(const float* __restrict__ nf, const float* __restrict__ gs,
                            const float* __restrict__ bs, const float* __restrict__ gv,
                            int n_nodes) {
    int w = (blockIdx.x * 256 + threadIdx.x) >> 5;
    int l = threadIdx.x & 31;
    if (w >= n_nodes) return;
    const float* r = nf + (size_t)w * DIMX;
    float s0 = r[l], s1 = r[32 + l];
    float mu = wsum(s0 + s1) * (1.f / 64.f);
    float m2 = wsum(s0 * s0 + s1 * s1) * (1.f / 64.f);
    float rsv = rsqrtf(m2 - mu * mu + EPSF);
    float v0 = r[64 + 3 * l], v1 = r[65 + 3 * l], v2 = r[66 + 3 * l];
    float rmi = rsqrtf(wsum(v0 * v0 + v1 * v1 + v2 * v2) * (1.f / 32.f) + EPSF);
    float* o = g_nf + (size_t)w * DIMX;
    o[l] = (s0 - mu) * rsv * gs[l] + bs[l];
    o[32 + l] = (s1 - mu) * rsv * gs[32 + l] + bs[32 + l];
    float gk = gv[l] * rmi;
    o[64 + 3 * l] = v0 * gk; o[65 + 3 * l] = v1 * gk; o[66 + 3 * l] = v2 * gk;
}

// ===================== K2a: gather + edge SLN + tensor product =====================
// 512 threads / 16 warps / EPW=2 -> 4 warps per SMSP (was 2)
#define EA_T 512
#define EA_W 16
#define EA_E 2
#define SMEM_A ((96*196 + 96*100 + 32*196 + 32*100 + EA_W*EA_E*576) * 4)
__global__ __launch_bounds__(EA_T, 1) void k_edge_a(
    const float* __restrict__ ef, const float* __restrict__ esh,
    const int* __restrict__ eidx, const int* __restrict__ act,
    const float* __restrict__ onehot,
    const float* __restrict__ egs, const float* __restrict__ ebs, const float* __restrict__ egv,
    const float* __restrict__ Wa, const float* __restrict__ Wb,
    const float* __restrict__ Wc, const float* __restrict__ Wd,
    int n_act, int n_edges) {
    extern __shared__ float sm[];
    float* WaT = sm;
    float* WbT = WaT + 96 * 196;
    float* WcT = WbT + 96 * 100;
    float* WdT = WcT + 32 * 196;
    float* STG = WdT + 32 * 100;
    int tid = threadIdx.x;
    for (int i = tid; i < 192 * 96; i += EA_T) WaT[(i % 96) * 196 + i / 96] = Wa[i];
    for (int i = tid; i < 96 * 96; i += EA_T)  WbT[(i % 96) * 100 + i / 96] = Wb[i];
    for (int i = tid; i < 192 * 32; i += EA_T) WcT[(i % 32) * 196 + i / 32] = Wc[i];
    for (int i = tid; i < 96 * 32; i += EA_T)  WdT[(i % 32) * 100 + i / 32] = Wd[i];
    __syncthreads();
    int wq = tid >> 5, l = tid & 31;
    float* ST = STG + wq * (EA_E * 576);
    int gw = blockIdx.x * EA_W + wq;
    int stride = gridDim.x * EA_W * EA_E;
    for (int eb = gw * EA_E; eb < n_act; eb += stride) {
        float sh0r[EA_E], s10[EA_E], s11[EA_E], s12[EA_E];
        int inode[EA_E], jnode[EA_E];
#pragma unroll
        for (int e = 0; e < EA_E; e++) {
            int ec = eb + e; if (ec >= n_act) ec = n_act - 1;
            int ae = act[ec];
            int ii = eidx[ae], jj = eidx[n_edges + ae];
            inode[e] = ii; jnode[e] = jj;
            float* sA = ST + e * 576;
            float* vA = sA + 192;
            float* u = sA + 480;
            const float* ri = g_nf + (size_t)ii * DIMX;
            sA[l] = ri[l]; sA[32 + l] = ri[32 + l];
            vA[l] = ri[64 + 3 * l]; vA[96 + l] = ri[65 + 3 * l]; vA[192 + l] = ri[66 + 3 * l];
            const float* rj = g_nf + (size_t)jj * DIMX;
            sA[128 + l] = rj[l]; sA[160 + l] = rj[32 + l];
            vA[64 + l] = rj[64 + 3 * l]; vA[160 + l] = rj[65 + 3 * l]; vA[256 + l] = rj[66 + 3 * l];
            const float* re = ef + (size_t)ec * DIMX;
            float s0 = re[l], s1 = re[32 + l];
            float mu = wsum(s0 + s1) * (1.f / 64.f);
            float m2 = wsum(s0 * s0 + s1 * s1) * (1.f / 64.f);
            float rsv = rsqrtf(m2 - mu * mu + EPSF);
            sA[64 + l] = (s0 - mu) * rsv * egs[l] + ebs[l];
            sA[96 + l] = (s1 - mu) * rsv * egs[32 + l] + ebs[32 + l];
            float v0 = re[64 + 3 * l], v1 = re[65 + 3 * l], v2 = re[66 + 3 * l];
            float rmi = rsqrtf(wsum(v0 * v0 + v1 * v1 + v2 * v2) * (1.f / 32.f) + EPSF);
            float gk = egv[l] * rmi;
            vA[32 + l] = v0 * gk; vA[128 + l] = v1 * gk; vA[224 + l] = v2 * gk;
            const float* sp = esh + (size_t)ec * 4;
            sh0r[e] = sp[0]; s10[e] = sp[1]; s11[e] = sp[2]; s12[e] = sp[3];
#pragma unroll
            for (int t = 0; t < 3; t++) {
                int k = l + 32 * t;
                u[k] = (vA[k] * s10[e] + vA[96 + k] * s11[e] + vA[192 + k] * s12[e]) * INV_SQ3;
            }
        }
        __syncwarp();
        u64 aA[3][EA_E];
#pragma unroll
        for (int j = 0; j < 3; j++)
#pragma unroll
            for (int e = 0; e < EA_E; e++) aA[j][e] = 0ull;
        for (int k = 0; k < 192; k += 4) {
            ulonglong2 w0 = ld2(&WaT[l * 196 + k]);
            ulonglong2 w1 = ld2(&WaT[(l + 32) * 196 + k]);
            ulonglong2 w2 = ld2(&WaT[(l + 64) * 196 + k]);
#pragma unroll
            for (int e = 0; e < EA_E; e++) {
                ulonglong2 x = ld2(&ST[e * 576 + k]);
                ffma2(aA[0][e], x.x, w0.x); ffma2(aA[0][e], x.y, w0.y);
                ffma2(aA[1][e], x.x, w1.x); ffma2(aA[1][e], x.y, w1.y);
                ffma2(aA[2][e], x.x, w2.x); ffma2(aA[2][e], x.y, w2.y);
            }
        }
        float fA[3][EA_E];
#pragma unroll
        for (int j = 0; j < 3; j++)
#pragma unroll
            for (int e = 0; e < EA_E; e++) fA[j][e] = hadd2(aA[j][e]);
        u64 aB[3][EA_E];
#pragma unroll
        for (int j = 0; j < 3; j++)
#pragma unroll
            for (int e = 0; e < EA_E; e++) aB[j][e] = 0ull;
        for (int k = 0; k < 96; k += 4) {
            ulonglong2 w0 = ld2(&WbT[l * 100 + k]);
            ulonglong2 w1 = ld2(&WbT[(l + 32) * 100 + k]);
            ulonglong2 w2 = ld2(&WbT[(l + 64) * 100 + k]);
#pragma unroll
            for (int e = 0; e < EA_E; e++) {
                ulonglong2 x = ld2(&ST[e * 576 + 480 + k]);
                ffma2(aB[0][e], x.x, w0.x); ffma2(aB[0][e], x.y, w0.y);
                ffma2(aB[1][e], x.x, w1.x); ffma2(aB[1][e], x.y, w1.y);
                ffma2(aB[2][e], x.x, w2.x); ffma2(aB[2][e], x.y, w2.y);
            }
        }
        float os[3][EA_E];
#pragma unroll
        for (int j = 0; j < 3; j++)
#pragma unroll
            for (int e = 0; e < EA_E; e++) os[j][e] = fmaf(sh0r[e], fA[j][e], hadd2(aB[j][e]));
        u64 swc[EA_E], wd[3][EA_E];
#pragma unroll
        for (int e = 0; e < EA_E; e++) { swc[e] = 0ull; wd[0][e] = 0ull; wd[1][e] = 0ull; wd[2][e] = 0ull; }
        for (int k = 0; k < 192; k += 4) {
            ulonglong2 w = ld2(&WcT[l * 196 + k]);
#pragma unroll
            for (int e = 0; e < EA_E; e++) {
                ulonglong2 x = ld2(&ST[e * 576 + k]);
                ffma2(swc[e], x.x, w.x); ffma2(swc[e], x.y, w.y);
            }
        }
        for (int k = 0; k < 96; k += 4) {
            ulonglong2 w = ld2(&WdT[l * 100 + k]);
#pragma unroll
            for (int e = 0; e < EA_E; e++) {
#pragma unroll
                for (int c = 0; c < 3; c++) {
                    ulonglong2 x = ld2(&ST[e * 576 + 192 + 96 * c + k]);
                    ffma2(wd[c][e], x.x, w.x); ffma2(wd[c][e], x.y, w.y);
                }
            }
        }
#pragma unroll
        for (int e = 0; e < EA_E; e++) {
            int eg = eb + e;
            if (eg < n_act) {
                float gate = sigm(os[2][e]);
                g_ms[(size_t)eg * 64 + l] = os[0][e] * sigm(os[0][e]);
                g_ms[(size_t)eg * 64 + 32 + l] = os[1][e] * sigm(os[1][e]);
                float s1c[3] = { s10[e], s11[e], s12[e] };
                float sw = hadd2(swc[e]);
#pragma unroll
                for (int c = 0; c < 3; c++) {
                    float ov = fmaf(sw, s1c[c], hadd2(wd[c][e]) * sh0r[e]);
                    g_mv[(size_t)eg * 96 + 3 * l + c] = ov * gate;
                }
                float* li = g_lat_in + (size_t)eg * 232;
                li[132 + l] = os[0][e]; li[164 + l] = os[1][e]; li[196 + l] = os[2][e];
                if (l < 4) { li[l] = onehot[inode[e] * 4 + l]; li[228 + l] = onehot[jnode[e] * 4 + l]; }
            }
        }
        __syncwarp();
    }
}

// ===================== K2b: W_edge / Wp / Wres + latent LN + edge_out =====================
#define EB_T 512
#define EB_W 16
#define EB_E 4
#define SMEM_B ((96*132 + 64*68 + 32*36 + 64*68 + 32*36 + EB_W*EB_E*448) * 4)
__global__ __launch_bounds__(EB_T, 1) void k_edge_b(
    const float* __restrict__ latents, const float* __restrict__ ef,
    const int* __restrict__ act,
    const float* __restrict__ lg, const float* __restrict__ lb,
    const float* __restrict__ We, const float* __restrict__ Wps, const float* __restrict__ Wpv,
    const float* __restrict__ Wrs, const float* __restrict__ Wrv,
    float* __restrict__ out_edge, int n_act) {
    extern __shared__ float sm[];
    float* WeT = sm;
    float* WpsT = WeT + 96 * 132;
    float* WpvT = WpsT + 64 * 68;
    float* WrsT = WpvT + 32 * 36;
    float* WrvT = WrsT + 64 * 68;
    float* STG = WrvT + 32 * 36;
    int tid = threadIdx.x;
    for (int i = tid; i < 128 * 96; i += EB_T) WeT[(i % 96) * 132 + i / 96] = We[i];
    for (int i = tid; i < 64 * 64; i += EB_T)  WpsT[(i % 64) * 68 + i / 64] = Wps[i];
    for (int i = tid; i < 32 * 32; i += EB_T)  WpvT[(i % 32) * 36 + i / 32] = Wpv[i];
    for (int i = tid; i < 64 * 64; i += EB_T)  WrsT[(i % 64) * 68 + i / 64] = Wrs[i];
    for (int i = tid; i < 32 * 32; i += EB_T)  WrvT[(i % 32) * 36 + i / 32] = Wrv[i];
    __syncthreads();
    int wq = tid >> 5, l = tid & 31;
    float* ST = STG + wq * (EB_E * 448);
    int gw = blockIdx.x * EB_W + wq;
    int stride = gridDim.x * EB_W * EB_E;
    for (int eb = gw * EB_E; eb < n_act; eb += stride) {
#pragma unroll
        for (int e = 0; e < EB_E; e++) {
            int ec = eb + e; if (ec >= n_act) ec = n_act - 1;
            int ae = act[ec];
            float* S = ST + e * 448;
            const float* la = latents + (size_t)ae * 128;
            float x0 = la[l], x1 = la[32 + l], x2 = la[64 + l], x3 = la[96 + l];
            S[l] = x0; S[32 + l] = x1; S[64 + l] = x2; S[96 + l] = x3;
            float mu = wsum(x0 + x1 + x2 + x3) * (1.f / 128.f);
            float m2 = wsum(x0 * x0 + x1 * x1 + x2 * x2 + x3 * x3) * (1.f / 128.f);
            float rsv = rsqrtf(m2 - mu * mu + EPSF);
            int eg = eb + e;
            if (eg < n_act) {
                float* li = g_lat_in + (size_t)eg * 232 + 4;
                li[l] = (x0 - mu) * rsv * lg[l] + lb[l];
                li[32 + l] = (x1 - mu) * rsv * lg[32 + l] + lb[32 + l];
                li[64 + l] = (x2 - mu) * rsv * lg[64 + l] + lb[64 + l];
                li[96 + l] = (x3 - mu) * rsv * lg[96 + l] + lb[96 + l];
            }
            const float* ms = g_ms + (size_t)ec * 64;
            S[128 + l] = ms[l]; S[160 + l] = ms[32 + l];
            const float* mv = g_mv + (size_t)ec * 96;
            S[192 + l] = mv[3 * l]; S[224 + l] = mv[3 * l + 1]; S[256 + l] = mv[3 * l + 2];
            const float* re = ef + (size_t)ec * DIMX;
            S[288 + l] = re[l]; S[320 + l] = re[32 + l];
            S[352 + l] = re[64 + 3 * l]; S[384 + l] = re[65 + 3 * l]; S[416 + l] = re[66 + 3 * l];
        }
        __syncwarp();
        u64 ww[3][EB_E];
#pragma unroll
        for (int j = 0; j < 3; j++)
#pragma unroll
            for (int e = 0; e < EB_E; e++) ww[j][e] = 0ull;
        for (int k = 0; k < 128; k += 4) {
            ulonglong2 w0 = ld2(&WeT[l * 132 + k]);
            ulonglong2 w1 = ld2(&WeT[(l + 32) * 132 + k]);
            ulonglong2 w2 = ld2(&WeT[(l + 64) * 132 + k]);
#pragma unroll
            for (int e = 0; e < EB_E; e++) {
                ulonglong2 x = ld2(&ST[e * 448 + k]);
                ffma2(ww[0][e], x.x, w0.x); ffma2(ww[0][e], x.y, w0.y);
                ffma2(ww[1][e], x.x, w1.x); ffma2(ww[1][e], x.y, w1.y);
                ffma2(ww[2][e], x.x, w2.x); ffma2(ww[2][e], x.y, w2.y);
            }
        }
        float fw[3][EB_E];
#pragma unroll
        for (int j = 0; j < 3; j++)
#pragma unroll
            for (int e = 0; e < EB_E; e++) fw[j][e] = hadd2(ww[j][e]);
        u64 ps[2][EB_E], rs[2][EB_E];
#pragma unroll
        for (int e = 0; e < EB_E; e++) { ps[0][e] = ps[1][e] = rs[0][e] = rs[1][e] = 0ull; }
        for (int k = 0; k < 64; k += 4) {
            ulonglong2 p0 = ld2(&WpsT[l * 68 + k]);
            ulonglong2 p1 = ld2(&WpsT[(l + 32) * 68 + k]);
            ulonglong2 r0 = ld2(&WrsT[l * 68 + k]);
            ulonglong2 r1 = ld2(&WrsT[(l + 32) * 68 + k]);
#pragma unroll
            for (int e = 0; e < EB_E; e++) {
                ulonglong2 xm = ld2(&ST[e * 448 + 128 + k]);
                ulonglong2 xr = ld2(&ST[e * 448 + 288 + k]);
                ffma2(ps[0][e], xm.x, p0.x); ffma2(ps[0][e], xm.y, p0.y);
                ffma2(ps[1][e], xm.x, p1.x); ffma2(ps[1][e], xm.y, p1.y);
                ffma2(rs[0][e], xr.x, r0.x); ffma2(rs[0][e], xr.y, r0.y);
                ffma2(rs[1][e], xr.x, r1.x); ffma2(rs[1][e], xr.y, r1.y);
            }
        }
        float fps[2][EB_E], frs[2][EB_E];
#pragma unroll
        for (int j = 0; j < 2; j++)
#pragma unroll
            for (int e = 0; e < EB_E; e++) { fps[j][e] = hadd2(ps[j][e]); frs[j][e] = hadd2(rs[j][e]); }
        u64 pv[3][EB_E], rv[3][EB_E];
#pragma unroll
        for (int c = 0; c < 3; c++)
#pragma unroll
            for (int e = 0; e < EB_E; e++) { pv[c][e] = 0ull; rv[c][e] = 0ull; }
        for (int k = 0; k < 32; k += 4) {
            ulonglong2 pw = ld2(&WpvT[l * 36 + k]);
            ulonglong2 rw = ld2(&WrvT[l * 36 + k]);
#pragma unroll
            for (int e = 0; e < EB_E; e++) {
#pragma unroll
                for (int c = 0; c < 3; c++) {
                    ulonglong2 xm = ld2(&ST[e * 448 + 192 + 32 * c + k]);
                    ulonglong2 xr = ld2(&ST[e * 448 + 352 + 32 * c + k]);
                    ffma2(pv[c][e], xm.x, pw.x); ffma2(pv[c][e], xm.y, pw.y);
                    ffma2(rv[c][e], xr.x, rw.x); ffma2(rv[c][e], xr.y, rw.y);
                }
            }
        }
#pragma unroll
        for (int e = 0; e < EB_E; e++) {
            int eg = eb + e;
            if (eg < n_act) {
                float* oe = out_edge + (size_t)eg * DIMX;
                oe[l] = fmaf(fps[0][e], fw[0][e], frs[0][e]);
                oe[32 + l] = fmaf(fps[1][e], fw[1][e], frs[1][e]);
#pragma unroll
                for (int c = 0; c < 3; c++)
                    oe[64 + 3 * l + c] = fmaf(hadd2(pv[c][e]), fw[2][e], hadd2(rv[c][e]));
            }
        }
        __syncwarp();
    }
}

// ===================== K3: GEMM1 hid = silu(lat_in @ W1), 512 threads =====================
#define M1_SMEM ((2 * 240 * 136 + 2 * 128 * 136) * 2)
__global__ __launch_bounds__(512, 1) void k_mma1(const float* __restrict__ W1, int n_act) {
    extern __shared__ __nv_bfloat16 sb[];
    __nv_bfloat16* Wh = sb;
    __nv_bfloat16* Wl = Wh + 240 * 136;
    __nv_bfloat16* Ah = Wl + 240 * 136;
    __nv_bfloat16* Al = Ah + 128 * 136;
    int tid = threadIdx.x, wid = tid >> 5, lane = tid & 31;
    int base = blockIdx.y * 128;
    for (int i = tid; i < 240 * 128; i += 512) {
        int k = i >> 7, n = i & 127;
        float w = (k < 232) ? W1[k * 256 + base + n] : 0.f;
        __nv_bfloat16 h = __float2bfloat16(w);
        Wh[k * 136 + n] = h;
        Wl[k * 136 + n] = __float2bfloat16(w - __bfloat162float(h));
    }
    uint32_t aWh = s2u(Wh), aWl = s2u(Wl), aAh = s2u(Ah), aAl = s2u(Al);
    int warp_m = wid & 7, warp_n = wid >> 3;
    int ntile = (n_act + 127) >> 7;
    for (int tile = blockIdx.x; tile < ntile; tile += gridDim.x) {
        float C[8][4];
#pragma unroll
        for (int b = 0; b < 8; b++)
#pragma unroll
            for (int c = 0; c < 4; c++) C[b][c] = 0.f;
#pragma unroll 1
        for (int chunk = 0; chunk < 2; chunk++) {
            int k0 = chunk * 128;
            int cw = chunk ? 112 : 128;
            int kw = chunk ? 104 : 128;
            int nks = chunk ? 7 : 8;
            __syncthreads();
            int c4 = lane * 4;
#pragma unroll
            for (int rr = 0; rr < 8; rr++) {
                int r = wid * 8 + rr;
                int eg = tile * 128 + r;
                int ec = eg < n_act ? eg : n_act - 1;
                const float* li = g_lat_in + (size_t)ec * 232 + k0;
                if (c4 < cw) {
                    float4 v;
                    if (c4 + 3 < kw) v = *(const float4*)(li + c4);
                    else {
                        v.x = (c4 + 0 < kw) ? li[c4 + 0] : 0.f;
                        v.y = (c4 + 1 < kw) ? li[c4 + 1] : 0.f;
                        v.z = (c4 + 2 < kw) ? li[c4 + 2] : 0.f;
                        v.w = (c4 + 3 < kw) ? li[c4 + 3] : 0.f;
                    }
                    uint32_t h0, l0, h1, l1;
                    split2(v.x, v.y, h0, l0);
                    split2(v.z, v.w, h1, l1);
                    *(uint2*)&Ah[r * 136 + c4] = make_uint2(h0, h1);
                    *(uint2*)&Al[r * 136 + c4] = make_uint2(l0, l1);
                }
            }
            __syncthreads();
#pragma unroll 1
            for (int ks = 0; ks < nks; ks++) {
                uint32_t fAh[4], fAl[4];
                int arow = warp_m * 16 + (lane & 15);
                int acol = ks * 16 + ((lane >> 4) << 3);
                uint32_t ao = (uint32_t)((arow * 136 + acol) * 2);
                ldsm4(fAh, aAh + ao);
                ldsm4(fAl, aAl + ao);
#pragma unroll
                for (int ng = 0; ng < 4; ng++) {
                    int brow = k0 + ks * 16 + (lane & 15);
                    int bcol = warp_n * 64 + ng * 16 + ((lane >> 4) << 3);
                    uint32_t bo = (uint32_t)((brow * 136 + bcol) * 2);
                    uint32_t fBh[4], fBl[4];
                    ldsm4t(fBh, aWh + bo);
                    ldsm4t(fBl, aWl + bo);
                    mma16816(C[ng * 2],     fAh, fBh);
                    mma16816(C[ng * 2],     fAl, fBh);
                    mma16816(C[ng * 2],     fAh, fBl);
                    mma16816(C[ng * 2 + 1], fAh, fBh + 2);
                    mma16816(C[ng * 2 + 1], fAl, fBh + 2);
                    mma16816(C[ng * 2 + 1], fAh, fBl + 2);
                }
            }
        }
#pragma unroll
        for (int p = 0; p < 2; p++) {
            int row = tile * 128 + warp_m * 16 + (lane >> 2) + p * 8;
            if (row < n_act) {
#pragma unroll
                for (int n8 = 0; n8 < 8; n8++) {
                    float v0 = C[n8][p * 2], v1 = C[n8][p * 2 + 1];
                    v0 = v0 * sigm(v0); v1 = v1 * sigm(v1);
                    uint32_t hw, lw;
                    split2(v0, v1, hw, lw);
                    int col = base + warp_n * 64 + n8 * 8 + (lane & 3) * 2;
                    *(uint32_t*)&g_hidh[(size_t)row * 256 + col] = hw;
                    *(uint32_t*)&g_hidl[(size_t)row * 256 + col] = lw;
                }
            }
        }
    }
}

// ===================== K4: GEMM2 out = (hid @ W2) * cutoff, 512 threads =====================
#define M2_SMEM ((2 * 256 * 136 + 2 * 128 * 136) * 2)
__global__ __launch_bounds__(512, 1) void k_mma2(
    const float* __restrict__ W2, const int* __restrict__ act,
    const float* __restrict__ cutoff, float* __restrict__ out_lat, int n_act) {
    extern __shared__ __nv_bfloat16 sb[];
    __nv_bfloat16* Wh = sb;
    __nv_bfloat16* Wl = Wh + 256 * 136;
    __nv_bfloat16* Ah = Wl + 256 * 136;
    __nv_bfloat16* Al = Ah + 128 * 136;
    int tid = threadIdx.x, wid = tid >> 5, lane = tid & 31;
    for (int i = tid; i < 256 * 128; i += 512) {
        int k = i >> 7, n = i & 127;
        float w = W2[k * 128 + n];
        __nv_bfloat16 h = __float2bfloat16(w);
        Wh[k * 136 + n] = h;
        Wl[k * 136 + n] = __float2bfloat16(w - __bfloat162float(h));
    }
    uint32_t aWh = s2u(Wh), aWl = s2u(Wl), aAh = s2u(Ah), aAl = s2u(Al);
    int warp_m = wid & 7, warp_n = wid >> 3;
    int ntile = (n_act + 127) >> 7;
    for (int tile = blockIdx.x; tile < ntile; tile += gridDim.x) {
        float C[8][4];
#pragma unroll
        for (int b = 0; b < 8; b++)
#pragma unroll
            for (int c = 0; c < 4; c++) C[b][c] = 0.f;
#pragma unroll 1
        for (int chunk = 0; chunk < 2; chunk++) {
            int k0 = chunk * 128;
            __syncthreads();
#pragma unroll
            for (int rr = 0; rr < 8; rr++) {
                int r = wid * 8 + rr;
                int eg = tile * 128 + r;
                int ec = eg < n_act ? eg : n_act - 1;
                *(uint2*)&Ah[r * 136 + lane * 4] = *(const uint2*)(g_hidh + (size_t)ec * 256 + k0 + lane * 4);
                *(uint2*)&Al[r * 136 + lane * 4] = *(const uint2*)(g_hidl + (size_t)ec * 256 + k0 + lane * 4);
            }
            __syncthreads();
#pragma unroll 1
            for (int ks = 0; ks < 8; ks++) {
                uint32_t fAh[4], fAl[4];
                int arow = warp_m * 16 + (lane & 15);
                int acol = ks * 16 + ((lane >> 4) << 3);
                uint32_t ao = (uint32_t)((arow * 136 + acol) * 2);
                ldsm4(fAh, aAh + ao);
                ldsm4(fAl, aAl + ao);
#pragma unroll
                for (int ng = 0; ng < 4; ng++) {
                    int brow = k0 + ks * 16 + (lane & 15);
                    int bcol = warp_n * 64 + ng * 16 + ((lane >> 4) << 3);
                    uint32_t bo = (uint32_t)((brow * 136 + bcol) * 2);
                    uint32_t fBh[4], fBl[4];
                    ldsm4t(fBh, aWh + bo);
                    ldsm4t(fBl, aWl + bo);
                    mma16816(C[ng * 2],     fAh, fBh);
                    mma16816(C[ng * 2],     fAl, fBh);
                    mma16816(C[ng * 2],     fAh, fBl);
                    mma16816(C[ng * 2 + 1], fAh, fBh + 2);
                    mma16816(C[ng * 2 + 1], fAl, fBh + 2);
                    mma16816(C[ng * 2 + 1], fAh, fBl + 2);
                }
            }
        }
#pragma unroll
        for (int p = 0; p < 2; p++) {
            int eg = tile * 128 + warp_m * 16 + (lane >> 2) + p * 8;
            if (eg < n_act) {
                int ae = act[eg];
                float cc = cutoff[ae];
                float* o = out_lat + (size_t)ae * 128;
#pragma unroll
                for (int n8 = 0; n8 < 8; n8++) {
                    int col = warp_n * 64 + n8 * 8 + (lane & 3) * 2;
                    float2 v;
                    v.x = C[n8][p * 2] * cc;
                    v.y = C[n8][p * 2 + 1] * cc;
                    *(float2*)(o + col) = v;
                }
            }
        }
    }
}

// ===================== launcher =====================
extern "C" void kernel_launch(void* const* d_in, const int* in_sizes, int n_in,
                              void* d_out, int out_size) {
    const float* latents   = (const float*)d_in[0];
    const float* node_feat = (const float*)d_in[1];
    const float* onehot    = (const float*)d_in[2];
    const float* edge_feat = (const float*)d_in[3];
    const float* edge_sh   = (const float*)d_in[4];
    const int*   edge_idx  = (const int*)d_in[5];
    const float* cutoff    = (const float*)d_in[6];
    const int*   act       = (const int*)d_in[7];
    const float* n_gs = (const float*)d_in[8];
    const float* n_bs = (const float*)d_in[9];
    const float* n_gv = (const float*)d_in[10];
    const float* e_gs = (const float*)d_in[11];
    const float* e_bs = (const float*)d_in[12];
    const float* e_gv = (const float*)d_in[13];
    const float* lg   = (const float*)d_in[14];
    const float* lb   = (const float*)d_in[15];
    const float* Wa   = (const float*)d_in[16];
    const float* Wb   = (const float*)d_in[17];
    const float* Wc   = (const float*)d_in[18];
    const float* Wd   = (const float*)d_in[19];
    const float* Wps  = (const float*)d_in[20];
    const float* Wpv  = (const float*)d_in[21];
    const float* We   = (const float*)d_in[22];
    const float* W1   = (const float*)d_in[23];
    const float* W2   = (const float*)d_in[24];
    const float* Wrs  = (const float*)d_in[25];
    const float* Wrv  = (const float*)d_in[26];

    int n_nodes = in_sizes[1] / DIMX;
    int n_act   = in_sizes[7];
    int n_edges = in_sizes[6];

    float* out_edge = (float*)d_out;
    float* out_lat  = out_edge + (size_t)n_act * DIMX;

    cudaFuncSetAttribute(k_edge_a, cudaFuncAttributeMaxDynamicSharedMemorySize, SMEM_A);
    cudaFuncSetAttribute(k_edge_b, cudaFuncAttributeMaxDynamicSharedMemorySize, SMEM_B);
    cudaFuncSetAttribute(k_mma1,   cudaFuncAttributeMaxDynamicSharedMemorySize, M1_SMEM);
    cudaFuncSetAttribute(k_mma2,   cudaFuncAttributeMaxDynamicSharedMemorySize, M2_SMEM);

    cudaMemcpyAsync(out_lat, latents, (size_t)n_edges * 128 * sizeof(float),
                    cudaMemcpyDeviceToDevice, 0);

    int nb1 = (n_nodes * 32 + 255) / 256;
    k_node_norm<<<nb1, 256>>>(node_feat, n_gs, n_bs, n_gv, n_nodes);

    k_edge_a<<<148, EA_T, SMEM_A>>>(edge_feat, edge_sh, edge_idx, act, onehot,
                                    e_gs, e_bs, e_gv, Wa, Wb, Wc, Wd, n_act, n_edges);

    k_edge_b<<<148, EB_T, SMEM_B>>>(latents, edge_feat, act, lg, lb,
                                    We, Wps, Wpv, Wrs, Wrv, out_edge, n_act);

    k_mma1<<<dim3(148, 2), 512, M1_SMEM>>>(W1, n_act);

    k_mma2<<<148, 512, M2_SMEM>>>(W2, act, cutoff, out_lat, n_act);
}

// round 12
// speedup vs baseline: 1.1062x; 1.1062x over previous
#include <cuda_runtime.h>
#include <cuda_bf16.h>
#include <math.h>
#include <stdint.h>

#define DIMX 160
#define EPSF 1e-5f
#define INV_SQ3 0.57735026918962576451f
#define MAX_NODES 50000
#define MAX_ACT 200000

typedef unsigned long long u64;

__device__ float g_nf[MAX_NODES * DIMX];
__device__ float g_ms[MAX_ACT * 64];
__device__ float g_mv[MAX_ACT * 96];
__device__ float g_lat_in[MAX_ACT * 232];
__device__ __align__(16) __nv_bfloat16 g_hidh[(size_t)MAX_ACT * 256];
__device__ __align__(16) __nv_bfloat16 g_hidl[(size_t)MAX_ACT * 256];

__device__ __forceinline__ float wsum(float v) {
#pragma unroll
    for (int o = 16; o > 0; o >>= 1) v += __shfl_xor_sync(0xffffffffu, v, o);
    return v;
}
__device__ __forceinline__ float sigm(float x) { return 1.f / (1.f + expf(-x)); }
__device__ __forceinline__ void ffma2(u64& a, u64 x, u64 w) {
    asm("fma.rn.f32x2 %0, %1, %2, %0;" : "+l"(a) : "l"(x), "l"(w));
}
__device__ __forceinline__ float hadd2(u64 a) {
    return __uint_as_float((unsigned)a) + __uint_as_float((unsigned)(a >> 32));
}
__device__ __forceinline__ ulonglong2 ld2(const float* p) {
    return *reinterpret_cast<const ulonglong2*>(p);
}
__device__ __forceinline__ uint32_t s2u(const void* p) {
    uint32_t a;
    asm("{ .reg .u64 t; cvta.to.shared.u64 t, %1; cvt.u32.u64 %0, t; }" : "=r"(a) : "l"(p));
    return a;
}
__device__ __forceinline__ void pf_l2(const void* p) {
    asm volatile("prefetch.global.L2 [%0];" :: "l"(p));
}
__device__ __forceinline__ void mma16816(float* c, const uint32_t* a, const uint32_t* b) {
    asm volatile("mma.sync.aligned.m16n8k16.row.col.f32.bf16.bf16.f32 "
        "{%0,%1,%2,%3}, {%4,%5,%6,%7}, {%8,%9}, {%0,%1,%2,%3};"
        : "+f"(c[0]), "+f"(c[1]), "+f"(c[2]), "+f"(c[3])
        : "r"(a[0]), "r"(a[1]), "r"(a[2]), "r"(a[3]), "r"(b[0]), "r"(b[1]));
}
__device__ __forceinline__ void ldsm4(uint32_t* r, uint32_t a) {
    asm volatile("ldmatrix.sync.aligned.m8n8.x4.shared.b16 {%0,%1,%2,%3}, [%4];"
        : "=r"(r[0]), "=r"(r[1]), "=r"(r[2]), "=r"(r[3]) : "r"(a));
}
__device__ __forceinline__ void ldsm4t(uint32_t* r, uint32_t a) {
    asm volatile("ldmatrix.sync.aligned.m8n8.x4.trans.shared.b16 {%0,%1,%2,%3}, [%4];"
        : "=r"(r[0]), "=r"(r[1]), "=r"(r[2]), "=r"(r[3]) : "r"(a));
}
__device__ __forceinline__ void split2(float v0, float v1, uint32_t& hi, uint32_t& lo) {
    float h0 = __bfloat162float(__float2bfloat16(v0));
    float h1 = __bfloat162float(__float2bfloat16(v1));
    asm("cvt.rn.bf16x2.f32 %0, %1, %2;" : "=r"(hi) : "f"(v1), "f"(v0));
    float r0 = v0 - h0, r1 = v1 - h1;
    asm("cvt.rn.bf16x2.f32 %0, %1, %2;" : "=r"(lo) : "f"(r1), "f"(r0));
}

// ===================== K1: node SLN =====================
__global__ void k_node_norm(const float* __restrict__ nf, const float* __restrict__ gs,
                            const float* __restrict__ bs, const float* __restrict__ gv,
                            int n_nodes) {
    int w = (blockIdx.x * 256 + threadIdx.x) >> 5;
    int l = threadIdx.x & 31;
    if (w >= n_nodes) return;
    const float* r = nf + (size_t)w * DIMX;
    float s0 = r[l], s1 = r[32 + l];
    float mu = wsum(s0 + s1) * (1.f / 64.f);
    float m2 = wsum(s0 * s0 + s1 * s1) * (1.f / 64.f);
    float rsv = rsqrtf(m2 - mu * mu + EPSF);
    float v0 = r[64 + 3 * l], v1 = r[65 + 3 * l], v2 = r[66 + 3 * l];
    float rmi = rsqrtf(wsum(v0 * v0 + v1 * v1 + v2 * v2) * (1.f / 32.f) + EPSF);
    float* o = g_nf + (size_t)w * DIMX;
    o[l] = (s0 - mu) * rsv * gs[l] + bs[l];
    o[32 + l] = (s1 - mu) * rsv * gs[32 + l] + bs[32 + l];
    float gk = gv[l] * rmi;
    o[64 + 3 * l] = v0 * gk; o[65 + 3 * l] = v1 * gk; o[66 + 3 * l] = v2 * gk;
}

// ===================== K2a: gather + edge SLN + tensor product =====================
// 256 threads / 8 warps / EPW=4 + batched-load staging (one latency exposure)
#define EA_T 256
#define EA_W 8
#define EA_E 4
#define SMEM_A ((96*196 + 96*100 + 32*196 + 32*100 + EA_W*EA_E*576) * 4)
__global__ __launch_bounds__(EA_T, 1) void k_edge_a(
    const float* __restrict__ ef, const float* __restrict__ esh,
    const int* __restrict__ eidx, const int* __restrict__ act,
    const float* __restrict__ onehot,
    const float* __restrict__ egs, const float* __restrict__ ebs, const float* __restrict__ egv,
    const float* __restrict__ Wa, const float* __restrict__ Wb,
    const float* __restrict__ Wc, const float* __restrict__ Wd,
    int n_act, int n_edges) {
    extern __shared__ float sm[];
    float* WaT = sm;
    float* WbT = WaT + 96 * 196;
    float* WcT = WbT + 96 * 100;
    float* WdT = WcT + 32 * 196;
    float* STG = WdT + 32 * 100;
    int tid = threadIdx.x;
    for (int i = tid; i < 192 * 96; i += EA_T) WaT[(i % 96) * 196 + i / 96] = Wa[i];
    for (int i = tid; i < 96 * 96; i += EA_T)  WbT[(i % 96) * 100 + i / 96] = Wb[i];
    for (int i = tid; i < 192 * 32; i += EA_T) WcT[(i % 32) * 196 + i / 32] = Wc[i];
    for (int i = tid; i < 96 * 32; i += EA_T)  WdT[(i % 32) * 100 + i / 32] = Wd[i];
    __syncthreads();
    int wq = tid >> 5, l = tid & 31;
    float* ST = STG + wq * (EA_E * 576);
    int gw = blockIdx.x * EA_W + wq;
    int stride = gridDim.x * EA_W * EA_E;
    for (int eb = gw * EA_E; eb < n_act; eb += stride) {
        // ---- phase A: batched index chain + row loads ----
        int ecs[EA_E], aes[EA_E], iis[EA_E], jjs[EA_E];
#pragma unroll
        for (int e = 0; e < EA_E; e++) { int ec = eb + e; ecs[e] = ec < n_act ? ec : n_act - 1; }
#pragma unroll
        for (int e = 0; e < EA_E; e++) aes[e] = act[ecs[e]];
#pragma unroll
        for (int e = 0; e < EA_E; e++) { iis[e] = eidx[aes[e]]; jjs[e] = eidx[n_edges + aes[e]]; }
        float4 shp[EA_E];
        float is0[EA_E], is1[EA_E], iv0[EA_E], iv1[EA_E], iv2[EA_E];
        float js0[EA_E], js1[EA_E], jv0[EA_E], jv1[EA_E], jv2[EA_E];
        float es0[EA_E], es1[EA_E], ev0[EA_E], ev1[EA_E], ev2[EA_E];
#pragma unroll
        for (int e = 0; e < EA_E; e++) {
            const float* ri = g_nf + (size_t)iis[e] * DIMX;
            is0[e] = ri[l]; is1[e] = ri[32 + l];
            iv0[e] = ri[64 + 3 * l]; iv1[e] = ri[65 + 3 * l]; iv2[e] = ri[66 + 3 * l];
            const float* rj = g_nf + (size_t)jjs[e] * DIMX;
            js0[e] = rj[l]; js1[e] = rj[32 + l];
            jv0[e] = rj[64 + 3 * l]; jv1[e] = rj[65 + 3 * l]; jv2[e] = rj[66 + 3 * l];
            const float* re = ef + (size_t)ecs[e] * DIMX;
            es0[e] = re[l]; es1[e] = re[32 + l];
            ev0[e] = re[64 + 3 * l]; ev1[e] = re[65 + 3 * l]; ev2[e] = re[66 + 3 * l];
            shp[e] = *(const float4*)(esh + (size_t)ecs[e] * 4);
        }
        // ---- phase B: LN + stores ----
        float sh0r[EA_E], s10[EA_E], s11[EA_E], s12[EA_E];
#pragma unroll
        for (int e = 0; e < EA_E; e++) {
            float* sA = ST + e * 576;
            float* vA = sA + 192;
            float* u = sA + 480;
            sA[l] = is0[e]; sA[32 + l] = is1[e];
            vA[l] = iv0[e]; vA[96 + l] = iv1[e]; vA[192 + l] = iv2[e];
            sA[128 + l] = js0[e]; sA[160 + l] = js1[e];
            vA[64 + l] = jv0[e]; vA[160 + l] = jv1[e]; vA[256 + l] = jv2[e];
            float s0 = es0[e], s1 = es1[e];
            float mu = wsum(s0 + s1) * (1.f / 64.f);
            float m2 = wsum(s0 * s0 + s1 * s1) * (1.f / 64.f);
            float rsv = rsqrtf(m2 - mu * mu + EPSF);
            sA[64 + l] = (s0 - mu) * rsv * egs[l] + ebs[l];
            sA[96 + l] = (s1 - mu) * rsv * egs[32 + l] + ebs[32 + l];
            float rmi = rsqrtf(wsum(ev0[e] * ev0[e] + ev1[e] * ev1[e] + ev2[e] * ev2[e]) * (1.f / 32.f) + EPSF);
            float gk = egv[l] * rmi;
            float e0 = ev0[e] * gk, e1 = ev1[e] * gk, e2 = ev2[e] * gk;
            vA[32 + l] = e0; vA[128 + l] = e1; vA[224 + l] = e2;
            sh0r[e] = shp[e].x; s10[e] = shp[e].y; s11[e] = shp[e].z; s12[e] = shp[e].w;
            u[l]      = (iv0[e] * s10[e] + iv1[e] * s11[e] + iv2[e] * s12[e]) * INV_SQ3;
            u[32 + l] = (e0 * s10[e] + e1 * s11[e] + e2 * s12[e]) * INV_SQ3;
            u[64 + l] = (jv0[e] * s10[e] + jv1[e] * s11[e] + jv2[e] * s12[e]) * INV_SQ3;
        }
        __syncwarp();
        u64 aA[3][EA_E];
#pragma unroll
        for (int j = 0; j < 3; j++)
#pragma unroll
            for (int e = 0; e < EA_E; e++) aA[j][e] = 0ull;
        for (int k = 0; k < 192; k += 4) {
            ulonglong2 w0 = ld2(&WaT[l * 196 + k]);
            ulonglong2 w1 = ld2(&WaT[(l + 32) * 196 + k]);
            ulonglong2 w2 = ld2(&WaT[(l + 64) * 196 + k]);
#pragma unroll
            for (int e = 0; e < EA_E; e++) {
                ulonglong2 x = ld2(&ST[e * 576 + k]);
                ffma2(aA[0][e], x.x, w0.x); ffma2(aA[0][e], x.y, w0.y);
                ffma2(aA[1][e], x.x, w1.x); ffma2(aA[1][e], x.y, w1.y);
                ffma2(aA[2][e], x.x, w2.x); ffma2(aA[2][e], x.y, w2.y);
            }
        }
        float fA[3][EA_E];
#pragma unroll
        for (int j = 0; j < 3; j++)
#pragma unroll
            for (int e = 0; e < EA_E; e++) fA[j][e] = hadd2(aA[j][e]);
        u64 aB[3][EA_E];
#pragma unroll
        for (int j = 0; j < 3; j++)
#pragma unroll
            for (int e = 0; e < EA_E; e++) aB[j][e] = 0ull;
        for (int k = 0; k < 96; k += 4) {
            ulonglong2 w0 = ld2(&WbT[l * 100 + k]);
            ulonglong2 w1 = ld2(&WbT[(l + 32) * 100 + k]);
            ulonglong2 w2 = ld2(&WbT[(l + 64) * 100 + k]);
#pragma unroll
            for (int e = 0; e < EA_E; e++) {
                ulonglong2 x = ld2(&ST[e * 576 + 480 + k]);
                ffma2(aB[0][e], x.x, w0.x); ffma2(aB[0][e], x.y, w0.y);
                ffma2(aB[1][e], x.x, w1.x); ffma2(aB[1][e], x.y, w1.y);
                ffma2(aB[2][e], x.x, w2.x); ffma2(aB[2][e], x.y, w2.y);
            }
        }
        float os[3][EA_E];
#pragma unroll
        for (int j = 0; j < 3; j++)
#pragma unroll
            for (int e = 0; e < EA_E; e++) os[j][e] = fmaf(sh0r[e], fA[j][e], hadd2(aB[j][e]));
        u64 swc[EA_E], wd[3][EA_E];
#pragma unroll
        for (int e = 0; e < EA_E; e++) { swc[e] = 0ull; wd[0][e] = 0ull; wd[1][e] = 0ull; wd[2][e] = 0ull; }
        for (int k = 0; k < 192; k += 4) {
            ulonglong2 w = ld2(&WcT[l * 196 + k]);
#pragma unroll
            for (int e = 0; e < EA_E; e++) {
                ulonglong2 x = ld2(&ST[e * 576 + k]);
                ffma2(swc[e], x.x, w.x); ffma2(swc[e], x.y, w.y);
            }
        }
        for (int k = 0; k < 96; k += 4) {
            ulonglong2 w = ld2(&WdT[l * 100 + k]);
#pragma unroll
            for (int e = 0; e < EA_E; e++) {
#pragma unroll
                for (int c = 0; c < 3; c++) {
                    ulonglong2 x = ld2(&ST[e * 576 + 192 + 96 * c + k]);
                    ffma2(wd[c][e], x.x, w.x); ffma2(wd[c][e], x.y, w.y);
                }
            }
        }
#pragma unroll
        for (int e = 0; e < EA_E; e++) {
            int eg = eb + e;
            if (eg < n_act) {
                float gate = sigm(os[2][e]);
                g_ms[(size_t)eg * 64 + l] = os[0][e] * sigm(os[0][e]);
                g_ms[(size_t)eg * 64 + 32 + l] = os[1][e] * sigm(os[1][e]);
                float s1c[3] = { s10[e], s11[e], s12[e] };
                float sw = hadd2(swc[e]);
#pragma unroll
                for (int c = 0; c < 3; c++) {
                    float ov = fmaf(sw, s1c[c], hadd2(wd[c][e]) * sh0r[e]);
                    g_mv[(size_t)eg * 96 + 3 * l + c] = ov * gate;
                }
                float* li = g_lat_in + (size_t)eg * 232;
                li[132 + l] = os[0][e]; li[164 + l] = os[1][e]; li[196 + l] = os[2][e];
                if (l < 4) { li[l] = onehot[iis[e] * 4 + l]; li[228 + l] = onehot[jjs[e] * 4 + l]; }
            }
        }
        __syncwarp();
    }
}

// ===================== K2b: W_edge / Wp / Wres + latent LN + edge_out =====================
#define EB_T 512
#define EB_W 16
#define EB_E 4
#define SMEM_B ((96*132 + 64*68 + 32*36 + 64*68 + 32*36 + EB_W*EB_E*448) * 4)
__global__ __launch_bounds__(EB_T, 1) void k_edge_b(
    const float* __restrict__ latents, const float* __restrict__ ef,
    const int* __restrict__ act,
    const float* __restrict__ lg, const float* __restrict__ lb,
    const float* __restrict__ We, const float* __restrict__ Wps, const float* __restrict__ Wpv,
    const float* __restrict__ Wrs, const float* __restrict__ Wrv,
    float* __restrict__ out_edge, int n_act) {
    extern __shared__ float sm[];
    float* WeT = sm;
    float* WpsT = WeT + 96 * 132;
    float* WpvT = WpsT + 64 * 68;
    float* WrsT = WpvT + 32 * 36;
    float* WrvT = WrsT + 64 * 68;
    float* STG = WrvT + 32 * 36;
    int tid = threadIdx.x;
    for (int i = tid; i < 128 * 96; i += EB_T) WeT[(i % 96) * 132 + i / 96] = We[i];
    for (int i = tid; i < 64 * 64; i += EB_T)  WpsT[(i % 64) * 68 + i / 64] = Wps[i];
    for (int i = tid; i < 32 * 32; i += EB_T)  WpvT[(i % 32) * 36 + i / 32] = Wpv[i];
    for (int i = tid; i < 64 * 64; i += EB_T)  WrsT[(i % 64) * 68 + i / 64] = Wrs[i];
    for (int i = tid; i < 32 * 32; i += EB_T)  WrvT[(i % 32) * 36 + i / 32] = Wrv[i];
    __syncthreads();
    int wq = tid >> 5, l = tid & 31;
    float* ST = STG + wq * (EB_E * 448);
    int gw = blockIdx.x * EB_W + wq;
    int stride = gridDim.x * EB_W * EB_E;
    for (int eb = gw * EB_E; eb < n_act; eb += stride) {
#pragma unroll
        for (int half = 0; half < 2; half++) {
            int ecs[2], aes[2];
            float lx[2][4], msr[2][2], mvr[2][3], res[2][2], rev[2][3];
#pragma unroll
            for (int q = 0; q < 2; q++) {
                int ec = eb + half * 2 + q;
                ecs[q] = ec < n_act ? ec : n_act - 1;
            }
#pragma unroll
            for (int q = 0; q < 2; q++) aes[q] = act[ecs[q]];
#pragma unroll
            for (int q = 0; q < 2; q++) {
                const float* la = latents + (size_t)aes[q] * 128;
                lx[q][0] = la[l]; lx[q][1] = la[32 + l]; lx[q][2] = la[64 + l]; lx[q][3] = la[96 + l];
                const float* ms = g_ms + (size_t)ecs[q] * 64;
                msr[q][0] = ms[l]; msr[q][1] = ms[32 + l];
                const float* mv = g_mv + (size_t)ecs[q] * 96;
                mvr[q][0] = mv[3 * l]; mvr[q][1] = mv[3 * l + 1]; mvr[q][2] = mv[3 * l + 2];
                const float* re = ef + (size_t)ecs[q] * DIMX;
                res[q][0] = re[l]; res[q][1] = re[32 + l];
                rev[q][0] = re[64 + 3 * l]; rev[q][1] = re[65 + 3 * l]; rev[q][2] = re[66 + 3 * l];
            }
#pragma unroll
            for (int q = 0; q < 2; q++) {
                int e = half * 2 + q;
                float* S = ST + e * 448;
                float x0 = lx[q][0], x1 = lx[q][1], x2 = lx[q][2], x3 = lx[q][3];
                S[l] = x0; S[32 + l] = x1; S[64 + l] = x2; S[96 + l] = x3;
                float mu = wsum(x0 + x1 + x2 + x3) * (1.f / 128.f);
                float m2 = wsum(x0 * x0 + x1 * x1 + x2 * x2 + x3 * x3) * (1.f / 128.f);
                float rsv = rsqrtf(m2 - mu * mu + EPSF);
                int eg = eb + e;
                if (eg < n_act) {
                    float* li = g_lat_in + (size_t)eg * 232 + 4;
                    li[l] = (x0 - mu) * rsv * lg[l] + lb[l];
                    li[32 + l] = (x1 - mu) * rsv * lg[32 + l] + lb[32 + l];
                    li[64 + l] = (x2 - mu) * rsv * lg[64 + l] + lb[64 + l];
                    li[96 + l] = (x3 - mu) * rsv * lg[96 + l] + lb[96 + l];
                }
                S[128 + l] = msr[q][0]; S[160 + l] = msr[q][1];
                S[192 + l] = mvr[q][0]; S[224 + l] = mvr[q][1]; S[256 + l] = mvr[q][2];
                S[288 + l] = res[q][0]; S[320 + l] = res[q][1];
                S[352 + l] = rev[q][0]; S[384 + l] = rev[q][1]; S[416 + l] = rev[q][2];
            }
        }
        __syncwarp();
        u64 ww[3][EB_E];
#pragma unroll
        for (int j = 0; j < 3; j++)
#pragma unroll
            for (int e = 0; e < EB_E; e++) ww[j][e] = 0ull;
        for (int k = 0; k < 128; k += 4) {
            ulonglong2 w0 = ld2(&WeT[l * 132 + k]);
            ulonglong2 w1 = ld2(&WeT[(l + 32) * 132 + k]);
            ulonglong2 w2 = ld2(&WeT[(l + 64) * 132 + k]);
#pragma unroll
            for (int e = 0; e < EB_E; e++) {
                ulonglong2 x = ld2(&ST[e * 448 + k]);
                ffma2(ww[0][e], x.x, w0.x); ffma2(ww[0][e], x.y, w0.y);
                ffma2(ww[1][e], x.x, w1.x); ffma2(ww[1][e], x.y, w1.y);
                ffma2(ww[2][e], x.x, w2.x); ffma2(ww[2][e], x.y, w2.y);
            }
        }
        float fw[3][EB_E];
#pragma unroll
        for (int j = 0; j < 3; j++)
#pragma unroll
            for (int e = 0; e < EB_E; e++) fw[j][e] = hadd2(ww[j][e]);
        u64 ps[2][EB_E], rs[2][EB_E];
#pragma unroll
        for (int e = 0; e < EB_E; e++) { ps[0][e] = ps[1][e] = rs[0][e] = rs[1][e] = 0ull; }
        for (int k = 0; k < 64; k += 4) {
            ulonglong2 p0 = ld2(&WpsT[l * 68 + k]);
            ulonglong2 p1 = ld2(&WpsT[(l + 32) * 68 + k]);
            ulonglong2 r0 = ld2(&WrsT[l * 68 + k]);
            ulonglong2 r1 = ld2(&WrsT[(l + 32) * 68 + k]);
#pragma unroll
            for (int e = 0; e < EB_E; e++) {
                ulonglong2 xm = ld2(&ST[e * 448 + 128 + k]);
                ulonglong2 xr = ld2(&ST[e * 448 + 288 + k]);
                ffma2(ps[0][e], xm.x, p0.x); ffma2(ps[0][e], xm.y, p0.y);
                ffma2(ps[1][e], xm.x, p1.x); ffma2(ps[1][e], xm.y, p1.y);
                ffma2(rs[0][e], xr.x, r0.x); ffma2(rs[0][e], xr.y, r0.y);
                ffma2(rs[1][e], xr.x, r1.x); ffma2(rs[1][e], xr.y, r1.y);
            }
        }
        float fps[2][EB_E], frs[2][EB_E];
#pragma unroll
        for (int j = 0; j < 2; j++)
#pragma unroll
            for (int e = 0; e < EB_E; e++) { fps[j][e] = hadd2(ps[j][e]); frs[j][e] = hadd2(rs[j][e]); }
        u64 pv[3][EB_E], rv[3][EB_E];
#pragma unroll
        for (int c = 0; c < 3; c++)
#pragma unroll
            for (int e = 0; e < EB_E; e++) { pv[c][e] = 0ull; rv[c][e] = 0ull; }
        for (int k = 0; k < 32; k += 4) {
            ulonglong2 pw = ld2(&WpvT[l * 36 + k]);
            ulonglong2 rw = ld2(&WrvT[l * 36 + k]);
#pragma unroll
            for (int e = 0; e < EB_E; e++) {
#pragma unroll
                for (int c = 0; c < 3; c++) {
                    ulonglong2 xm = ld2(&ST[e * 448 + 192 + 32 * c + k]);
                    ulonglong2 xr = ld2(&ST[e * 448 + 352 + 32 * c + k]);
                    ffma2(pv[c][e], xm.x, pw.x); ffma2(pv[c][e], xm.y, pw.y);
                    ffma2(rv[c][e], xr.x, rw.x); ffma2(rv[c][e], xr.y, rw.y);
                }
            }
        }
#pragma unroll
        for (int e = 0; e < EB_E; e++) {
            int eg = eb + e;
            if (eg < n_act) {
                float* oe = out_edge + (size_t)eg * DIMX;
                oe[l] = fmaf(fps[0][e], fw[0][e], frs[0][e]);
                oe[32 + l] = fmaf(fps[1][e], fw[1][e], frs[1][e]);
#pragma unroll
                for (int c = 0; c < 3; c++)
                    oe[64 + 3 * l + c] = fmaf(hadd2(pv[c][e]), fw[2][e], hadd2(rv[c][e]));
            }
        }
        __syncwarp();
    }
}

// ===================== K3: GEMM1 hid = silu(lat_in @ W1), 512 threads =====================
#define M1_SMEM ((2 * 240 * 136 + 2 * 128 * 136) * 2)
__global__ __launch_bounds__(512, 1) void k_mma1(const float* __restrict__ W1, int n_act) {
    extern __shared__ __nv_bfloat16 sb[];
    __nv_bfloat16* Wh = sb;
    __nv_bfloat16* Wl = Wh + 240 * 136;
    __nv_bfloat16* Ah = Wl + 240 * 136;
    __nv_bfloat16* Al = Ah + 128 * 136;
    int tid = threadIdx.x, wid = tid >> 5, lane = tid & 31;
    int base = blockIdx.y * 128;
    for (int i = tid; i < 240 * 128; i += 512) {
        int k = i >> 7, n = i & 127;
        float w = (k < 232) ? W1[k * 256 + base + n] : 0.f;
        __nv_bfloat16 h = __float2bfloat16(w);
        Wh[k * 136 + n] = h;
        Wl[k * 136 + n] = __float2bfloat16(w - __bfloat162float(h));
    }
    uint32_t aWh = s2u(Wh), aWl = s2u(Wl), aAh = s2u(Ah), aAl = s2u(Al);
    int warp_m = wid & 7, warp_n = wid >> 3;
    int ntile = (n_act + 127) >> 7;
    for (int tile = blockIdx.x; tile < ntile; tile += gridDim.x) {
        int nt = tile + gridDim.x;
        if (nt < ntile) {
            const char* p = (const char*)(g_lat_in + (size_t)nt * 128 * 232);
            for (int i = tid; i < 928; i += 512) pf_l2(p + (size_t)i * 128);
        }
        float C[8][4];
#pragma unroll
        for (int b = 0; b < 8; b++)
#pragma unroll
            for (int c = 0; c < 4; c++) C[b][c] = 0.f;
#pragma unroll 1
        for (int chunk = 0; chunk < 2; chunk++) {
            int k0 = chunk * 128;
            int cw = chunk ? 112 : 128;
            int kw = chunk ? 104 : 128;
            int nks = chunk ? 7 : 8;
            __syncthreads();
            int c4 = lane * 4;
#pragma unroll
            for (int rr = 0; rr < 8; rr++) {
                int r = wid * 8 + rr;
                int eg = tile * 128 + r;
                int ec = eg < n_act ? eg : n_act - 1;
                const float* li = g_lat_in + (size_t)ec * 232 + k0;
                if (c4 < cw) {
                    float4 v;
                    if (c4 + 3 < kw) v = *(const float4*)(li + c4);
                    else {
                        v.x = (c4 + 0 < kw) ? li[c4 + 0] : 0.f;
                        v.y = (c4 + 1 < kw) ? li[c4 + 1] : 0.f;
                        v.z = (c4 + 2 < kw) ? li[c4 + 2] : 0.f;
                        v.w = (c4 + 3 < kw) ? li[c4 + 3] : 0.f;
                    }
                    uint32_t h0, l0, h1, l1;
                    split2(v.x, v.y, h0, l0);
                    split2(v.z, v.w, h1, l1);
                    *(uint2*)&Ah[r * 136 + c4] = make_uint2(h0, h1);
                    *(uint2*)&Al[r * 136 + c4] = make_uint2(l0, l1);
                }
            }
            __syncthreads();
#pragma unroll 1
            for (int ks = 0; ks < nks; ks++) {
                uint32_t fAh[4], fAl[4];
                int arow = warp_m * 16 + (lane & 15);
                int acol = ks * 16 + ((lane >> 4) << 3);
                uint32_t ao = (uint32_t)((arow * 136 + acol) * 2);
                ldsm4(fAh, aAh + ao);
                ldsm4(fAl, aAl + ao);
#pragma unroll
                for (int ng = 0; ng < 4; ng++) {
                    int brow = k0 + ks * 16 + (lane & 15);
                    int bcol = warp_n * 64 + ng * 16 + ((lane >> 4) << 3);
                    uint32_t bo = (uint32_t)((brow * 136 + bcol) * 2);
                    uint32_t fBh[4], fBl[4];
                    ldsm4t(fBh, aWh + bo);
                    ldsm4t(fBl, aWl + bo);
                    mma16816(C[ng * 2],     fAh, fBh);
                    mma16816(C[ng * 2],     fAl, fBh);
                    mma16816(C[ng * 2],     fAh, fBl);
                    mma16816(C[ng * 2 + 1], fAh, fBh + 2);
                    mma16816(C[ng * 2 + 1], fAl, fBh + 2);
                    mma16816(C[ng * 2 + 1], fAh, fBl + 2);
                }
            }
        }
#pragma unroll
        for (int p = 0; p < 2; p++) {
            int row = tile * 128 + warp_m * 16 + (lane >> 2) + p * 8;
            if (row < n_act) {
#pragma unroll
                for (int n8 = 0; n8 < 8; n8++) {
                    float v0 = C[n8][p * 2], v1 = C[n8][p * 2 + 1];
                    v0 = v0 * sigm(v0); v1 = v1 * sigm(v1);
                    uint32_t hw, lw;
                    split2(v0, v1, hw, lw);
                    int col = base + warp_n * 64 + n8 * 8 + (lane & 3) * 2;
                    *(uint32_t*)&g_hidh[(size_t)row * 256 + col] = hw;
                    *(uint32_t*)&g_hidl[(size_t)row * 256 + col] = lw;
                }
            }
        }
    }
}

// ===================== K4: GEMM2 out = (hid @ W2) * cutoff, 512 threads =====================
#define M2_SMEM ((2 * 256 * 136 + 2 * 128 * 136) * 2)
__global__ __launch_bounds__(512, 1) void k_mma2(
    const float* __restrict__ W2, const int* __restrict__ act,
    const float* __restrict__ cutoff, float* __restrict__ out_lat, int n_act) {
    extern __shared__ __nv_bfloat16 sb[];
    __nv_bfloat16* Wh = sb;
    __nv_bfloat16* Wl = Wh + 256 * 136;
    __nv_bfloat16* Ah = Wl + 256 * 136;
    __nv_bfloat16* Al = Ah + 128 * 136;
    int tid = threadIdx.x, wid = tid >> 5, lane = tid & 31;
    for (int i = tid; i < 256 * 128; i += 512) {
        int k = i >> 7, n = i & 127;
        float w = W2[k * 128 + n];
        __nv_bfloat16 h = __float2bfloat16(w);
        Wh[k * 136 + n] = h;
        Wl[k * 136 + n] = __float2bfloat16(w - __bfloat162float(h));
    }
    uint32_t aWh = s2u(Wh), aWl = s2u(Wl), aAh = s2u(Ah), aAl = s2u(Al);
    int warp_m = wid & 7, warp_n = wid >> 3;
    int ntile = (n_act + 127) >> 7;
    for (int tile = blockIdx.x; tile < ntile; tile += gridDim.x) {
        int nt = tile + gridDim.x;
        if (nt < ntile) {
            const char* ph = (const char*)(g_hidh + (size_t)nt * 128 * 256);
            const char* pl = (const char*)(g_hidl + (size_t)nt * 128 * 256);
            if (tid < 512) { pf_l2(ph + (size_t)tid * 128); pf_l2(pl + (size_t)tid * 128); }
        }
        float C[8][4];
#pragma unroll
        for (int b = 0; b < 8; b++)
#pragma unroll
            for (int c = 0; c < 4; c++) C[b][c] = 0.f;
#pragma unroll 1
        for (int chunk = 0; chunk < 2; chunk++) {
            int k0 = chunk * 128;
            __syncthreads();
#pragma unroll
            for (int rr = 0; rr < 8; rr++) {
                int r = wid * 8 + rr;
                int eg = tile * 128 + r;
                int ec = eg < n_act ? eg : n_act - 1;
                *(uint2*)&Ah[r * 136 + lane * 4] = *(const uint2*)(g_hidh + (size_t)ec * 256 + k0 + lane * 4);
                *(uint2*)&Al[r * 136 + lane * 4] = *(const uint2*)(g_hidl + (size_t)ec * 256 + k0 + lane * 4);
            }
            __syncthreads();
#pragma unroll 1
            for (int ks = 0; ks < 8; ks++) {
                uint32_t fAh[4], fAl[4];
                int arow = warp_m * 16 + (lane & 15);
                int acol = ks * 16 + ((lane >> 4) << 3);
                uint32_t ao = (uint32_t)((arow * 136 + acol) * 2);
                ldsm4(fAh, aAh + ao);
                ldsm4(fAl, aAl + ao);
#pragma unroll
                for (int ng = 0; ng < 4; ng++) {
                    int brow = k0 + ks * 16 + (lane & 15);
                    int bcol = warp_n * 64 + ng * 16 + ((lane >> 4) << 3);
                    uint32_t bo = (uint32_t)((brow * 136 + bcol) * 2);
                    uint32_t fBh[4], fBl[4];
                    ldsm4t(fBh, aWh + bo);
                    ldsm4t(fBl, aWl + bo);
                    mma16816(C[ng * 2],     fAh, fBh);
                    mma16816(C[ng * 2],     fAl, fBh);
                    mma16816(C[ng * 2],     fAh, fBl);
                    mma16816(C[ng * 2 + 1], fAh, fBh + 2);
                    mma16816(C[ng * 2 + 1], fAl, fBh + 2);
                    mma16816(C[ng * 2 + 1], fAh, fBl + 2);
                }
            }
        }
#pragma unroll
        for (int p = 0; p < 2; p++) {
            int eg = tile * 128 + warp_m * 16 + (lane >> 2) + p * 8;
            if (eg < n_act) {
                int ae = act[eg];
                float cc = cutoff[ae];
                float* o = out_lat + (size_t)ae * 128;
#pragma unroll
                for (int n8 = 0; n8 < 8; n8++) {
                    int col = warp_n * 64 + n8 * 8 + (lane & 3) * 2;
                    float2 v;
                    v.x = C[n8][p * 2] * cc;
                    v.y = C[n8][p * 2 + 1] * cc;
                    *(float2*)(o + col) = v;
                }
            }
        }
    }
}

// ===================== launcher =====================
extern "C" void kernel_launch(void* const* d_in, const int* in_sizes, int n_in,
                              void* d_out, int out_size) {
    const float* latents   = (const float*)d_in[0];
    const float* node_feat = (const float*)d_in[1];
    const float* onehot    = (const float*)d_in[2];
    const float* edge_feat = (const float*)d_in[3];
    const float* edge_sh   = (const float*)d_in[4];
    const int*   edge_idx  = (const int*)d_in[5];
    const float* cutoff    = (const float*)d_in[6];
    const int*   act       = (const int*)d_in[7];
    const float* n_gs = (const float*)d_in[8];
    const float* n_bs = (const float*)d_in[9];
    const float* n_gv = (const float*)d_in[10];
    const float* e_gs = (const float*)d_in[11];
    const float* e_bs = (const float*)d_in[12];
    const float* e_gv = (const float*)d_in[13];
    const float* lg   = (const float*)d_in[14];
    const float* lb   = (const float*)d_in[15];
    const float* Wa   = (const float*)d_in[16];
    const float* Wb   = (const float*)d_in[17];
    const float* Wc   = (const float*)d_in[18];
    const float* Wd   = (const float*)d_in[19];
    const float* Wps  = (const float*)d_in[20];
    const float* Wpv  = (const float*)d_in[21];
    const float* We   = (const float*)d_in[22];
    const float* W1   = (const float*)d_in[23];
    const float* W2   = (const float*)d_in[24];
    const float* Wrs  = (const float*)d_in[25];
    const float* Wrv  = (const float*)d_in[26];

    int n_nodes = in_sizes[1] / DIMX;
    int n_act   = in_sizes[7];
    int n_edges = in_sizes[6];

    float* out_edge = (float*)d_out;
    float* out_lat  = out_edge + (size_t)n_act * DIMX;

    cudaFuncSetAttribute(k_edge_a, cudaFuncAttributeMaxDynamicSharedMemorySize, SMEM_A);
    cudaFuncSetAttribute(k_edge_b, cudaFuncAttributeMaxDynamicSharedMemorySize, SMEM_B);
    cudaFuncSetAttribute(k_mma1,   cudaFuncAttributeMaxDynamicSharedMemorySize, M1_SMEM);
    cudaFuncSetAttribute(k_mma2,   cudaFuncAttributeMaxDynamicSharedMemorySize, M2_SMEM);

    cudaMemcpyAsync(out_lat, latents, (size_t)n_edges * 128 * sizeof(float),
                    cudaMemcpyDeviceToDevice, 0);

    int nb1 = (n_nodes * 32 + 255) / 256;
    k_node_norm<<<nb1, 256>>>(node_feat, n_gs, n_bs, n_gv, n_nodes);

    k_edge_a<<<148, EA_T, SMEM_A>>>(edge_feat, edge_sh, edge_idx, act, onehot,
                                    e_gs, e_bs, e_gv, Wa, Wb, Wc, Wd, n_act, n_edges);

    k_edge_b<<<148, EB_T, SMEM_B>>>(latents, edge_feat, act, lg, lb,
                                    We, Wps, Wpv, Wrs, Wrv, out_edge, n_act);

    k_mma1<<<dim3(148, 2), 512, M1_SMEM>>>(W1, n_act);

    k_mma2<<<148, 512, M2_SMEM>>>(W2, act, cutoff, out_lat, n_act);
}

// round 13
// speedup vs baseline: 1.1271x; 1.0190x over previous
#include <cuda_runtime.h>
#include <cuda_bf16.h>
#include <math.h>
#include <stdint.h>

#define DIMX 160
#define EPSF 1e-5f
#define INV_SQ3 0.57735026918962576451f
#define MAX_NODES 50000
#define MAX_ACT 200000

typedef unsigned long long u64;

__device__ float g_nf[MAX_NODES * DIMX];
__device__ float g_ms[MAX_ACT * 64];
__device__ float g_mv[MAX_ACT * 96];
__device__ float g_lat_in[MAX_ACT * 232];
__device__ __align__(16) __nv_bfloat16 g_hidh[(size_t)MAX_ACT * 256];
__device__ __align__(16) __nv_bfloat16 g_hidl[(size_t)MAX_ACT * 256];

__device__ __forceinline__ float wsum(float v) {
#pragma unroll
    for (int o = 16; o > 0; o >>= 1) v += __shfl_xor_sync(0xffffffffu, v, o);
    return v;
}
__device__ __forceinline__ float sigm(float x) { return 1.f / (1.f + expf(-x)); }
__device__ __forceinline__ void ffma2(u64& a, u64 x, u64 w) {
    asm("fma.rn.f32x2 %0, %1, %2, %0;" : "+l"(a) : "l"(x), "l"(w));
}
__device__ __forceinline__ float hadd2(u64 a) {
    return __uint_as_float((unsigned)a) + __uint_as_float((unsigned)(a >> 32));
}
__device__ __forceinline__ ulonglong2 ld2(const float* p) {
    return *reinterpret_cast<const ulonglong2*>(p);
}
__device__ __forceinline__ uint32_t s2u(const void* p) {
    uint32_t a;
    asm("{ .reg .u64 t; cvta.to.shared.u64 t, %1; cvt.u32.u64 %0, t; }" : "=r"(a) : "l"(p));
    return a;
}
__device__ __forceinline__ void pf_l2(const void* p) {
    asm volatile("prefetch.global.L2 [%0];" :: "l"(p));
}
__device__ __forceinline__ void mma16816(float* c, const uint32_t* a, const uint32_t* b) {
    asm volatile("mma.sync.aligned.m16n8k16.row.col.f32.bf16.bf16.f32 "
        "{%0,%1,%2,%3}, {%4,%5,%6,%7}, {%8,%9}, {%0,%1,%2,%3};"
        : "+f"(c[0]), "+f"(c[1]), "+f"(c[2]), "+f"(c[3])
        : "r"(a[0]), "r"(a[1]), "r"(a[2]), "r"(a[3]), "r"(b[0]), "r"(b[1]));
}
__device__ __forceinline__ void ldsm4(uint32_t* r, uint32_t a) {
    asm volatile("ldmatrix.sync.aligned.m8n8.x4.shared.b16 {%0,%1,%2,%3}, [%4];"
        : "=r"(r[0]), "=r"(r[1]), "=r"(r[2]), "=r"(r[3]) : "r"(a));
}
__device__ __forceinline__ void ldsm4t(uint32_t* r, uint32_t a) {
    asm volatile("ldmatrix.sync.aligned.m8n8.x4.trans.shared.b16 {%0,%1,%2,%3}, [%4];"
        : "=r"(r[0]), "=r"(r[1]), "=r"(r[2]), "=r"(r[3]) : "r"(a));
}
__device__ __forceinline__ void split2(float v0, float v1, uint32_t& hi, uint32_t& lo) {
    float h0 = __bfloat162float(__float2bfloat16(v0));
    float h1 = __bfloat162float(__float2bfloat16(v1));
    asm("cvt.rn.bf16x2.f32 %0, %1, %2;" : "=r"(hi) : "f"(v1), "f"(v0));
    float r0 = v0 - h0, r1 = v1 - h1;
    asm("cvt.rn.bf16x2.f32 %0, %1, %2;" : "=r"(lo) : "f"(r1), "f"(r0));
}

// ===================== K1: node SLN =====================
__global__ void k_node_norm(const float* __restrict__ nf, const float* __restrict__ gs,
                            const float* __restrict__ bs, const float* __restrict__ gv,
                            int n_nodes) {
    int w = (blockIdx.x * 256 + threadIdx.x) >> 5;
    int l = threadIdx.x & 31;
    if (w >= n_nodes) return;
    const float* r = nf + (size_t)w * DIMX;
    float s0 = r[l], s1 = r[32 + l];
    float mu = wsum(s0 + s1) * (1.f / 64.f);
    float m2 = wsum(s0 * s0 + s1 * s1) * (1.f / 64.f);
    float rsv = rsqrtf(m2 - mu * mu + EPSF);
    float v0 = r[64 + 3 * l], v1 = r[65 + 3 * l], v2 = r[66 + 3 * l];
    float rmi = rsqrtf(wsum(v0 * v0 + v1 * v1 + v2 * v2) * (1.f / 32.f) + EPSF);
    float* o = g_nf + (size_t)w * DIMX;
    o[l] = (s0 - mu) * rsv * gs[l] + bs[l];
    o[32 + l] = (s1 - mu) * rsv * gs[32 + l] + bs[32 + l];
    float gk = gv[l] * rmi;
    o[64 + 3 * l] = v0 * gk; o[65 + 3 * l] = v1 * gk; o[66 + 3 * l] = v2 * gk;
}

// ===================== K2a: gather + edge SLN + tensor product =====================
#define EA_T 256
#define EA_W 8
#define EA_E 4
#define SMEM_A ((96*196 + 96*100 + 32*196 + 32*100 + EA_W*EA_E*576) * 4)
__global__ __launch_bounds__(EA_T, 1) void k_edge_a(
    const float* __restrict__ ef, const float* __restrict__ esh,
    const int* __restrict__ eidx, const int* __restrict__ act,
    const float* __restrict__ onehot,
    const float* __restrict__ egs, const float* __restrict__ ebs, const float* __restrict__ egv,
    const float* __restrict__ Wa, const float* __restrict__ Wb,
    const float* __restrict__ Wc, const float* __restrict__ Wd,
    int n_act, int n_edges) {
    extern __shared__ float sm[];
    float* WaT = sm;
    float* WbT = WaT + 96 * 196;
    float* WcT = WbT + 96 * 100;
    float* WdT = WcT + 32 * 196;
    float* STG = WdT + 32 * 100;
    int tid = threadIdx.x;
    for (int i = tid; i < 192 * 96; i += EA_T) WaT[(i % 96) * 196 + i / 96] = Wa[i];
    for (int i = tid; i < 96 * 96; i += EA_T)  WbT[(i % 96) * 100 + i / 96] = Wb[i];
    for (int i = tid; i < 192 * 32; i += EA_T) WcT[(i % 32) * 196 + i / 32] = Wc[i];
    for (int i = tid; i < 96 * 32; i += EA_T)  WdT[(i % 32) * 100 + i / 32] = Wd[i];
    __syncthreads();
    int wq = tid >> 5, l = tid & 31;
    float* ST = STG + wq * (EA_E * 576);
    int gw = blockIdx.x * EA_W + wq;
    int stride = gridDim.x * EA_W * EA_E;
    for (int eb = gw * EA_E; eb < n_act; eb += stride) {
        int ecs[EA_E], aes[EA_E], iis[EA_E], jjs[EA_E];
#pragma unroll
        for (int e = 0; e < EA_E; e++) { int ec = eb + e; ecs[e] = ec < n_act ? ec : n_act - 1; }
#pragma unroll
        for (int e = 0; e < EA_E; e++) aes[e] = act[ecs[e]];
#pragma unroll
        for (int e = 0; e < EA_E; e++) { iis[e] = eidx[aes[e]]; jjs[e] = eidx[n_edges + aes[e]]; }
        float4 shp[EA_E];
        float is0[EA_E], is1[EA_E], iv0[EA_E], iv1[EA_E], iv2[EA_E];
        float js0[EA_E], js1[EA_E], jv0[EA_E], jv1[EA_E], jv2[EA_E];
        float es0[EA_E], es1[EA_E], ev0[EA_E], ev1[EA_E], ev2[EA_E];
#pragma unroll
        for (int e = 0; e < EA_E; e++) {
            const float* ri = g_nf + (size_t)iis[e] * DIMX;
            is0[e] = ri[l]; is1[e] = ri[32 + l];
            iv0[e] = ri[64 + 3 * l]; iv1[e] = ri[65 + 3 * l]; iv2[e] = ri[66 + 3 * l];
            const float* rj = g_nf + (size_t)jjs[e] * DIMX;
            js0[e] = rj[l]; js1[e] = rj[32 + l];
            jv0[e] = rj[64 + 3 * l]; jv1[e] = rj[65 + 3 * l]; jv2[e] = rj[66 + 3 * l];
            const float* re = ef + (size_t)ecs[e] * DIMX;
            es0[e] = re[l]; es1[e] = re[32 + l];
            ev0[e] = re[64 + 3 * l]; ev1[e] = re[65 + 3 * l]; ev2[e] = re[66 + 3 * l];
            shp[e] = *(const float4*)(esh + (size_t)ecs[e] * 4);
        }
        float sh0r[EA_E], s10[EA_E], s11[EA_E], s12[EA_E];
#pragma unroll
        for (int e = 0; e < EA_E; e++) {
            float* sA = ST + e * 576;
            float* vA = sA + 192;
            float* u = sA + 480;
            sA[l] = is0[e]; sA[32 + l] = is1[e];
            vA[l] = iv0[e]; vA[96 + l] = iv1[e]; vA[192 + l] = iv2[e];
            sA[128 + l] = js0[e]; sA[160 + l] = js1[e];
            vA[64 + l] = jv0[e]; vA[160 + l] = jv1[e]; vA[256 + l] = jv2[e];
            float s0 = es0[e], s1 = es1[e];
            float mu = wsum(s0 + s1) * (1.f / 64.f);
            float m2 = wsum(s0 * s0 + s1 * s1) * (1.f / 64.f);
            float rsv = rsqrtf(m2 - mu * mu + EPSF);
            sA[64 + l] = (s0 - mu) * rsv * egs[l] + ebs[l];
            sA[96 + l] = (s1 - mu) * rsv * egs[32 + l] + ebs[32 + l];
            float rmi = rsqrtf(wsum(ev0[e] * ev0[e] + ev1[e] * ev1[e] + ev2[e] * ev2[e]) * (1.f / 32.f) + EPSF);
            float gk = egv[l] * rmi;
            float e0 = ev0[e] * gk, e1 = ev1[e] * gk, e2 = ev2[e] * gk;
            vA[32 + l] = e0; vA[128 + l] = e1; vA[224 + l] = e2;
            sh0r[e] = shp[e].x; s10[e] = shp[e].y; s11[e] = shp[e].z; s12[e] = shp[e].w;
            u[l]      = (iv0[e] * s10[e] + iv1[e] * s11[e] + iv2[e] * s12[e]) * INV_SQ3;
            u[32 + l] = (e0 * s10[e] + e1 * s11[e] + e2 * s12[e]) * INV_SQ3;
            u[64 + l] = (jv0[e] * s10[e] + jv1[e] * s11[e] + jv2[e] * s12[e]) * INV_SQ3;
        }
        __syncwarp();
        u64 aA[3][EA_E];
#pragma unroll
        for (int j = 0; j < 3; j++)
#pragma unroll
            for (int e = 0; e < EA_E; e++) aA[j][e] = 0ull;
        for (int k = 0; k < 192; k += 4) {
            ulonglong2 w0 = ld2(&WaT[l * 196 + k]);
            ulonglong2 w1 = ld2(&WaT[(l + 32) * 196 + k]);
            ulonglong2 w2 = ld2(&WaT[(l + 64) * 196 + k]);
#pragma unroll
            for (int e = 0; e < EA_E; e++) {
                ulonglong2 x = ld2(&ST[e * 576 + k]);
                ffma2(aA[0][e], x.x, w0.x); ffma2(aA[0][e], x.y, w0.y);
                ffma2(aA[1][e], x.x, w1.x); ffma2(aA[1][e], x.y, w1.y);
                ffma2(aA[2][e], x.x, w2.x); ffma2(aA[2][e], x.y, w2.y);
            }
        }
        float fA[3][EA_E];
#pragma unroll
        for (int j = 0; j < 3; j++)
#pragma unroll
            for (int e = 0; e < EA_E; e++) fA[j][e] = hadd2(aA[j][e]);
        u64 aB[3][EA_E];
#pragma unroll
        for (int j = 0; j < 3; j++)
#pragma unroll
            for (int e = 0; e < EA_E; e++) aB[j][e] = 0ull;
        for (int k = 0; k < 96; k += 4) {
            ulonglong2 w0 = ld2(&WbT[l * 100 + k]);
            ulonglong2 w1 = ld2(&WbT[(l + 32) * 100 + k]);
            ulonglong2 w2 = ld2(&WbT[(l + 64) * 100 + k]);
#pragma unroll
            for (int e = 0; e < EA_E; e++) {
                ulonglong2 x = ld2(&ST[e * 576 + 480 + k]);
                ffma2(aB[0][e], x.x, w0.x); ffma2(aB[0][e], x.y, w0.y);
                ffma2(aB[1][e], x.x, w1.x); ffma2(aB[1][e], x.y, w1.y);
                ffma2(aB[2][e], x.x, w2.x); ffma2(aB[2][e], x.y, w2.y);
            }
        }
        float os[3][EA_E];
#pragma unroll
        for (int j = 0; j < 3; j++)
#pragma unroll
            for (int e = 0; e < EA_E; e++) os[j][e] = fmaf(sh0r[e], fA[j][e], hadd2(aB[j][e]));
        u64 swc[EA_E], wd[3][EA_E];
#pragma unroll
        for (int e = 0; e < EA_E; e++) { swc[e] = 0ull; wd[0][e] = 0ull; wd[1][e] = 0ull; wd[2][e] = 0ull; }
        for (int k = 0; k < 192; k += 4) {
            ulonglong2 w = ld2(&WcT[l * 196 + k]);
#pragma unroll
            for (int e = 0; e < EA_E; e++) {
                ulonglong2 x = ld2(&ST[e * 576 + k]);
                ffma2(swc[e], x.x, w.x); ffma2(swc[e], x.y, w.y);
            }
        }
        for (int k = 0; k < 96; k += 4) {
            ulonglong2 w = ld2(&WdT[l * 100 + k]);
#pragma unroll
            for (int e = 0; e < EA_E; e++) {
#pragma unroll
                for (int c = 0; c < 3; c++) {
                    ulonglong2 x = ld2(&ST[e * 576 + 192 + 96 * c + k]);
                    ffma2(wd[c][e], x.x, w.x); ffma2(wd[c][e], x.y, w.y);
                }
            }
        }
#pragma unroll
        for (int e = 0; e < EA_E; e++) {
            int eg = eb + e;
            if (eg < n_act) {
                float gate = sigm(os[2][e]);
                g_ms[(size_t)eg * 64 + l] = os[0][e] * sigm(os[0][e]);
                g_ms[(size_t)eg * 64 + 32 + l] = os[1][e] * sigm(os[1][e]);
                float s1c[3] = { s10[e], s11[e], s12[e] };
                float sw = hadd2(swc[e]);
#pragma unroll
                for (int c = 0; c < 3; c++) {
                    float ov = fmaf(sw, s1c[c], hadd2(wd[c][e]) * sh0r[e]);
                    g_mv[(size_t)eg * 96 + 3 * l + c] = ov * gate;
                }
                float* li = g_lat_in + (size_t)eg * 232;
                li[132 + l] = os[0][e]; li[164 + l] = os[1][e]; li[196 + l] = os[2][e];
                if (l < 4) { li[l] = onehot[iis[e] * 4 + l]; li[228 + l] = onehot[jjs[e] * 4 + l]; }
            }
        }
        __syncwarp();
    }
}

// ===================== K2b: W_edge / Wp / Wres + latent LN + edge_out =====================
#define EB_T 512
#define EB_W 16
#define EB_E 4
#define SMEM_B ((96*132 + 64*68 + 32*36 + 64*68 + 32*36 + EB_W*EB_E*448) * 4)
__global__ __launch_bounds__(EB_T, 1) void k_edge_b(
    const float* __restrict__ latents, const float* __restrict__ ef,
    const int* __restrict__ act,
    const float* __restrict__ lg, const float* __restrict__ lb,
    const float* __restrict__ We, const float* __restrict__ Wps, const float* __restrict__ Wpv,
    const float* __restrict__ Wrs, const float* __restrict__ Wrv,
    float* __restrict__ out_edge, int n_act) {
    extern __shared__ float sm[];
    float* WeT = sm;
    float* WpsT = WeT + 96 * 132;
    float* WpvT = WpsT + 64 * 68;
    float* WrsT = WpvT + 32 * 36;
    float* WrvT = WrsT + 64 * 68;
    float* STG = WrvT + 32 * 36;
    int tid = threadIdx.x;
    for (int i = tid; i < 128 * 96; i += EB_T) WeT[(i % 96) * 132 + i / 96] = We[i];
    for (int i = tid; i < 64 * 64; i += EB_T)  WpsT[(i % 64) * 68 + i / 64] = Wps[i];
    for (int i = tid; i < 32 * 32; i += EB_T)  WpvT[(i % 32) * 36 + i / 32] = Wpv[i];
    for (int i = tid; i < 64 * 64; i += EB_T)  WrsT[(i % 64) * 68 + i / 64] = Wrs[i];
    for (int i = tid; i < 32 * 32; i += EB_T)  WrvT[(i % 32) * 36 + i / 32] = Wrv[i];
    __syncthreads();
    int wq = tid >> 5, l = tid & 31;
    float* ST = STG + wq * (EB_E * 448);
    int gw = blockIdx.x * EB_W + wq;
    int stride = gridDim.x * EB_W * EB_E;
    for (int eb = gw * EB_E; eb < n_act; eb += stride) {
#pragma unroll
        for (int half = 0; half < 2; half++) {
            int ecs[2], aes[2];
            float lx[2][4], msr[2][2], mvr[2][3], res[2][2], rev[2][3];
#pragma unroll
            for (int q = 0; q < 2; q++) {
                int ec = eb + half * 2 + q;
                ecs[q] = ec < n_act ? ec : n_act - 1;
            }
#pragma unroll
            for (int q = 0; q < 2; q++) aes[q] = act[ecs[q]];
#pragma unroll
            for (int q = 0; q < 2; q++) {
                const float* la = latents + (size_t)aes[q] * 128;
                lx[q][0] = la[l]; lx[q][1] = la[32 + l]; lx[q][2] = la[64 + l]; lx[q][3] = la[96 + l];
                const float* ms = g_ms + (size_t)ecs[q] * 64;
                msr[q][0] = ms[l]; msr[q][1] = ms[32 + l];
                const float* mv = g_mv + (size_t)ecs[q] * 96;
                mvr[q][0] = mv[3 * l]; mvr[q][1] = mv[3 * l + 1]; mvr[q][2] = mv[3 * l + 2];
                const float* re = ef + (size_t)ecs[q] * DIMX;
                res[q][0] = re[l]; res[q][1] = re[32 + l];
                rev[q][0] = re[64 + 3 * l]; rev[q][1] = re[65 + 3 * l]; rev[q][2] = re[66 + 3 * l];
            }
#pragma unroll
            for (int q = 0; q < 2; q++) {
                int e = half * 2 + q;
                float* S = ST + e * 448;
                float x0 = lx[q][0], x1 = lx[q][1], x2 = lx[q][2], x3 = lx[q][3];
                S[l] = x0; S[32 + l] = x1; S[64 + l] = x2; S[96 + l] = x3;
                float mu = wsum(x0 + x1 + x2 + x3) * (1.f / 128.f);
                float m2 = wsum(x0 * x0 + x1 * x1 + x2 * x2 + x3 * x3) * (1.f / 128.f);
                float rsv = rsqrtf(m2 - mu * mu + EPSF);
                int eg = eb + e;
                if (eg < n_act) {
                    float* li = g_lat_in + (size_t)eg * 232 + 4;
                    li[l] = (x0 - mu) * rsv * lg[l] + lb[l];
                    li[32 + l] = (x1 - mu) * rsv * lg[32 + l] + lb[32 + l];
                    li[64 + l] = (x2 - mu) * rsv * lg[64 + l] + lb[64 + l];
                    li[96 + l] = (x3 - mu) * rsv * lg[96 + l] + lb[96 + l];
                }
                S[128 + l] = msr[q][0]; S[160 + l] = msr[q][1];
                S[192 + l] = mvr[q][0]; S[224 + l] = mvr[q][1]; S[256 + l] = mvr[q][2];
                S[288 + l] = res[q][0]; S[320 + l] = res[q][1];
                S[352 + l] = rev[q][0]; S[384 + l] = rev[q][1]; S[416 + l] = rev[q][2];
            }
        }
        __syncwarp();
        u64 ww[3][EB_E];
#pragma unroll
        for (int j = 0; j < 3; j++)
#pragma unroll
            for (int e = 0; e < EB_E; e++) ww[j][e] = 0ull;
        for (int k = 0; k < 128; k += 4) {
            ulonglong2 w0 = ld2(&WeT[l * 132 + k]);
            ulonglong2 w1 = ld2(&WeT[(l + 32) * 132 + k]);
            ulonglong2 w2 = ld2(&WeT[(l + 64) * 132 + k]);
#pragma unroll
            for (int e = 0; e < EB_E; e++) {
                ulonglong2 x = ld2(&ST[e * 448 + k]);
                ffma2(ww[0][e], x.x, w0.x); ffma2(ww[0][e], x.y, w0.y);
                ffma2(ww[1][e], x.x, w1.x); ffma2(ww[1][e], x.y, w1.y);
                ffma2(ww[2][e], x.x, w2.x); ffma2(ww[2][e], x.y, w2.y);
            }
        }
        float fw[3][EB_E];
#pragma unroll
        for (int j = 0; j < 3; j++)
#pragma unroll
            for (int e = 0; e < EB_E; e++) fw[j][e] = hadd2(ww[j][e]);
        u64 ps[2][EB_E], rs[2][EB_E];
#pragma unroll
        for (int e = 0; e < EB_E; e++) { ps[0][e] = ps[1][e] = rs[0][e] = rs[1][e] = 0ull; }
        for (int k = 0; k < 64; k += 4) {
            ulonglong2 p0 = ld2(&WpsT[l * 68 + k]);
            ulonglong2 p1 = ld2(&WpsT[(l + 32) * 68 + k]);
            ulonglong2 r0 = ld2(&WrsT[l * 68 + k]);
            ulonglong2 r1 = ld2(&WrsT[(l + 32) * 68 + k]);
#pragma unroll
            for (int e = 0; e < EB_E; e++) {
                ulonglong2 xm = ld2(&ST[e * 448 + 128 + k]);
                ulonglong2 xr = ld2(&ST[e * 448 + 288 + k]);
                ffma2(ps[0][e], xm.x, p0.x); ffma2(ps[0][e], xm.y, p0.y);
                ffma2(ps[1][e], xm.x, p1.x); ffma2(ps[1][e], xm.y, p1.y);
                ffma2(rs[0][e], xr.x, r0.x); ffma2(rs[0][e], xr.y, r0.y);
                ffma2(rs[1][e], xr.x, r1.x); ffma2(rs[1][e], xr.y, r1.y);
            }
        }
        float fps[2][EB_E], frs[2][EB_E];
#pragma unroll
        for (int j = 0; j < 2; j++)
#pragma unroll
            for (int e = 0; e < EB_E; e++) { fps[j][e] = hadd2(ps[j][e]); frs[j][e] = hadd2(rs[j][e]); }
        u64 pv[3][EB_E], rv[3][EB_E];
#pragma unroll
        for (int c = 0; c < 3; c++)
#pragma unroll
            for (int e = 0; e < EB_E; e++) { pv[c][e] = 0ull; rv[c][e] = 0ull; }
        for (int k = 0; k < 32; k += 4) {
            ulonglong2 pw = ld2(&WpvT[l * 36 + k]);
            ulonglong2 rw = ld2(&WrvT[l * 36 + k]);
#pragma unroll
            for (int e = 0; e < EB_E; e++) {
#pragma unroll
                for (int c = 0; c < 3; c++) {
                    ulonglong2 xm = ld2(&ST[e * 448 + 192 + 32 * c + k]);
                    ulonglong2 xr = ld2(&ST[e * 448 + 352 + 32 * c + k]);
                    ffma2(pv[c][e], xm.x, pw.x); ffma2(pv[c][e], xm.y, pw.y);
                    ffma2(rv[c][e], xr.x, rw.x); ffma2(rv[c][e], xr.y, rw.y);
                }
            }
        }
#pragma unroll
        for (int e = 0; e < EB_E; e++) {
            int eg = eb + e;
            if (eg < n_act) {
                float* oe = out_edge + (size_t)eg * DIMX;
                oe[l] = fmaf(fps[0][e], fw[0][e], frs[0][e]);
                oe[32 + l] = fmaf(fps[1][e], fw[1][e], frs[1][e]);
#pragma unroll
                for (int c = 0; c < 3; c++)
                    oe[64 + 3 * l + c] = fmaf(hadd2(pv[c][e]), fw[2][e], hadd2(rv[c][e]));
            }
        }
        __syncwarp();
    }
}

// ===================== K3: GEMM1 hid = silu(lat_in @ W1), 512 threads, A dbl-buf =====================
#define M1_SMEM ((2 * 240 * 136 + 2 * 128 * 136) * 2)
__global__ __launch_bounds__(512, 1) void k_mma1(const float* __restrict__ W1, int n_act) {
    extern __shared__ __nv_bfloat16 sb[];
    __nv_bfloat16* Wh = sb;
    __nv_bfloat16* Wl = Wh + 240 * 136;
    __nv_bfloat16* Ah = Wl + 240 * 136;
    __nv_bfloat16* Al = Ah + 128 * 136;
    int tid = threadIdx.x, wid = tid >> 5, lane = tid & 31;
    int base = blockIdx.y * 128;
    for (int i = tid; i < 240 * 128; i += 512) {
        int k = i >> 7, n = i & 127;
        float w = (k < 232) ? W1[k * 256 + base + n] : 0.f;
        __nv_bfloat16 h = __float2bfloat16(w);
        Wh[k * 136 + n] = h;
        Wl[k * 136 + n] = __float2bfloat16(w - __bfloat162float(h));
    }
    uint32_t aWh = s2u(Wh), aWl = s2u(Wl), aAh = s2u(Ah), aAl = s2u(Al);
    int warp_m = wid & 7, warp_n = wid >> 3;
    int ntile = (n_act + 127) >> 7;
    int c4 = lane * 4;
    for (int tile = blockIdx.x; tile < ntile; tile += gridDim.x) {
        int nt = tile + gridDim.x;
        if (nt < ntile) {
            const char* p = (const char*)(g_lat_in + (size_t)nt * 128 * 232);
            for (int i = tid; i < 928; i += 512) pf_l2(p + (size_t)i * 128);
        }
        float C[8][4];
#pragma unroll
        for (int b = 0; b < 8; b++)
#pragma unroll
            for (int c = 0; c < 4; c++) C[b][c] = 0.f;
#pragma unroll 1
        for (int chunk = 0; chunk < 2; chunk++) {
            int k0 = chunk * 128;
            int cw = chunk ? 112 : 128;
            int kw = chunk ? 104 : 128;
            int nks = chunk ? 7 : 8;
            __syncthreads();
            // batched staging loads (transient regs), then split+store
            {
                float4 vb[8];
#pragma unroll
                for (int rr = 0; rr < 8; rr++) {
                    int r = wid * 8 + rr;
                    int eg = tile * 128 + r;
                    int ec = eg < n_act ? eg : n_act - 1;
                    const float* li = g_lat_in + (size_t)ec * 232 + k0;
                    float4 v = make_float4(0.f, 0.f, 0.f, 0.f);
                    if (c4 < cw) {
                        if (c4 + 3 < kw) v = *(const float4*)(li + c4);
                        else {
                            v.x = (c4 + 0 < kw) ? li[c4 + 0] : 0.f;
                            v.y = (c4 + 1 < kw) ? li[c4 + 1] : 0.f;
                            v.z = (c4 + 2 < kw) ? li[c4 + 2] : 0.f;
                            v.w = (c4 + 3 < kw) ? li[c4 + 3] : 0.f;
                        }
                    }
                    vb[rr] = v;
                }
#pragma unroll
                for (int rr = 0; rr < 8; rr++) {
                    if (c4 < cw) {
                        int r = wid * 8 + rr;
                        uint32_t h0, l0, h1, l1;
                        split2(vb[rr].x, vb[rr].y, h0, l0);
                        split2(vb[rr].z, vb[rr].w, h1, l1);
                        *(uint2*)&Ah[r * 136 + c4] = make_uint2(h0, h1);
                        *(uint2*)&Al[r * 136 + c4] = make_uint2(l0, l1);
                    }
                }
            }
            __syncthreads();
            int arow = warp_m * 16 + (lane & 15);
            int acolb = (lane >> 4) << 3;
            // A fragment double buffer
            uint32_t fAh[2][4], fAl[2][4];
            {
                uint32_t ao = (uint32_t)((arow * 136 + acolb) * 2);
                ldsm4(fAh[0], aAh + ao);
                ldsm4(fAl[0], aAl + ao);
            }
#pragma unroll 1
            for (int ks = 0; ks < nks; ks++) {
                int cur = ks & 1, nxt = cur ^ 1;
                if (ks + 1 < nks) {
                    uint32_t ao = (uint32_t)((arow * 136 + (ks + 1) * 16 + acolb) * 2);
                    ldsm4(fAh[nxt], aAh + ao);
                    ldsm4(fAl[nxt], aAl + ao);
                }
#pragma unroll
                for (int ng = 0; ng < 4; ng++) {
                    int brow = k0 + ks * 16 + (lane & 15);
                    int bcol = warp_n * 64 + ng * 16 + acolb;
                    uint32_t bo = (uint32_t)((brow * 136 + bcol) * 2);
                    uint32_t fBh[4], fBl[4];
                    ldsm4t(fBh, aWh + bo);
                    ldsm4t(fBl, aWl + bo);
                    mma16816(C[ng * 2],     fAh[cur], fBh);
                    mma16816(C[ng * 2],     fAl[cur], fBh);
                    mma16816(C[ng * 2],     fAh[cur], fBl);
                    mma16816(C[ng * 2 + 1], fAh[cur], fBh + 2);
                    mma16816(C[ng * 2 + 1], fAl[cur], fBh + 2);
                    mma16816(C[ng * 2 + 1], fAh[cur], fBl + 2);
                }
            }
        }
#pragma unroll
        for (int p = 0; p < 2; p++) {
            int row = tile * 128 + warp_m * 16 + (lane >> 2) + p * 8;
            if (row < n_act) {
#pragma unroll
                for (int n8 = 0; n8 < 8; n8++) {
                    float v0 = C[n8][p * 2], v1 = C[n8][p * 2 + 1];
                    v0 = v0 * sigm(v0); v1 = v1 * sigm(v1);
                    uint32_t hw, lw;
                    split2(v0, v1, hw, lw);
                    int col = base + warp_n * 64 + n8 * 8 + (lane & 3) * 2;
                    *(uint32_t*)&g_hidh[(size_t)row * 256 + col] = hw;
                    *(uint32_t*)&g_hidl[(size_t)row * 256 + col] = lw;
                }
            }
        }
    }
}

// ===================== K4: GEMM2 out = (hid @ W2) * cutoff, 512 threads, A dbl-buf =====================
#define M2_SMEM ((2 * 256 * 136 + 2 * 128 * 136) * 2)
__global__ __launch_bounds__(512, 1) void k_mma2(
    const float* __restrict__ W2, const int* __restrict__ act,
    const float* __restrict__ cutoff, float* __restrict__ out_lat, int n_act) {
    extern __shared__ __nv_bfloat16 sb[];
    __nv_bfloat16* Wh = sb;
    __nv_bfloat16* Wl = Wh + 256 * 136;
    __nv_bfloat16* Ah = Wl + 256 * 136;
    __nv_bfloat16* Al = Ah + 128 * 136;
    int tid = threadIdx.x, wid = tid >> 5, lane = tid & 31;
    for (int i = tid; i < 256 * 128; i += 512) {
        int k = i >> 7, n = i & 127;
        float w = W2[k * 128 + n];
        __nv_bfloat16 h = __float2bfloat16(w);
        Wh[k * 136 + n] = h;
        Wl[k * 136 + n] = __float2bfloat16(w - __bfloat162float(h));
    }
    uint32_t aWh = s2u(Wh), aWl = s2u(Wl), aAh = s2u(Ah), aAl = s2u(Al);
    int warp_m = wid & 7, warp_n = wid >> 3;
    int ntile = (n_act + 127) >> 7;
    int c4 = lane * 4;
    for (int tile = blockIdx.x; tile < ntile; tile += gridDim.x) {
        int nt = tile + gridDim.x;
        if (nt < ntile) {
            const char* ph = (const char*)(g_hidh + (size_t)nt * 128 * 256);
            const char* pl = (const char*)(g_hidl + (size_t)nt * 128 * 256);
            pf_l2(ph + (size_t)tid * 128); pf_l2(pl + (size_t)tid * 128);
        }
        float C[8][4];
#pragma unroll
        for (int b = 0; b < 8; b++)
#pragma unroll
            for (int c = 0; c < 4; c++) C[b][c] = 0.f;
#pragma unroll 1
        for (int chunk = 0; chunk < 2; chunk++) {
            int k0 = chunk * 128;
            __syncthreads();
            {
                uint2 vh[8], vl[8];
#pragma unroll
                for (int rr = 0; rr < 8; rr++) {
                    int r = wid * 8 + rr;
                    int eg = tile * 128 + r;
                    int ec = eg < n_act ? eg : n_act - 1;
                    vh[rr] = *(const uint2*)(g_hidh + (size_t)ec * 256 + k0 + c4);
                    vl[rr] = *(const uint2*)(g_hidl + (size_t)ec * 256 + k0 + c4);
                }
#pragma unroll
                for (int rr = 0; rr < 8; rr++) {
                    int r = wid * 8 + rr;
                    *(uint2*)&Ah[r * 136 + c4] = vh[rr];
                    *(uint2*)&Al[r * 136 + c4] = vl[rr];
                }
            }
            __syncthreads();
            int arow = warp_m * 16 + (lane & 15);
            int acolb = (lane >> 4) << 3;
            uint32_t fAh[2][4], fAl[2][4];
            {
                uint32_t ao = (uint32_t)((arow * 136 + acolb) * 2);
                ldsm4(fAh[0], aAh + ao);
                ldsm4(fAl[0], aAl + ao);
            }
#pragma unroll 1
            for (int ks = 0; ks < 8; ks++) {
                int cur = ks & 1, nxt = cur ^ 1;
                if (ks + 1 < 8) {
                    uint32_t ao = (uint32_t)((arow * 136 + (ks + 1) * 16 + acolb) * 2);
                    ldsm4(fAh[nxt], aAh + ao);
                    ldsm4(fAl[nxt], aAl + ao);
                }
#pragma unroll
                for (int ng = 0; ng < 4; ng++) {
                    int brow = k0 + ks * 16 + (lane & 15);
                    int bcol = warp_n * 64 + ng * 16 + acolb;
                    uint32_t bo = (uint32_t)((brow * 136 + bcol) * 2);
                    uint32_t fBh[4], fBl[4];
                    ldsm4t(fBh, aWh + bo);
                    ldsm4t(fBl, aWl + bo);
                    mma16816(C[ng * 2],     fAh[cur], fBh);
                    mma16816(C[ng * 2],     fAl[cur], fBh);
                    mma16816(C[ng * 2],     fAh[cur], fBl);
                    mma16816(C[ng * 2 + 1], fAh[cur], fBh + 2);
                    mma16816(C[ng * 2 + 1], fAl[cur], fBh + 2);
                    mma16816(C[ng * 2 + 1], fAh[cur], fBl + 2);
                }
            }
        }
#pragma unroll
        for (int p = 0; p < 2; p++) {
            int eg = tile * 128 + warp_m * 16 + (lane >> 2) + p * 8;
            if (eg < n_act) {
                int ae = act[eg];
                float cc = cutoff[ae];
                float* o = out_lat + (size_t)ae * 128;
#pragma unroll
                for (int n8 = 0; n8 < 8; n8++) {
                    int col = warp_n * 64 + n8 * 8 + (lane & 3) * 2;
                    float2 v;
                    v.x = C[n8][p * 2] * cc;
                    v.y = C[n8][p * 2 + 1] * cc;
                    *(float2*)(o + col) = v;
                }
            }
        }
    }
}

// ===================== launcher =====================
extern "C" void kernel_launch(void* const* d_in, const int* in_sizes, int n_in,
                              void* d_out, int out_size) {
    const float* latents   = (const float*)d_in[0];
    const float* node_feat = (const float*)d_in[1];
    const float* onehot    = (const float*)d_in[2];
    const float* edge_feat = (const float*)d_in[3];
    const float* edge_sh   = (const float*)d_in[4];
    const int*   edge_idx  = (const int*)d_in[5];
    const float* cutoff    = (const float*)d_in[6];
    const int*   act       = (const int*)d_in[7];
    const float* n_gs = (const float*)d_in[8];
    const float* n_bs = (const float*)d_in[9];
    const float* n_gv = (const float*)d_in[10];
    const float* e_gs = (const float*)d_in[11];
    const float* e_bs = (const float*)d_in[12];
    const float* e_gv = (const float*)d_in[13];
    const float* lg   = (const float*)d_in[14];
    const float* lb   = (const float*)d_in[15];
    const float* Wa   = (const float*)d_in[16];
    const float* Wb   = (const float*)d_in[17];
    const float* Wc   = (const float*)d_in[18];
    const float* Wd   = (const float*)d_in[19];
    const float* Wps  = (const float*)d_in[20];
    const float* Wpv  = (const float*)d_in[21];
    const float* We   = (const float*)d_in[22];
    const float* W1   = (const float*)d_in[23];
    const float* W2   = (const float*)d_in[24];
    const float* Wrs  = (const float*)d_in[25];
    const float* Wrv  = (const float*)d_in[26];

    int n_nodes = in_sizes[1] / DIMX;
    int n_act   = in_sizes[7];
    int n_edges = in_sizes[6];

    float* out_edge = (float*)d_out;
    float* out_lat  = out_edge + (size_t)n_act * DIMX;

    cudaFuncSetAttribute(k_edge_a, cudaFuncAttributeMaxDynamicSharedMemorySize, SMEM_A);
    cudaFuncSetAttribute(k_edge_b, cudaFuncAttributeMaxDynamicSharedMemorySize, SMEM_B);
    cudaFuncSetAttribute(k_mma1,   cudaFuncAttributeMaxDynamicSharedMemorySize, M1_SMEM);
    cudaFuncSetAttribute(k_mma2,   cudaFuncAttributeMaxDynamicSharedMemorySize, M2_SMEM);

    cudaMemcpyAsync(out_lat, latents, (size_t)n_edges * 128 * sizeof(float),
                    cudaMemcpyDeviceToDevice, 0);

    int nb1 = (n_nodes * 32 + 255) / 256;
    k_node_norm<<<nb1, 256>>>(node_feat, n_gs, n_bs, n_gv, n_nodes);

    k_edge_a<<<148, EA_T, SMEM_A>>>(edge_feat, edge_sh, edge_idx, act, onehot,
                                    e_gs, e_bs, e_gv, Wa, Wb, Wc, Wd, n_act, n_edges);

    k_edge_b<<<148, EB_T, SMEM_B>>>(latents, edge_feat, act, lg, lb,
                                    We, Wps, Wpv, Wrs, Wrv, out_edge, n_act);

    k_mma1<<<dim3(148, 2), 512, M1_SMEM>>>(W1, n_act);

    k_mma2<<<148, 512, M2_SMEM>>>(W2, act, cutoff, out_lat, n_act);
}

// round 14
// speedup vs baseline: 1.1694x; 1.0375x over previous
#include <cuda_runtime.h>
#include <cuda_bf16.h>
#include <math.h>
#include <stdint.h>

#define DIMX 160
#define EPSF 1e-5f
#define INV_SQ3 0.57735026918962576451f
#define MAX_NODES 50000
#define MAX_ACT 200000

typedef unsigned long long u64;

__device__ float g_nf[MAX_NODES * DIMX];
__device__ float g_ms[MAX_ACT * 64];
__device__ float g_mv[MAX_ACT * 96];
__device__ float g_lat_in[MAX_ACT * 232];
__device__ __align__(16) __nv_bfloat16 g_hidh[(size_t)MAX_ACT * 256];
__device__ __align__(16) __nv_bfloat16 g_hidl[(size_t)MAX_ACT * 256];

__device__ __forceinline__ float wsum(float v) {
#pragma unroll
    for (int o = 16; o > 0; o >>= 1) v += __shfl_xor_sync(0xffffffffu, v, o);
    return v;
}
__device__ __forceinline__ float sigm(float x) { return 1.f / (1.f + expf(-x)); }
__device__ __forceinline__ void ffma2(u64& a, u64 x, u64 w) {
    asm("fma.rn.f32x2 %0, %1, %2, %0;" : "+l"(a) : "l"(x), "l"(w));
}
__device__ __forceinline__ float hadd2(u64 a) {
    return __uint_as_float((unsigned)a) + __uint_as_float((unsigned)(a >> 32));
}
__device__ __forceinline__ ulonglong2 ld2(const float* p) {
    return *reinterpret_cast<const ulonglong2*>(p);
}
__device__ __forceinline__ uint32_t s2u(const void* p) {
    uint32_t a;
    asm("{ .reg .u64 t; cvta.to.shared.u64 t, %1; cvt.u32.u64 %0, t; }" : "=r"(a) : "l"(p));
    return a;
}
__device__ __forceinline__ void pf_l2(const void* p) {
    asm volatile("prefetch.global.L2 [%0];" :: "l"(p));
}
__device__ __forceinline__ void mma16816(float* c, const uint32_t* a, const uint32_t* b) {
    asm volatile("mma.sync.aligned.m16n8k16.row.col.f32.bf16.bf16.f32 "
        "{%0,%1,%2,%3}, {%4,%5,%6,%7}, {%8,%9}, {%0,%1,%2,%3};"
        : "+f"(c[0]), "+f"(c[1]), "+f"(c[2]), "+f"(c[3])
        : "r"(a[0]), "r"(a[1]), "r"(a[2]), "r"(a[3]), "r"(b[0]), "r"(b[1]));
}
__device__ __forceinline__ void ldsm4(uint32_t* r, uint32_t a) {
    asm volatile("ldmatrix.sync.aligned.m8n8.x4.shared.b16 {%0,%1,%2,%3}, [%4];"
        : "=r"(r[0]), "=r"(r[1]), "=r"(r[2]), "=r"(r[3]) : "r"(a));
}
__device__ __forceinline__ void ldsm4t(uint32_t* r, uint32_t a) {
    asm volatile("ldmatrix.sync.aligned.m8n8.x4.trans.shared.b16 {%0,%1,%2,%3}, [%4];"
        : "=r"(r[0]), "=r"(r[1]), "=r"(r[2]), "=r"(r[3]) : "r"(a));
}
__device__ __forceinline__ void split2(float v0, float v1, uint32_t& hi, uint32_t& lo) {
    float h0 = __bfloat162float(__float2bfloat16(v0));
    float h1 = __bfloat162float(__float2bfloat16(v1));
    asm("cvt.rn.bf16x2.f32 %0, %1, %2;" : "=r"(hi) : "f"(v1), "f"(v0));
    float r0 = v0 - h0, r1 = v1 - h1;
    asm("cvt.rn.bf16x2.f32 %0, %1, %2;" : "=r"(lo) : "f"(r1), "f"(r0));
}

// ===================== K1: node SLN =====================
__global__ void k_node_norm(const float* __restrict__ nf, const float* __restrict__ gs,
                            const float* __restrict__ bs, const float* __restrict__ gv,
                            int n_nodes) {
    int w = (blockIdx.x * 256 + threadIdx.x) >> 5;
    int l = threadIdx.x & 31;
    if (w >= n_nodes) return;
    const float* r = nf + (size_t)w * DIMX;
    float s0 = r[l], s1 = r[32 + l];
    float mu = wsum(s0 + s1) * (1.f / 64.f);
    float m2 = wsum(s0 * s0 + s1 * s1) * (1.f / 64.f);
    float rsv = rsqrtf(m2 - mu * mu + EPSF);
    float v0 = r[64 + 3 * l], v1 = r[65 + 3 * l], v2 = r[66 + 3 * l];
    float rmi = rsqrtf(wsum(v0 * v0 + v1 * v1 + v2 * v2) * (1.f / 32.f) + EPSF);
    float* o = g_nf + (size_t)w * DIMX;
    o[l] = (s0 - mu) * rsv * gs[l] + bs[l];
    o[32 + l] = (s1 - mu) * rsv * gs[32 + l] + bs[32 + l];
    float gk = gv[l] * rmi;
    o[64 + 3 * l] = v0 * gk; o[65 + 3 * l] = v1 * gk; o[66 + 3 * l] = v2 * gk;
}

// ===================== K2a: gather + edge SLN + tensor product =====================
#define EA_T 256
#define EA_W 8
#define EA_E 4
#define SMEM_A ((96*196 + 96*100 + 32*196 + 32*100 + EA_W*EA_E*576) * 4)
__global__ __launch_bounds__(EA_T, 1) void k_edge_a(
    const float* __restrict__ ef, const float* __restrict__ esh,
    const int* __restrict__ eidx, const int* __restrict__ act,
    const float* __restrict__ onehot,
    const float* __restrict__ egs, const float* __restrict__ ebs, const float* __restrict__ egv,
    const float* __restrict__ Wa, const float* __restrict__ Wb,
    const float* __restrict__ Wc, const float* __restrict__ Wd,
    int n_act, int n_edges) {
    extern __shared__ float sm[];
    float* WaT = sm;
    float* WbT = WaT + 96 * 196;
    float* WcT = WbT + 96 * 100;
    float* WdT = WcT + 32 * 196;
    float* STG = WdT + 32 * 100;
    int tid = threadIdx.x;
    for (int i = tid; i < 192 * 96; i += EA_T) WaT[(i % 96) * 196 + i / 96] = Wa[i];
    for (int i = tid; i < 96 * 96; i += EA_T)  WbT[(i % 96) * 100 + i / 96] = Wb[i];
    for (int i = tid; i < 192 * 32; i += EA_T) WcT[(i % 32) * 196 + i / 32] = Wc[i];
    for (int i = tid; i < 96 * 32; i += EA_T)  WdT[(i % 32) * 100 + i / 32] = Wd[i];
    __syncthreads();
    int wq = tid >> 5, l = tid & 31;
    float* ST = STG + wq * (EA_E * 576);
    int gw = blockIdx.x * EA_W + wq;
    int stride = gridDim.x * EA_W * EA_E;
    for (int eb = gw * EA_E; eb < n_act; eb += stride) {
        int ecs[EA_E], aes[EA_E], iis[EA_E], jjs[EA_E];
#pragma unroll
        for (int e = 0; e < EA_E; e++) { int ec = eb + e; ecs[e] = ec < n_act ? ec : n_act - 1; }
#pragma unroll
        for (int e = 0; e < EA_E; e++) aes[e] = act[ecs[e]];
#pragma unroll
        for (int e = 0; e < EA_E; e++) { iis[e] = eidx[aes[e]]; jjs[e] = eidx[n_edges + aes[e]]; }
        float4 shp[EA_E];
        float is0[EA_E], is1[EA_E], iv0[EA_E], iv1[EA_E], iv2[EA_E];
        float js0[EA_E], js1[EA_E], jv0[EA_E], jv1[EA_E], jv2[EA_E];
        float es0[EA_E], es1[EA_E], ev0[EA_E], ev1[EA_E], ev2[EA_E];
#pragma unroll
        for (int e = 0; e < EA_E; e++) {
            const float* ri = g_nf + (size_t)iis[e] * DIMX;
            is0[e] = ri[l]; is1[e] = ri[32 + l];
            iv0[e] = ri[64 + 3 * l]; iv1[e] = ri[65 + 3 * l]; iv2[e] = ri[66 + 3 * l];
            const float* rj = g_nf + (size_t)jjs[e] * DIMX;
            js0[e] = rj[l]; js1[e] = rj[32 + l];
            jv0[e] = rj[64 + 3 * l]; jv1[e] = rj[65 + 3 * l]; jv2[e] = rj[66 + 3 * l];
            const float* re = ef + (size_t)ecs[e] * DIMX;
            es0[e] = re[l]; es1[e] = re[32 + l];
            ev0[e] = re[64 + 3 * l]; ev1[e] = re[65 + 3 * l]; ev2[e] = re[66 + 3 * l];
            shp[e] = *(const float4*)(esh + (size_t)ecs[e] * 4);
        }
        float sh0r[EA_E], s10[EA_E], s11[EA_E], s12[EA_E];
#pragma unroll
        for (int e = 0; e < EA_E; e++) {
            float* sA = ST + e * 576;
            float* vA = sA + 192;
            float* u = sA + 480;
            sA[l] = is0[e]; sA[32 + l] = is1[e];
            vA[l] = iv0[e]; vA[96 + l] = iv1[e]; vA[192 + l] = iv2[e];
            sA[128 + l] = js0[e]; sA[160 + l] = js1[e];
            vA[64 + l] = jv0[e]; vA[160 + l] = jv1[e]; vA[256 + l] = jv2[e];
            float s0 = es0[e], s1 = es1[e];
            float mu = wsum(s0 + s1) * (1.f / 64.f);
            float m2 = wsum(s0 * s0 + s1 * s1) * (1.f / 64.f);
            float rsv = rsqrtf(m2 - mu * mu + EPSF);
            sA[64 + l] = (s0 - mu) * rsv * egs[l] + ebs[l];
            sA[96 + l] = (s1 - mu) * rsv * egs[32 + l] + ebs[32 + l];
            float rmi = rsqrtf(wsum(ev0[e] * ev0[e] + ev1[e] * ev1[e] + ev2[e] * ev2[e]) * (1.f / 32.f) + EPSF);
            float gk = egv[l] * rmi;
            float e0 = ev0[e] * gk, e1 = ev1[e] * gk, e2 = ev2[e] * gk;
            vA[32 + l] = e0; vA[128 + l] = e1; vA[224 + l] = e2;
            sh0r[e] = shp[e].x; s10[e] = shp[e].y; s11[e] = shp[e].z; s12[e] = shp[e].w;
            u[l]      = (iv0[e] * s10[e] + iv1[e] * s11[e] + iv2[e] * s12[e]) * INV_SQ3;
            u[32 + l] = (e0 * s10[e] + e1 * s11[e] + e2 * s12[e]) * INV_SQ3;
            u[64 + l] = (jv0[e] * s10[e] + jv1[e] * s11[e] + jv2[e] * s12[e]) * INV_SQ3;
        }
        __syncwarp();
        // fused Wa + Wc pass over sA (shared x loads, 4 chains per edge)
        u64 aA[3][EA_E], swc[EA_E];
#pragma unroll
        for (int j = 0; j < 3; j++)
#pragma unroll
            for (int e = 0; e < EA_E; e++) aA[j][e] = 0ull;
#pragma unroll
        for (int e = 0; e < EA_E; e++) swc[e] = 0ull;
        for (int k = 0; k < 192; k += 4) {
            ulonglong2 w0 = ld2(&WaT[l * 196 + k]);
            ulonglong2 w1 = ld2(&WaT[(l + 32) * 196 + k]);
            ulonglong2 w2 = ld2(&WaT[(l + 64) * 196 + k]);
            ulonglong2 wc = ld2(&WcT[l * 196 + k]);
#pragma unroll
            for (int e = 0; e < EA_E; e++) {
                ulonglong2 x = ld2(&ST[e * 576 + k]);
                ffma2(aA[0][e], x.x, w0.x); ffma2(aA[0][e], x.y, w0.y);
                ffma2(aA[1][e], x.x, w1.x); ffma2(aA[1][e], x.y, w1.y);
                ffma2(aA[2][e], x.x, w2.x); ffma2(aA[2][e], x.y, w2.y);
                ffma2(swc[e],   x.x, wc.x); ffma2(swc[e],   x.y, wc.y);
            }
        }
        float fA[3][EA_E];
#pragma unroll
        for (int j = 0; j < 3; j++)
#pragma unroll
            for (int e = 0; e < EA_E; e++) fA[j][e] = hadd2(aA[j][e]);
        u64 aB[3][EA_E];
#pragma unroll
        for (int j = 0; j < 3; j++)
#pragma unroll
            for (int e = 0; e < EA_E; e++) aB[j][e] = 0ull;
        for (int k = 0; k < 96; k += 4) {
            ulonglong2 w0 = ld2(&WbT[l * 100 + k]);
            ulonglong2 w1 = ld2(&WbT[(l + 32) * 100 + k]);
            ulonglong2 w2 = ld2(&WbT[(l + 64) * 100 + k]);
#pragma unroll
            for (int e = 0; e < EA_E; e++) {
                ulonglong2 x = ld2(&ST[e * 576 + 480 + k]);
                ffma2(aB[0][e], x.x, w0.x); ffma2(aB[0][e], x.y, w0.y);
                ffma2(aB[1][e], x.x, w1.x); ffma2(aB[1][e], x.y, w1.y);
                ffma2(aB[2][e], x.x, w2.x); ffma2(aB[2][e], x.y, w2.y);
            }
        }
        float os[3][EA_E];
#pragma unroll
        for (int j = 0; j < 3; j++)
#pragma unroll
            for (int e = 0; e < EA_E; e++) os[j][e] = fmaf(sh0r[e], fA[j][e], hadd2(aB[j][e]));
        u64 wd[3][EA_E];
#pragma unroll
        for (int e = 0; e < EA_E; e++) { wd[0][e] = 0ull; wd[1][e] = 0ull; wd[2][e] = 0ull; }
        for (int k = 0; k < 96; k += 4) {
            ulonglong2 w = ld2(&WdT[l * 100 + k]);
#pragma unroll
            for (int e = 0; e < EA_E; e++) {
#pragma unroll
                for (int c = 0; c < 3; c++) {
                    ulonglong2 x = ld2(&ST[e * 576 + 192 + 96 * c + k]);
                    ffma2(wd[c][e], x.x, w.x); ffma2(wd[c][e], x.y, w.y);
                }
            }
        }
#pragma unroll
        for (int e = 0; e < EA_E; e++) {
            int eg = eb + e;
            if (eg < n_act) {
                float gate = sigm(os[2][e]);
                g_ms[(size_t)eg * 64 + l] = os[0][e] * sigm(os[0][e]);
                g_ms[(size_t)eg * 64 + 32 + l] = os[1][e] * sigm(os[1][e]);
                float s1c[3] = { s10[e], s11[e], s12[e] };
                float sw = hadd2(swc[e]);
#pragma unroll
                for (int c = 0; c < 3; c++) {
                    float ov = fmaf(sw, s1c[c], hadd2(wd[c][e]) * sh0r[e]);
                    g_mv[(size_t)eg * 96 + 3 * l + c] = ov * gate;
                }
                float* li = g_lat_in + (size_t)eg * 232;
                li[132 + l] = os[0][e]; li[164 + l] = os[1][e]; li[196 + l] = os[2][e];
                if (l < 4) { li[l] = onehot[iis[e] * 4 + l]; li[228 + l] = onehot[jjs[e] * 4 + l]; }
            }
        }
        __syncwarp();
    }
}

// ===================== K2b: W_edge / Wp / Wres + latent LN + edge_out =====================
#define EB_T 512
#define EB_W 16
#define EB_E 4
#define SMEM_B ((96*132 + 64*68 + 32*36 + 64*68 + 32*36 + EB_W*EB_E*448) * 4)
__global__ __launch_bounds__(EB_T, 1) void k_edge_b(
    const float* __restrict__ latents, const float* __restrict__ ef,
    const int* __restrict__ act,
    const float* __restrict__ lg, const float* __restrict__ lb,
    const float* __restrict__ We, const float* __restrict__ Wps, const float* __restrict__ Wpv,
    const float* __restrict__ Wrs, const float* __restrict__ Wrv,
    float* __restrict__ out_edge, int n_act) {
    extern __shared__ float sm[];
    float* WeT = sm;
    float* WpsT = WeT + 96 * 132;
    float* WpvT = WpsT + 64 * 68;
    float* WrsT = WpvT + 32 * 36;
    float* WrvT = WrsT + 64 * 68;
    float* STG = WrvT + 32 * 36;
    int tid = threadIdx.x;
    for (int i = tid; i < 128 * 96; i += EB_T) WeT[(i % 96) * 132 + i / 96] = We[i];
    for (int i = tid; i < 64 * 64; i += EB_T)  WpsT[(i % 64) * 68 + i / 64] = Wps[i];
    for (int i = tid; i < 32 * 32; i += EB_T)  WpvT[(i % 32) * 36 + i / 32] = Wpv[i];
    for (int i = tid; i < 64 * 64; i += EB_T)  WrsT[(i % 64) * 68 + i / 64] = Wrs[i];
    for (int i = tid; i < 32 * 32; i += EB_T)  WrvT[(i % 32) * 36 + i / 32] = Wrv[i];
    __syncthreads();
    int wq = tid >> 5, l = tid & 31;
    float* ST = STG + wq * (EB_E * 448);
    int gw = blockIdx.x * EB_W + wq;
    int stride = gridDim.x * EB_W * EB_E;
    for (int eb = gw * EB_E; eb < n_act; eb += stride) {
#pragma unroll
        for (int half = 0; half < 2; half++) {
            int ecs[2], aes[2];
            float lx[2][4], msr[2][2], mvr[2][3], res[2][2], rev[2][3];
#pragma unroll
            for (int q = 0; q < 2; q++) {
                int ec = eb + half * 2 + q;
                ecs[q] = ec < n_act ? ec : n_act - 1;
            }
#pragma unroll
            for (int q = 0; q < 2; q++) aes[q] = act[ecs[q]];
#pragma unroll
            for (int q = 0; q < 2; q++) {
                const float* la = latents + (size_t)aes[q] * 128;
                lx[q][0] = la[l]; lx[q][1] = la[32 + l]; lx[q][2] = la[64 + l]; lx[q][3] = la[96 + l];
                const float* ms = g_ms + (size_t)ecs[q] * 64;
                msr[q][0] = ms[l]; msr[q][1] = ms[32 + l];
                const float* mv = g_mv + (size_t)ecs[q] * 96;
                mvr[q][0] = mv[3 * l]; mvr[q][1] = mv[3 * l + 1]; mvr[q][2] = mv[3 * l + 2];
                const float* re = ef + (size_t)ecs[q] * DIMX;
                res[q][0] = re[l]; res[q][1] = re[32 + l];
                rev[q][0] = re[64 + 3 * l]; rev[q][1] = re[65 + 3 * l]; rev[q][2] = re[66 + 3 * l];
            }
#pragma unroll
            for (int q = 0; q < 2; q++) {
                int e = half * 2 + q;
                float* S = ST + e * 448;
                float x0 = lx[q][0], x1 = lx[q][1], x2 = lx[q][2], x3 = lx[q][3];
                S[l] = x0; S[32 + l] = x1; S[64 + l] = x2; S[96 + l] = x3;
                float mu = wsum(x0 + x1 + x2 + x3) * (1.f / 128.f);
                float m2 = wsum(x0 * x0 + x1 * x1 + x2 * x2 + x3 * x3) * (1.f / 128.f);
                float rsv = rsqrtf(m2 - mu * mu + EPSF);
                int eg = eb + e;
                if (eg < n_act) {
                    float* li = g_lat_in + (size_t)eg * 232 + 4;
                    li[l] = (x0 - mu) * rsv * lg[l] + lb[l];
                    li[32 + l] = (x1 - mu) * rsv * lg[32 + l] + lb[32 + l];
                    li[64 + l] = (x2 - mu) * rsv * lg[64 + l] + lb[64 + l];
                    li[96 + l] = (x3 - mu) * rsv * lg[96 + l] + lb[96 + l];
                }
                S[128 + l] = msr[q][0]; S[160 + l] = msr[q][1];
                S[192 + l] = mvr[q][0]; S[224 + l] = mvr[q][1]; S[256 + l] = mvr[q][2];
                S[288 + l] = res[q][0]; S[320 + l] = res[q][1];
                S[352 + l] = rev[q][0]; S[384 + l] = rev[q][1]; S[416 + l] = rev[q][2];
            }
        }
        __syncwarp();
        u64 ww[3][EB_E];
#pragma unroll
        for (int j = 0; j < 3; j++)
#pragma unroll
            for (int e = 0; e < EB_E; e++) ww[j][e] = 0ull;
        for (int k = 0; k < 128; k += 4) {
            ulonglong2 w0 = ld2(&WeT[l * 132 + k]);
            ulonglong2 w1 = ld2(&WeT[(l + 32) * 132 + k]);
            ulonglong2 w2 = ld2(&WeT[(l + 64) * 132 + k]);
#pragma unroll
            for (int e = 0; e < EB_E; e++) {
                ulonglong2 x = ld2(&ST[e * 448 + k]);
                ffma2(ww[0][e], x.x, w0.x); ffma2(ww[0][e], x.y, w0.y);
                ffma2(ww[1][e], x.x, w1.x); ffma2(ww[1][e], x.y, w1.y);
                ffma2(ww[2][e], x.x, w2.x); ffma2(ww[2][e], x.y, w2.y);
            }
        }
        float fw[3][EB_E];
#pragma unroll
        for (int j = 0; j < 3; j++)
#pragma unroll
            for (int e = 0; e < EB_E; e++) fw[j][e] = hadd2(ww[j][e]);
        u64 ps[2][EB_E], rs[2][EB_E];
#pragma unroll
        for (int e = 0; e < EB_E; e++) { ps[0][e] = ps[1][e] = rs[0][e] = rs[1][e] = 0ull; }
        for (int k = 0; k < 64; k += 4) {
            ulonglong2 p0 = ld2(&WpsT[l * 68 + k]);
            ulonglong2 p1 = ld2(&WpsT[(l + 32) * 68 + k]);
            ulonglong2 r0 = ld2(&WrsT[l * 68 + k]);
            ulonglong2 r1 = ld2(&WrsT[(l + 32) * 68 + k]);
#pragma unroll
            for (int e = 0; e < EB_E; e++) {
                ulonglong2 xm = ld2(&ST[e * 448 + 128 + k]);
                ulonglong2 xr = ld2(&ST[e * 448 + 288 + k]);
                ffma2(ps[0][e], xm.x, p0.x); ffma2(ps[0][e], xm.y, p0.y);
                ffma2(ps[1][e], xm.x, p1.x); ffma2(ps[1][e], xm.y, p1.y);
                ffma2(rs[0][e], xr.x, r0.x); ffma2(rs[0][e], xr.y, r0.y);
                ffma2(rs[1][e], xr.x, r1.x); ffma2(rs[1][e], xr.y, r1.y);
            }
        }
        float fps[2][EB_E], frs[2][EB_E];
#pragma unroll
        for (int j = 0; j < 2; j++)
#pragma unroll
            for (int e = 0; e < EB_E; e++) { fps[j][e] = hadd2(ps[j][e]); frs[j][e] = hadd2(rs[j][e]); }
        u64 pv[3][EB_E], rv[3][EB_E];
#pragma unroll
        for (int c = 0; c < 3; c++)
#pragma unroll
            for (int e = 0; e < EB_E; e++) { pv[c][e] = 0ull; rv[c][e] = 0ull; }
        for (int k = 0; k < 32; k += 4) {
            ulonglong2 pw = ld2(&WpvT[l * 36 + k]);
            ulonglong2 rw = ld2(&WrvT[l * 36 + k]);
#pragma unroll
            for (int e = 0; e < EB_E; e++) {
#pragma unroll
                for (int c = 0; c < 3; c++) {
                    ulonglong2 xm = ld2(&ST[e * 448 + 192 + 32 * c + k]);
                    ulonglong2 xr = ld2(&ST[e * 448 + 352 + 32 * c + k]);
                    ffma2(pv[c][e], xm.x, pw.x); ffma2(pv[c][e], xm.y, pw.y);
                    ffma2(rv[c][e], xr.x, rw.x); ffma2(rv[c][e], xr.y, rw.y);
                }
            }
        }
#pragma unroll
        for (int e = 0; e < EB_E; e++) {
            int eg = eb + e;
            if (eg < n_act) {
                float* oe = out_edge + (size_t)eg * DIMX;
                oe[l] = fmaf(fps[0][e], fw[0][e], frs[0][e]);
                oe[32 + l] = fmaf(fps[1][e], fw[1][e], frs[1][e]);
#pragma unroll
                for (int c = 0; c < 3; c++)
                    oe[64 + 3 * l + c] = fmaf(hadd2(pv[c][e]), fw[2][e], hadd2(rv[c][e]));
            }
        }
        __syncwarp();
    }
}

// ===================== K3: GEMM1 hid = silu(lat_in @ W1) =====================
#define M1_SMEM ((2 * 240 * 136 + 2 * 128 * 136) * 2)
__global__ __launch_bounds__(512, 1) void k_mma1(const float* __restrict__ W1, int n_act) {
    extern __shared__ __nv_bfloat16 sb[];
    __nv_bfloat16* Wh = sb;
    __nv_bfloat16* Wl = Wh + 240 * 136;
    __nv_bfloat16* Ah = Wl + 240 * 136;
    __nv_bfloat16* Al = Ah + 128 * 136;
    int tid = threadIdx.x, wid = tid >> 5, lane = tid & 31;
    int base = blockIdx.y * 128;
    for (int i = tid; i < 240 * 128; i += 512) {
        int k = i >> 7, n = i & 127;
        float w = (k < 232) ? W1[k * 256 + base + n] : 0.f;
        __nv_bfloat16 h = __float2bfloat16(w);
        Wh[k * 136 + n] = h;
        Wl[k * 136 + n] = __float2bfloat16(w - __bfloat162float(h));
    }
    uint32_t aWh = s2u(Wh), aWl = s2u(Wl), aAh = s2u(Ah), aAl = s2u(Al);
    uint32_t dWl = aWl - aWh;     // const offset Wh->Wl
    uint32_t dAl = aAl - aAh;     // const offset Ah->Al
    int warp_m = wid & 7, warp_n = wid >> 3;
    int ntile = (n_act + 127) >> 7;
    int c4 = lane * 4;
    int arow = warp_m * 16 + (lane & 15);
    int acolb = (lane >> 4) << 3;
    uint32_t aBaseW = (uint32_t)((arow * 136 + acolb) * 2);                      // A frag base (k=0)
    uint32_t bBaseW = (uint32_t)(((lane & 15) * 136 + warp_n * 64 + acolb) * 2); // B frag base (k=0)
    for (int tile = blockIdx.x; tile < ntile; tile += gridDim.x) {
        int nt = tile + gridDim.x;
        if (nt < ntile) {
            const char* p = (const char*)(g_lat_in + (size_t)nt * 128 * 232);
            for (int i = tid; i < 928; i += 512) pf_l2(p + (size_t)i * 128);
        }
        float C[8][4];
#pragma unroll
        for (int b = 0; b < 8; b++)
#pragma unroll
            for (int c = 0; c < 4; c++) C[b][c] = 0.f;
#pragma unroll 1
        for (int chunk = 0; chunk < 2; chunk++) {
            int k0 = chunk * 128;
            int cw = chunk ? 112 : 128;
            int kw = chunk ? 104 : 128;
            int nks = chunk ? 7 : 8;
            __syncthreads();
            {
                float4 vb[8];
#pragma unroll
                for (int rr = 0; rr < 8; rr++) {
                    int r = wid * 8 + rr;
                    int eg = tile * 128 + r;
                    int ec = eg < n_act ? eg : n_act - 1;
                    const float* li = g_lat_in + (size_t)ec * 232 + k0;
                    float4 v = make_float4(0.f, 0.f, 0.f, 0.f);
                    if (c4 < cw) {
                        if (c4 + 3 < kw) v = *(const float4*)(li + c4);
                        else {
                            v.x = (c4 + 0 < kw) ? li[c4 + 0] : 0.f;
                            v.y = (c4 + 1 < kw) ? li[c4 + 1] : 0.f;
                            v.z = (c4 + 2 < kw) ? li[c4 + 2] : 0.f;
                            v.w = (c4 + 3 < kw) ? li[c4 + 3] : 0.f;
                        }
                    }
                    vb[rr] = v;
                }
#pragma unroll
                for (int rr = 0; rr < 8; rr++) {
                    if (c4 < cw) {
                        int r = wid * 8 + rr;
                        uint32_t h0, l0, h1, l1;
                        split2(vb[rr].x, vb[rr].y, h0, l0);
                        split2(vb[rr].z, vb[rr].w, h1, l1);
                        *(uint2*)&Ah[r * 136 + c4] = make_uint2(h0, h1);
                        *(uint2*)&Al[r * 136 + c4] = make_uint2(l0, l1);
                    }
                }
            }
            __syncthreads();
            uint32_t aAddr = aAh + aBaseW;
            uint32_t bAddr = aWh + bBaseW + (uint32_t)(k0 * 136 * 2);
            uint32_t fAh[2][4], fAl[2][4];
            ldsm4(fAh[0], aAddr);
            ldsm4(fAl[0], aAddr + dAl);
            aAddr += 32;
#pragma unroll 1
            for (int ks = 0; ks < nks; ks++) {
                int cur = ks & 1, nxt = cur ^ 1;
                if (ks + 1 < nks) {
                    ldsm4(fAh[nxt], aAddr);
                    ldsm4(fAl[nxt], aAddr + dAl);
                    aAddr += 32;
                }
#pragma unroll
                for (int ng = 0; ng < 4; ng++) {
                    uint32_t bo = bAddr + (uint32_t)(ng * 32);
                    uint32_t fBh[4], fBl[4];
                    ldsm4t(fBh, bo);
                    ldsm4t(fBl, bo + dWl);
                    mma16816(C[ng * 2],     fAh[cur], fBh);
                    mma16816(C[ng * 2],     fAl[cur], fBh);
                    mma16816(C[ng * 2],     fAh[cur], fBl);
                    mma16816(C[ng * 2 + 1], fAh[cur], fBh + 2);
                    mma16816(C[ng * 2 + 1], fAl[cur], fBh + 2);
                    mma16816(C[ng * 2 + 1], fAh[cur], fBl + 2);
                }
                bAddr += (uint32_t)(16 * 136 * 2);
            }
        }
#pragma unroll
        for (int p = 0; p < 2; p++) {
            int row = tile * 128 + warp_m * 16 + (lane >> 2) + p * 8;
            if (row < n_act) {
#pragma unroll
                for (int n8 = 0; n8 < 8; n8++) {
                    float v0 = C[n8][p * 2], v1 = C[n8][p * 2 + 1];
                    v0 = v0 * sigm(v0); v1 = v1 * sigm(v1);
                    uint32_t hw, lw;
                    split2(v0, v1, hw, lw);
                    int col = base + warp_n * 64 + n8 * 8 + (lane & 3) * 2;
                    *(uint32_t*)&g_hidh[(size_t)row * 256 + col] = hw;
                    *(uint32_t*)&g_hidl[(size_t)row * 256 + col] = lw;
                }
            }
        }
    }
}

// ===================== K4: GEMM2 out = (hid @ W2) * cutoff =====================
#define M2_SMEM ((2 * 256 * 136 + 2 * 128 * 136) * 2)
__global__ __launch_bounds__(512, 1) void k_mma2(
    const float* __restrict__ W2, const int* __restrict__ act,
    const float* __restrict__ cutoff, float* __restrict__ out_lat, int n_act) {
    extern __shared__ __nv_bfloat16 sb[];
    __nv_bfloat16* Wh = sb;
    __nv_bfloat16* Wl = Wh + 256 * 136;
    __nv_bfloat16* Ah = Wl + 256 * 136;
    __nv_bfloat16* Al = Ah + 128 * 136;
    int tid = threadIdx.x, wid = tid >> 5, lane = tid & 31;
    for (int i = tid; i < 256 * 128; i += 512) {
        int k = i >> 7, n = i & 127;
        float w = W2[k * 128 + n];
        __nv_bfloat16 h = __float2bfloat16(w);
        Wh[k * 136 + n] = h;
        Wl[k * 136 + n] = __float2bfloat16(w - __bfloat162float(h));
    }
    uint32_t aWh = s2u(Wh), aWl = s2u(Wl), aAh = s2u(Ah), aAl = s2u(Al);
    uint32_t dWl = aWl - aWh;
    uint32_t dAl = aAl - aAh;
    int warp_m = wid & 7, warp_n = wid >> 3;
    int ntile = (n_act + 127) >> 7;
    int c4 = lane * 4;
    int arow = warp_m * 16 + (lane & 15);
    int acolb = (lane >> 4) << 3;
    uint32_t aBaseW = (uint32_t)((arow * 136 + acolb) * 2);
    uint32_t bBaseW = (uint32_t)(((lane & 15) * 136 + warp_n * 64 + acolb) * 2);
    for (int tile = blockIdx.x; tile < ntile; tile += gridDim.x) {
        int nt = tile + gridDim.x;
        if (nt < ntile) {
            const char* ph = (const char*)(g_hidh + (size_t)nt * 128 * 256);
            const char* pl = (const char*)(g_hidl + (size_t)nt * 128 * 256);
            pf_l2(ph + (size_t)tid * 128); pf_l2(pl + (size_t)tid * 128);
        }
        float C[8][4];
#pragma unroll
        for (int b = 0; b < 8; b++)
#pragma unroll
            for (int c = 0; c < 4; c++) C[b][c] = 0.f;
#pragma unroll 1
        for (int chunk = 0; chunk < 2; chunk++) {
            int k0 = chunk * 128;
            __syncthreads();
            {
                uint2 vh[8], vl[8];
#pragma unroll
                for (int rr = 0; rr < 8; rr++) {
                    int r = wid * 8 + rr;
                    int eg = tile * 128 + r;
                    int ec = eg < n_act ? eg : n_act - 1;
                    vh[rr] = *(const uint2*)(g_hidh + (size_t)ec * 256 + k0 + c4);
                    vl[rr] = *(const uint2*)(g_hidl + (size_t)ec * 256 + k0 + c4);
                }
#pragma unroll
                for (int rr = 0; rr < 8; rr++) {
                    int r = wid * 8 + rr;
                    *(uint2*)&Ah[r * 136 + c4] = vh[rr];
                    *(uint2*)&Al[r * 136 + c4] = vl[rr];
                }
            }
            __syncthreads();
            uint32_t aAddr = aAh + aBaseW;
            uint32_t bAddr = aWh + bBaseW + (uint32_t)(k0 * 136 * 2);
            uint32_t fAh[2][4], fAl[2][4];
            ldsm4(fAh[0], aAddr);
            ldsm4(fAl[0], aAddr + dAl);
            aAddr += 32;
#pragma unroll 1
            for (int ks = 0; ks < 8; ks++) {
                int cur = ks & 1, nxt = cur ^ 1;
                if (ks + 1 < 8) {
                    ldsm4(fAh[nxt], aAddr);
                    ldsm4(fAl[nxt], aAddr + dAl);
                    aAddr += 32;
                }
#pragma unroll
                for (int ng = 0; ng < 4; ng++) {
                    uint32_t bo = bAddr + (uint32_t)(ng * 32);
                    uint32_t fBh[4], fBl[4];
                    ldsm4t(fBh, bo);
                    ldsm4t(fBl, bo + dWl);
                    mma16816(C[ng * 2],     fAh[cur], fBh);
                    mma16816(C[ng * 2],     fAl[cur], fBh);
                    mma16816(C[ng * 2],     fAh[cur], fBl);
                    mma16816(C[ng * 2 + 1], fAh[cur], fBh + 2);
                    mma16816(C[ng * 2 + 1], fAl[cur], fBh + 2);
                    mma16816(C[ng * 2 + 1], fAh[cur], fBl + 2);
                }
                bAddr += (uint32_t)(16 * 136 * 2);
            }
        }
#pragma unroll
        for (int p = 0; p < 2; p++) {
            int eg = tile * 128 + warp_m * 16 + (lane >> 2) + p * 8;
            if (eg < n_act) {
                int ae = act[eg];
                float cc = cutoff[ae];
                float* o = out_lat + (size_t)ae * 128;
#pragma unroll
                for (int n8 = 0; n8 < 8; n8++) {
                    int col = warp_n * 64 + n8 * 8 + (lane & 3) * 2;
                    float2 v;
                    v.x = C[n8][p * 2] * cc;
                    v.y = C[n8][p * 2 + 1] * cc;
                    *(float2*)(o + col) = v;
                }
            }
        }
    }
}

// ===================== launcher =====================
extern "C" void kernel_launch(void* const* d_in, const int* in_sizes, int n_in,
                              void* d_out, int out_size) {
    const float* latents   = (const float*)d_in[0];
    const float* node_feat = (const float*)d_in[1];
    const float* onehot    = (const float*)d_in[2];
    const float* edge_feat = (const float*)d_in[3];
    const float* edge_sh   = (const float*)d_in[4];
    const int*   edge_idx  = (const int*)d_in[5];
    const float* cutoff    = (const float*)d_in[6];
    const int*   act       = (const int*)d_in[7];
    const float* n_gs = (const float*)d_in[8];
    const float* n_bs = (const float*)d_in[9];
    const float* n_gv = (const float*)d_in[10];
    const float* e_gs = (const float*)d_in[11];
    const float* e_bs = (const float*)d_in[12];
    const float* e_gv = (const float*)d_in[13];
    const float* lg   = (const float*)d_in[14];
    const float* lb   = (const float*)d_in[15];
    const float* Wa   = (const float*)d_in[16];
    const float* Wb   = (const float*)d_in[17];
    const float* Wc   = (const float*)d_in[18];
    const float* Wd   = (const float*)d_in[19];
    const float* Wps  = (const float*)d_in[20];
    const float* Wpv  = (const float*)d_in[21];
    const float* We   = (const float*)d_in[22];
    const float* W1   = (const float*)d_in[23];
    const float* W2   = (const float*)d_in[24];
    const float* Wrs  = (const float*)d_in[25];
    const float* Wrv  = (const float*)d_in[26];

    int n_nodes = in_sizes[1] / DIMX;
    int n_act   = in_sizes[7];
    int n_edges = in_sizes[6];

    float* out_edge = (float*)d_out;
    float* out_lat  = out_edge + (size_t)n_act * DIMX;

    cudaFuncSetAttribute(k_edge_a, cudaFuncAttributeMaxDynamicSharedMemorySize, SMEM_A);
    cudaFuncSetAttribute(k_edge_b, cudaFuncAttributeMaxDynamicSharedMemorySize, SMEM_B);
    cudaFuncSetAttribute(k_mma1,   cudaFuncAttributeMaxDynamicSharedMemorySize, M1_SMEM);
    cudaFuncSetAttribute(k_mma2,   cudaFuncAttributeMaxDynamicSharedMemorySize, M2_SMEM);

    cudaMemcpyAsync(out_lat, latents, (size_t)n_edges * 128 * sizeof(float),
                    cudaMemcpyDeviceToDevice, 0);

    int nb1 = (n_nodes * 32 + 255) / 256;
    k_node_norm<<<nb1, 256>>>(node_feat, n_gs, n_bs, n_gv, n_nodes);

    k_edge_a<<<148, EA_T, SMEM_A>>>(edge_feat, edge_sh, edge_idx, act, onehot,
                                    e_gs, e_bs, e_gv, Wa, Wb, Wc, Wd, n_act, n_edges);

    k_edge_b<<<148, EB_T, SMEM_B>>>(latents, edge_feat, act, lg, lb,
                                    We, Wps, Wpv, Wrs, Wrv, out_edge, n_act);

    k_mma1<<<dim3(148, 2), 512, M1_SMEM>>>(W1, n_act);

    k_mma2<<<148, 512, M2_SMEM>>>(W2, act, cutoff, out_lat, n_act);
}

// round 15
// speedup vs baseline: 1.1903x; 1.0178x over previous
#include <cuda_runtime.h>
#include <cuda_bf16.h>
#include <math.h>
#include <stdint.h>

#define DIMX 160
#define EPSF 1e-5f
#define INV_SQ3 0.57735026918962576451f
#define MAX_NODES 50000
#define MAX_ACT 200000

typedef unsigned long long u64;

__device__ float g_nf[MAX_NODES * DIMX];
__device__ float g_ms[MAX_ACT * 64];
__device__ float g_mv[MAX_ACT * 96];
// lat_in pre-split to bf16 hi/lo, rows padded to 256 (cols 232..255 zero)
__device__ __align__(16) __nv_bfloat16 g_liah[(size_t)MAX_ACT * 256];
__device__ __align__(16) __nv_bfloat16 g_lial[(size_t)MAX_ACT * 256];
__device__ __align__(16) __nv_bfloat16 g_hidh[(size_t)MAX_ACT * 256];
__device__ __align__(16) __nv_bfloat16 g_hidl[(size_t)MAX_ACT * 256];

__device__ __forceinline__ float wsum(float v) {
#pragma unroll
    for (int o = 16; o > 0; o >>= 1) v += __shfl_xor_sync(0xffffffffu, v, o);
    return v;
}
__device__ __forceinline__ float sigm(float x) { return 1.f / (1.f + expf(-x)); }
__device__ __forceinline__ void ffma2(u64& a, u64 x, u64 w) {
    asm("fma.rn.f32x2 %0, %1, %2, %0;" : "+l"(a) : "l"(x), "l"(w));
}
__device__ __forceinline__ float hadd2(u64 a) {
    return __uint_as_float((unsigned)a) + __uint_as_float((unsigned)(a >> 32));
}
__device__ __forceinline__ ulonglong2 ld2(const float* p) {
    return *reinterpret_cast<const ulonglong2*>(p);
}
__device__ __forceinline__ uint32_t s2u(const void* p) {
    uint32_t a;
    asm("{ .reg .u64 t; cvta.to.shared.u64 t, %1; cvt.u32.u64 %0, t; }" : "=r"(a) : "l"(p));
    return a;
}
__device__ __forceinline__ void pf_l2(const void* p) {
    asm volatile("prefetch.global.L2 [%0];" :: "l"(p));
}
__device__ __forceinline__ void cp16(uint32_t d, const void* s) {
    asm volatile("cp.async.cg.shared.global [%0], [%1], 16;" :: "r"(d), "l"(s));
}
#define CP_COMMIT() asm volatile("cp.async.commit_group;" ::: "memory")
#define CP_WAIT1() asm volatile("cp.async.wait_group 1;" ::: "memory")
#define CP_WAIT0() asm volatile("cp.async.wait_group 0;" ::: "memory")
__device__ __forceinline__ void mma16816(float* c, const uint32_t* a, const uint32_t* b) {
    asm volatile("mma.sync.aligned.m16n8k16.row.col.f32.bf16.bf16.f32 "
        "{%0,%1,%2,%3}, {%4,%5,%6,%7}, {%8,%9}, {%0,%1,%2,%3};"
        : "+f"(c[0]), "+f"(c[1]), "+f"(c[2]), "+f"(c[3])
        : "r"(a[0]), "r"(a[1]), "r"(a[2]), "r"(a[3]), "r"(b[0]), "r"(b[1]));
}
__device__ __forceinline__ void ldsm4(uint32_t* r, uint32_t a) {
    asm volatile("ldmatrix.sync.aligned.m8n8.x4.shared.b16 {%0,%1,%2,%3}, [%4];"
        : "=r"(r[0]), "=r"(r[1]), "=r"(r[2]), "=r"(r[3]) : "r"(a));
}
__device__ __forceinline__ void ldsm4t(uint32_t* r, uint32_t a) {
    asm volatile("ldmatrix.sync.aligned.m8n8.x4.trans.shared.b16 {%0,%1,%2,%3}, [%4];"
        : "=r"(r[0]), "=r"(r[1]), "=r"(r[2]), "=r"(r[3]) : "r"(a));
}
__device__ __forceinline__ void split2(float v0, float v1, uint32_t& hi, uint32_t& lo) {
    float h0 = __bfloat162float(__float2bfloat16(v0));
    float h1 = __bfloat162float(__float2bfloat16(v1));
    asm("cvt.rn.bf16x2.f32 %0, %1, %2;" : "=r"(hi) : "f"(v1), "f"(v0));
    float r0 = v0 - h0, r1 = v1 - h1;
    asm("cvt.rn.bf16x2.f32 %0, %1, %2;" : "=r"(lo) : "f"(r1), "f"(r0));
}
__device__ __forceinline__ void wsplit(__nv_bfloat16* ph, __nv_bfloat16* pl, float v) {
    __nv_bfloat16 h = __float2bfloat16(v);
    *ph = h;
    *pl = __float2bfloat16(v - __bfloat162float(h));
}

// ===================== K1: node SLN =====================
__global__ void k_node_norm(const float* __restrict__ nf, const float* __restrict__ gs,
                            const float* __restrict__ bs, const float* __restrict__ gv,
                            int n_nodes) {
    int w = (blockIdx.x * 256 + threadIdx.x) >> 5;
    int l = threadIdx.x & 31;
    if (w >= n_nodes) return;
    const float* r = nf + (size_t)w * DIMX;
    float s0 = r[l], s1 = r[32 + l];
    float mu = wsum(s0 + s1) * (1.f / 64.f);
    float m2 = wsum(s0 * s0 + s1 * s1) * (1.f / 64.f);
    float rsv = rsqrtf(m2 - mu * mu + EPSF);
    float v0 = r[64 + 3 * l], v1 = r[65 + 3 * l], v2 = r[66 + 3 * l];
    float rmi = rsqrtf(wsum(v0 * v0 + v1 * v1 + v2 * v2) * (1.f / 32.f) + EPSF);
    float* o = g_nf + (size_t)w * DIMX;
    o[l] = (s0 - mu) * rsv * gs[l] + bs[l];
    o[32 + l] = (s1 - mu) * rsv * gs[32 + l] + bs[32 + l];
    float gk = gv[l] * rmi;
    o[64 + 3 * l] = v0 * gk; o[65 + 3 * l] = v1 * gk; o[66 + 3 * l] = v2 * gk;
}

// ===================== K2a: gather + edge SLN + tensor product =====================
#define EA_T 256
#define EA_W 8
#define EA_E 4
#define SMEM_A ((96*196 + 96*100 + 32*196 + 32*100 + EA_W*EA_E*576) * 4)
__global__ __launch_bounds__(EA_T, 1) void k_edge_a(
    const float* __restrict__ ef, const float* __restrict__ esh,
    const int* __restrict__ eidx, const int* __restrict__ act,
    const float* __restrict__ onehot,
    const float* __restrict__ egs, const float* __restrict__ ebs, const float* __restrict__ egv,
    const float* __restrict__ Wa, const float* __restrict__ Wb,
    const float* __restrict__ Wc, const float* __restrict__ Wd,
    int n_act, int n_edges) {
    extern __shared__ float sm[];
    float* WaT = sm;
    float* WbT = WaT + 96 * 196;
    float* WcT = WbT + 96 * 100;
    float* WdT = WcT + 32 * 196;
    float* STG = WdT + 32 * 100;
    int tid = threadIdx.x;
    for (int i = tid; i < 192 * 96; i += EA_T) WaT[(i % 96) * 196 + i / 96] = Wa[i];
    for (int i = tid; i < 96 * 96; i += EA_T)  WbT[(i % 96) * 100 + i / 96] = Wb[i];
    for (int i = tid; i < 192 * 32; i += EA_T) WcT[(i % 32) * 196 + i / 32] = Wc[i];
    for (int i = tid; i < 96 * 32; i += EA_T)  WdT[(i % 32) * 100 + i / 32] = Wd[i];
    __syncthreads();
    int wq = tid >> 5, l = tid & 31;
    float* ST = STG + wq * (EA_E * 576);
    int gw = blockIdx.x * EA_W + wq;
    int stride = gridDim.x * EA_W * EA_E;
    for (int eb = gw * EA_E; eb < n_act; eb += stride) {
        int ecs[EA_E], aes[EA_E], iis[EA_E], jjs[EA_E];
#pragma unroll
        for (int e = 0; e < EA_E; e++) { int ec = eb + e; ecs[e] = ec < n_act ? ec : n_act - 1; }
#pragma unroll
        for (int e = 0; e < EA_E; e++) aes[e] = act[ecs[e]];
#pragma unroll
        for (int e = 0; e < EA_E; e++) { iis[e] = eidx[aes[e]]; jjs[e] = eidx[n_edges + aes[e]]; }
        float4 shp[EA_E];
        float is0[EA_E], is1[EA_E], iv0[EA_E], iv1[EA_E], iv2[EA_E];
        float js0[EA_E], js1[EA_E], jv0[EA_E], jv1[EA_E], jv2[EA_E];
        float es0[EA_E], es1[EA_E], ev0[EA_E], ev1[EA_E], ev2[EA_E];
#pragma unroll
        for (int e = 0; e < EA_E; e++) {
            const float* ri = g_nf + (size_t)iis[e] * DIMX;
            is0[e] = ri[l]; is1[e] = ri[32 + l];
            iv0[e] = ri[64 + 3 * l]; iv1[e] = ri[65 + 3 * l]; iv2[e] = ri[66 + 3 * l];
            const float* rj = g_nf + (size_t)jjs[e] * DIMX;
            js0[e] = rj[l]; js1[e] = rj[32 + l];
            jv0[e] = rj[64 + 3 * l]; jv1[e] = rj[65 + 3 * l]; jv2[e] = rj[66 + 3 * l];
            const float* re = ef + (size_t)ecs[e] * DIMX;
            es0[e] = re[l]; es1[e] = re[32 + l];
            ev0[e] = re[64 + 3 * l]; ev1[e] = re[65 + 3 * l]; ev2[e] = re[66 + 3 * l];
            shp[e] = *(const float4*)(esh + (size_t)ecs[e] * 4);
        }
        float sh0r[EA_E], s10[EA_E], s11[EA_E], s12[EA_E];
#pragma unroll
        for (int e = 0; e < EA_E; e++) {
            float* sA = ST + e * 576;
            float* vA = sA + 192;
            float* u = sA + 480;
            sA[l] = is0[e]; sA[32 + l] = is1[e];
            vA[l] = iv0[e]; vA[96 + l] = iv1[e]; vA[192 + l] = iv2[e];
            sA[128 + l] = js0[e]; sA[160 + l] = js1[e];
            vA[64 + l] = jv0[e]; vA[160 + l] = jv1[e]; vA[256 + l] = jv2[e];
            float s0 = es0[e], s1 = es1[e];
            float mu = wsum(s0 + s1) * (1.f / 64.f);
            float m2 = wsum(s0 * s0 + s1 * s1) * (1.f / 64.f);
            float rsv = rsqrtf(m2 - mu * mu + EPSF);
            sA[64 + l] = (s0 - mu) * rsv * egs[l] + ebs[l];
            sA[96 + l] = (s1 - mu) * rsv * egs[32 + l] + ebs[32 + l];
            float rmi = rsqrtf(wsum(ev0[e] * ev0[e] + ev1[e] * ev1[e] + ev2[e] * ev2[e]) * (1.f / 32.f) + EPSF);
            float gk = egv[l] * rmi;
            float e0 = ev0[e] * gk, e1 = ev1[e] * gk, e2 = ev2[e] * gk;
            vA[32 + l] = e0; vA[128 + l] = e1; vA[224 + l] = e2;
            sh0r[e] = shp[e].x; s10[e] = shp[e].y; s11[e] = shp[e].z; s12[e] = shp[e].w;
            u[l]      = (iv0[e] * s10[e] + iv1[e] * s11[e] + iv2[e] * s12[e]) * INV_SQ3;
            u[32 + l] = (e0 * s10[e] + e1 * s11[e] + e2 * s12[e]) * INV_SQ3;
            u[64 + l] = (jv0[e] * s10[e] + jv1[e] * s11[e] + jv2[e] * s12[e]) * INV_SQ3;
        }
        __syncwarp();
        u64 aA[3][EA_E], swc[EA_E];
#pragma unroll
        for (int j = 0; j < 3; j++)
#pragma unroll
            for (int e = 0; e < EA_E; e++) aA[j][e] = 0ull;
#pragma unroll
        for (int e = 0; e < EA_E; e++) swc[e] = 0ull;
        for (int k = 0; k < 192; k += 4) {
            ulonglong2 w0 = ld2(&WaT[l * 196 + k]);
            ulonglong2 w1 = ld2(&WaT[(l + 32) * 196 + k]);
            ulonglong2 w2 = ld2(&WaT[(l + 64) * 196 + k]);
            ulonglong2 wc = ld2(&WcT[l * 196 + k]);
#pragma unroll
            for (int e = 0; e < EA_E; e++) {
                ulonglong2 x = ld2(&ST[e * 576 + k]);
                ffma2(aA[0][e], x.x, w0.x); ffma2(aA[0][e], x.y, w0.y);
                ffma2(aA[1][e], x.x, w1.x); ffma2(aA[1][e], x.y, w1.y);
                ffma2(aA[2][e], x.x, w2.x); ffma2(aA[2][e], x.y, w2.y);
                ffma2(swc[e],   x.x, wc.x); ffma2(swc[e],   x.y, wc.y);
            }
        }
        float fA[3][EA_E];
#pragma unroll
        for (int j = 0; j < 3; j++)
#pragma unroll
            for (int e = 0; e < EA_E; e++) fA[j][e] = hadd2(aA[j][e]);
        u64 aB[3][EA_E];
#pragma unroll
        for (int j = 0; j < 3; j++)
#pragma unroll
            for (int e = 0; e < EA_E; e++) aB[j][e] = 0ull;
        for (int k = 0; k < 96; k += 4) {
            ulonglong2 w0 = ld2(&WbT[l * 100 + k]);
            ulonglong2 w1 = ld2(&WbT[(l + 32) * 100 + k]);
            ulonglong2 w2 = ld2(&WbT[(l + 64) * 100 + k]);
#pragma unroll
            for (int e = 0; e < EA_E; e++) {
                ulonglong2 x = ld2(&ST[e * 576 + 480 + k]);
                ffma2(aB[0][e], x.x, w0.x); ffma2(aB[0][e], x.y, w0.y);
                ffma2(aB[1][e], x.x, w1.x); ffma2(aB[1][e], x.y, w1.y);
                ffma2(aB[2][e], x.x, w2.x); ffma2(aB[2][e], x.y, w2.y);
            }
        }
        float os[3][EA_E];
#pragma unroll
        for (int j = 0; j < 3; j++)
#pragma unroll
            for (int e = 0; e < EA_E; e++) os[j][e] = fmaf(sh0r[e], fA[j][e], hadd2(aB[j][e]));
        u64 wd[3][EA_E];
#pragma unroll
        for (int e = 0; e < EA_E; e++) { wd[0][e] = 0ull; wd[1][e] = 0ull; wd[2][e] = 0ull; }
        for (int k = 0; k < 96; k += 4) {
            ulonglong2 w = ld2(&WdT[l * 100 + k]);
#pragma unroll
            for (int e = 0; e < EA_E; e++) {
#pragma unroll
                for (int c = 0; c < 3; c++) {
                    ulonglong2 x = ld2(&ST[e * 576 + 192 + 96 * c + k]);
                    ffma2(wd[c][e], x.x, w.x); ffma2(wd[c][e], x.y, w.y);
                }
            }
        }
#pragma unroll
        for (int e = 0; e < EA_E; e++) {
            int eg = eb + e;
            if (eg < n_act) {
                float gate = sigm(os[2][e]);
                g_ms[(size_t)eg * 64 + l] = os[0][e] * sigm(os[0][e]);
                g_ms[(size_t)eg * 64 + 32 + l] = os[1][e] * sigm(os[1][e]);
                float s1c[3] = { s10[e], s11[e], s12[e] };
                float sw = hadd2(swc[e]);
#pragma unroll
                for (int c = 0; c < 3; c++) {
                    float ov = fmaf(sw, s1c[c], hadd2(wd[c][e]) * sh0r[e]);
                    g_mv[(size_t)eg * 96 + 3 * l + c] = ov * gate;
                }
                size_t lb8 = (size_t)eg * 256;
                wsplit(&g_liah[lb8 + 132 + l], &g_lial[lb8 + 132 + l], os[0][e]);
                wsplit(&g_liah[lb8 + 164 + l], &g_lial[lb8 + 164 + l], os[1][e]);
                wsplit(&g_liah[lb8 + 196 + l], &g_lial[lb8 + 196 + l], os[2][e]);
                if (l < 4) {
                    wsplit(&g_liah[lb8 + l], &g_lial[lb8 + l], onehot[iis[e] * 4 + l]);
                    wsplit(&g_liah[lb8 + 228 + l], &g_lial[lb8 + 228 + l], onehot[jjs[e] * 4 + l]);
                }
                if (l < 24) {
                    g_liah[lb8 + 232 + l] = __float2bfloat16(0.f);
                    g_lial[lb8 + 232 + l] = __float2bfloat16(0.f);
                }
            }
        }
        __syncwarp();
    }
}

// ===================== K2b: W_edge / Wp / Wres + latent LN + edge_out =====================
#define EB_T 512
#define EB_W 16
#define EB_E 4
#define SMEM_B ((96*132 + 64*68 + 32*36 + 64*68 + 32*36 + EB_W*EB_E*448) * 4)
__global__ __launch_bounds__(EB_T, 1) void k_edge_b(
    const float* __restrict__ latents, const float* __restrict__ ef,
    const int* __restrict__ act,
    const float* __restrict__ lg, const float* __restrict__ lb,
    const float* __restrict__ We, const float* __restrict__ Wps, const float* __restrict__ Wpv,
    const float* __restrict__ Wrs, const float* __restrict__ Wrv,
    float* __restrict__ out_edge, int n_act) {
    extern __shared__ float sm[];
    float* WeT = sm;
    float* WpsT = WeT + 96 * 132;
    float* WpvT = WpsT + 64 * 68;
    float* WrsT = WpvT + 32 * 36;
    float* WrvT = WrsT + 64 * 68;
    float* STG = WrvT + 32 * 36;
    int tid = threadIdx.x;
    for (int i = tid; i < 128 * 96; i += EB_T) WeT[(i % 96) * 132 + i / 96] = We[i];
    for (int i = tid; i < 64 * 64; i += EB_T)  WpsT[(i % 64) * 68 + i / 64] = Wps[i];
    for (int i = tid; i < 32 * 32; i += EB_T)  WpvT[(i % 32) * 36 + i / 32] = Wpv[i];
    for (int i = tid; i < 64 * 64; i += EB_T)  WrsT[(i % 64) * 68 + i / 64] = Wrs[i];
    for (int i = tid; i < 32 * 32; i += EB_T)  WrvT[(i % 32) * 36 + i / 32] = Wrv[i];
    __syncthreads();
    int wq = tid >> 5, l = tid & 31;
    float* ST = STG + wq * (EB_E * 448);
    int gw = blockIdx.x * EB_W + wq;
    int stride = gridDim.x * EB_W * EB_E;
    for (int eb = gw * EB_E; eb < n_act; eb += stride) {
#pragma unroll
        for (int half = 0; half < 2; half++) {
            int ecs[2], aes[2];
            float lx[2][4], msr[2][2], mvr[2][3], res[2][2], rev[2][3];
#pragma unroll
            for (int q = 0; q < 2; q++) {
                int ec = eb + half * 2 + q;
                ecs[q] = ec < n_act ? ec : n_act - 1;
            }
#pragma unroll
            for (int q = 0; q < 2; q++) aes[q] = act[ecs[q]];
#pragma unroll
            for (int q = 0; q < 2; q++) {
                const float* la = latents + (size_t)aes[q] * 128;
                lx[q][0] = la[l]; lx[q][1] = la[32 + l]; lx[q][2] = la[64 + l]; lx[q][3] = la[96 + l];
                const float* ms = g_ms + (size_t)ecs[q] * 64;
                msr[q][0] = ms[l]; msr[q][1] = ms[32 + l];
                const float* mv = g_mv + (size_t)ecs[q] * 96;
                mvr[q][0] = mv[3 * l]; mvr[q][1] = mv[3 * l + 1]; mvr[q][2] = mv[3 * l + 2];
                const float* re = ef + (size_t)ecs[q] * DIMX;
                res[q][0] = re[l]; res[q][1] = re[32 + l];
                rev[q][0] = re[64 + 3 * l]; rev[q][1] = re[65 + 3 * l]; rev[q][2] = re[66 + 3 * l];
            }
#pragma unroll
            for (int q = 0; q < 2; q++) {
                int e = half * 2 + q;
                float* S = ST + e * 448;
                float x0 = lx[q][0], x1 = lx[q][1], x2 = lx[q][2], x3 = lx[q][3];
                S[l] = x0; S[32 + l] = x1; S[64 + l] = x2; S[96 + l] = x3;
                float mu = wsum(x0 + x1 + x2 + x3) * (1.f / 128.f);
                float m2 = wsum(x0 * x0 + x1 * x1 + x2 * x2 + x3 * x3) * (1.f / 128.f);
                float rsv = rsqrtf(m2 - mu * mu + EPSF);
                int eg = eb + e;
                if (eg < n_act) {
                    size_t lb8 = (size_t)eg * 256 + 4;
                    wsplit(&g_liah[lb8 + l], &g_lial[lb8 + l], (x0 - mu) * rsv * lg[l] + lb[l]);
                    wsplit(&g_liah[lb8 + 32 + l], &g_lial[lb8 + 32 + l], (x1 - mu) * rsv * lg[32 + l] + lb[32 + l]);
                    wsplit(&g_liah[lb8 + 64 + l], &g_lial[lb8 + 64 + l], (x2 - mu) * rsv * lg[64 + l] + lb[64 + l]);
                    wsplit(&g_liah[lb8 + 96 + l], &g_lial[lb8 + 96 + l], (x3 - mu) * rsv * lg[96 + l] + lb[96 + l]);
                }
                S[128 + l] = msr[q][0]; S[160 + l] = msr[q][1];
                S[192 + l] = mvr[q][0]; S[224 + l] = mvr[q][1]; S[256 + l] = mvr[q][2];
                S[288 + l] = res[q][0]; S[320 + l] = res[q][1];
                S[352 + l] = rev[q][0]; S[384 + l] = rev[q][1]; S[416 + l] = rev[q][2];
            }
        }
        __syncwarp();
        u64 ww[3][EB_E];
#pragma unroll
        for (int j = 0; j < 3; j++)
#pragma unroll
            for (int e = 0; e < EB_E; e++) ww[j][e] = 0ull;
        for (int k = 0; k < 128; k += 4) {
            ulonglong2 w0 = ld2(&WeT[l * 132 + k]);
            ulonglong2 w1 = ld2(&WeT[(l + 32) * 132 + k]);
            ulonglong2 w2 = ld2(&WeT[(l + 64) * 132 + k]);
#pragma unroll
            for (int e = 0; e < EB_E; e++) {
                ulonglong2 x = ld2(&ST[e * 448 + k]);
                ffma2(ww[0][e], x.x, w0.x); ffma2(ww[0][e], x.y, w0.y);
                ffma2(ww[1][e], x.x, w1.x); ffma2(ww[1][e], x.y, w1.y);
                ffma2(ww[2][e], x.x, w2.x); ffma2(ww[2][e], x.y, w2.y);
            }
        }
        float fw[3][EB_E];
#pragma unroll
        for (int j = 0; j < 3; j++)
#pragma unroll
            for (int e = 0; e < EB_E; e++) fw[j][e] = hadd2(ww[j][e]);
        u64 ps[2][EB_E], rs[2][EB_E];
#pragma unroll
        for (int e = 0; e < EB_E; e++) { ps[0][e] = ps[1][e] = rs[0][e] = rs[1][e] = 0ull; }
        for (int k = 0; k < 64; k += 4) {
            ulonglong2 p0 = ld2(&WpsT[l * 68 + k]);
            ulonglong2 p1 = ld2(&WpsT[(l + 32) * 68 + k]);
            ulonglong2 r0 = ld2(&WrsT[l * 68 + k]);
            ulonglong2 r1 = ld2(&WrsT[(l + 32) * 68 + k]);
#pragma unroll
            for (int e = 0; e < EB_E; e++) {
                ulonglong2 xm = ld2(&ST[e * 448 + 128 + k]);
                ulonglong2 xr = ld2(&ST[e * 448 + 288 + k]);
                ffma2(ps[0][e], xm.x, p0.x); ffma2(ps[0][e], xm.y, p0.y);
                ffma2(ps[1][e], xm.x, p1.x); ffma2(ps[1][e], xm.y, p1.y);
                ffma2(rs[0][e], xr.x, r0.x); ffma2(rs[0][e], xr.y, r0.y);
                ffma2(rs[1][e], xr.x, r1.x); ffma2(rs[1][e], xr.y, r1.y);
            }
        }
        float fps[2][EB_E], frs[2][EB_E];
#pragma unroll
        for (int j = 0; j < 2; j++)
#pragma unroll
            for (int e = 0; e < EB_E; e++) { fps[j][e] = hadd2(ps[j][e]); frs[j][e] = hadd2(rs[j][e]); }
        u64 pv[3][EB_E], rv[3][EB_E];
#pragma unroll
        for (int c = 0; c < 3; c++)
#pragma unroll
            for (int e = 0; e < EB_E; e++) { pv[c][e] = 0ull; rv[c][e] = 0ull; }
        for (int k = 0; k < 32; k += 4) {
            ulonglong2 pw = ld2(&WpvT[l * 36 + k]);
            ulonglong2 rw = ld2(&WrvT[l * 36 + k]);
#pragma unroll
            for (int e = 0; e < EB_E; e++) {
#pragma unroll
                for (int c = 0; c < 3; c++) {
                    ulonglong2 xm = ld2(&ST[e * 448 + 192 + 32 * c + k]);
                    ulonglong2 xr = ld2(&ST[e * 448 + 352 + 32 * c + k]);
                    ffma2(pv[c][e], xm.x, pw.x); ffma2(pv[c][e], xm.y, pw.y);
                    ffma2(rv[c][e], xr.x, rw.x); ffma2(rv[c][e], xr.y, rw.y);
                }
            }
        }
#pragma unroll
        for (int e = 0; e < EB_E; e++) {
            int eg = eb + e;
            if (eg < n_act) {
                float* oe = out_edge + (size_t)eg * DIMX;
                oe[l] = fmaf(fps[0][e], fw[0][e], frs[0][e]);
                oe[32 + l] = fmaf(fps[1][e], fw[1][e], frs[1][e]);
#pragma unroll
                for (int c = 0; c < 3; c++)
                    oe[64 + 3 * l + c] = fmaf(hadd2(pv[c][e]), fw[2][e], hadd2(rv[c][e]));
            }
        }
        __syncwarp();
    }
}

// ===================== GEMM helpers: cp.async A-chunk stage =====================
// stage 128 rows x 64 halves (128B) of hi+lo into buf (pitch 72 halves)
__device__ __forceinline__ void stage_chunk(
    const __nv_bfloat16* __restrict__ srch, const __nv_bfloat16* __restrict__ srcl,
    uint32_t dsth, uint32_t dstl, int tile, int chunk, int n_act, int tid) {
#pragma unroll
    for (int i = 0; i < 4; i++) {
        int idx = tid + i * 512;
        int part = idx >> 10;          // 0 = hi, 1 = lo
        int rem = idx & 1023;
        int row = rem >> 3;
        int seg = rem & 7;
        int eg = tile * 128 + row;
        int ec = eg < n_act ? eg : n_act - 1;
        const __nv_bfloat16* s = (part ? srcl : srch) + (size_t)ec * 256 + chunk * 64 + seg * 8;
        uint32_t d = (part ? dstl : dsth) + (uint32_t)(row * 72 + seg * 8) * 2;
        cp16(d, s);
    }
}

// ===================== K3: GEMM1 hid = silu(lat_in @ W1), cp.async pipelined =====================
// smem halves: Wh[256*136] Wl[256*136] | A bufs: [2 bufs][h,l][128*72]
#define M1_SMEM ((2 * 256 * 136 + 4 * 128 * 72) * 2)
__global__ __launch_bounds__(512, 1) void k_mma1(const float* __restrict__ W1, int n_act) {
    extern __shared__ __nv_bfloat16 sb[];
    __nv_bfloat16* Wh = sb;
    __nv_bfloat16* Wl = Wh + 256 * 136;
    __nv_bfloat16* AB = Wl + 256 * 136;  // 4 x 128*72
    int tid = threadIdx.x, wid = tid >> 5, lane = tid & 31;
    int base = blockIdx.y * 128;
    for (int i = tid; i < 256 * 128; i += 512) {
        int k = i >> 7, n = i & 127;
        float w = (k < 232) ? W1[k * 256 + base + n] : 0.f;
        __nv_bfloat16 h = __float2bfloat16(w);
        Wh[k * 136 + n] = h;
        Wl[k * 136 + n] = __float2bfloat16(w - __bfloat162float(h));
    }
    uint32_t aWh = s2u(Wh);
    uint32_t dWl = (uint32_t)(256 * 136 * 2);
    uint32_t aA0h = s2u(AB);
    uint32_t bufsz = (uint32_t)(128 * 72 * 2);
    // buf b: hi at aA0h + b*2*bufsz, lo at +bufsz
    int warp_m = wid & 7, warp_n = wid >> 3;
    int ntile = (n_act + 127) >> 7;
    int arow = warp_m * 16 + (lane & 15);
    int acolb = (lane >> 4) << 3;
    uint32_t aBaseW = (uint32_t)((arow * 72 + acolb) * 2);
    uint32_t bBaseW = (uint32_t)(((lane & 15) * 136 + warp_n * 64 + acolb) * 2);
    __syncthreads();
    for (int tile = blockIdx.x; tile < ntile; tile += gridDim.x) {
        int nt = tile + gridDim.x;
        if (nt < ntile) {
            const char* p = (const char*)(g_liah + (size_t)nt * 128 * 256);
            const char* q = (const char*)(g_lial + (size_t)nt * 128 * 256);
            pf_l2(p + (size_t)tid * 128); pf_l2(q + (size_t)tid * 128);
        }
        float C[8][4];
#pragma unroll
        for (int b = 0; b < 8; b++)
#pragma unroll
            for (int c = 0; c < 4; c++) C[b][c] = 0.f;
        stage_chunk(g_liah, g_lial, aA0h, aA0h + bufsz, tile, 0, n_act, tid); CP_COMMIT();
        stage_chunk(g_liah, g_lial, aA0h + 2 * bufsz, aA0h + 3 * bufsz, tile, 1, n_act, tid); CP_COMMIT();
#pragma unroll 1
        for (int ch = 0; ch < 4; ch++) {
            if (ch < 3) CP_WAIT1(); else CP_WAIT0();
            __syncthreads();
            uint32_t bh = aA0h + (uint32_t)(ch & 1) * 2 * bufsz;
            uint32_t aAddr = bh + aBaseW;
            uint32_t bAddr = aWh + bBaseW + (uint32_t)(ch * 64 * 136 * 2);
            uint32_t fAh[2][4], fAl[2][4];
            ldsm4(fAh[0], aAddr);
            ldsm4(fAl[0], aAddr + bufsz);
            aAddr += 32;
#pragma unroll
            for (int ks = 0; ks < 4; ks++) {
                int cur = ks & 1, nxt = cur ^ 1;
                if (ks < 3) {
                    ldsm4(fAh[nxt], aAddr);
                    ldsm4(fAl[nxt], aAddr + bufsz);
                    aAddr += 32;
                }
#pragma unroll
                for (int ng = 0; ng < 4; ng++) {
                    uint32_t bo = bAddr + (uint32_t)(ng * 32);
                    uint32_t fBh[4], fBl[4];
                    ldsm4t(fBh, bo);
                    ldsm4t(fBl, bo + dWl);
                    mma16816(C[ng * 2],     fAh[cur], fBh);
                    mma16816(C[ng * 2],     fAl[cur], fBh);
                    mma16816(C[ng * 2],     fAh[cur], fBl);
                    mma16816(C[ng * 2 + 1], fAh[cur], fBh + 2);
                    mma16816(C[ng * 2 + 1], fAl[cur], fBh + 2);
                    mma16816(C[ng * 2 + 1], fAh[cur], fBl + 2);
                }
                bAddr += (uint32_t)(16 * 136 * 2);
            }
            __syncthreads();
            if (ch + 2 < 4) {
                uint32_t nb = aA0h + (uint32_t)(ch & 1) * 2 * bufsz;
                stage_chunk(g_liah, g_lial, nb, nb + bufsz, tile, ch + 2, n_act, tid);
                CP_COMMIT();
            }
        }
#pragma unroll
        for (int p = 0; p < 2; p++) {
            int row = tile * 128 + warp_m * 16 + (lane >> 2) + p * 8;
            if (row < n_act) {
#pragma unroll
                for (int n8 = 0; n8 < 8; n8++) {
                    float v0 = C[n8][p * 2], v1 = C[n8][p * 2 + 1];
                    v0 = v0 * sigm(v0); v1 = v1 * sigm(v1);
                    uint32_t hw, lw;
                    split2(v0, v1, hw, lw);
                    int col = base + warp_n * 64 + n8 * 8 + (lane & 3) * 2;
                    *(uint32_t*)&g_hidh[(size_t)row * 256 + col] = hw;
                    *(uint32_t*)&g_hidl[(size_t)row * 256 + col] = lw;
                }
            }
        }
    }
}

// ===================== K4: GEMM2 out = (hid @ W2) * cutoff, cp.async pipelined =====================
#define M2_SMEM ((2 * 256 * 136 + 4 * 128 * 72) * 2)
__global__ __launch_bounds__(512, 1) void k_mma2(
    const float* __restrict__ W2, const int* __restrict__ act,
    const float* __restrict__ cutoff, float* __restrict__ out_lat, int n_act) {
    extern __shared__ __nv_bfloat16 sb[];
    __nv_bfloat16* Wh = sb;
    __nv_bfloat16* Wl = Wh + 256 * 136;
    __nv_bfloat16* AB = Wl + 256 * 136;
    int tid = threadIdx.x, wid = tid >> 5, lane = tid & 31;
    for (int i = tid; i < 256 * 128; i += 512) {
        int k = i >> 7, n = i & 127;
        float w = W2[k * 128 + n];
        __nv_bfloat16 h = __float2bfloat16(w);
        Wh[k * 136 + n] = h;
        Wl[k * 136 + n] = __float2bfloat16(w - __bfloat162float(h));
    }
    uint32_t aWh = s2u(Wh);
    uint32_t dWl = (uint32_t)(256 * 136 * 2);
    uint32_t aA0h = s2u(AB);
    uint32_t bufsz = (uint32_t)(128 * 72 * 2);
    int warp_m = wid & 7, warp_n = wid >> 3;
    int ntile = (n_act + 127) >> 7;
    int arow = warp_m * 16 + (lane & 15);
    int acolb = (lane >> 4) << 3;
    uint32_t aBaseW = (uint32_t)((arow * 72 + acolb) * 2);
    uint32_t bBaseW = (uint32_t)(((lane & 15) * 136 + warp_n * 64 + acolb) * 2);
    __syncthreads();
    for (int tile = blockIdx.x; tile < ntile; tile += gridDim.x) {
        int nt = tile + gridDim.x;
        if (nt < ntile) {
            const char* ph = (const char*)(g_hidh + (size_t)nt * 128 * 256);
            const char* pl = (const char*)(g_hidl + (size_t)nt * 128 * 256);
            pf_l2(ph + (size_t)tid * 128); pf_l2(pl + (size_t)tid * 128);
        }
        float C[8][4];
#pragma unroll
        for (int b = 0; b < 8; b++)
#pragma unroll
            for (int c = 0; c < 4; c++) C[b][c] = 0.f;
        stage_chunk(g_hidh, g_hidl, aA0h, aA0h + bufsz, tile, 0, n_act, tid); CP_COMMIT();
        stage_chunk(g_hidh, g_hidl, aA0h + 2 * bufsz, aA0h + 3 * bufsz, tile, 1, n_act, tid); CP_COMMIT();
#pragma unroll 1
        for (int ch = 0; ch < 4; ch++) {
            if (ch < 3) CP_WAIT1(); else CP_WAIT0();
            __syncthreads();
            uint32_t bh = aA0h + (uint32_t)(ch & 1) * 2 * bufsz;
            uint32_t aAddr = bh + aBaseW;
            uint32_t bAddr = aWh + bBaseW + (uint32_t)(ch * 64 * 136 * 2);
            uint32_t fAh[2][4], fAl[2][4];
            ldsm4(fAh[0], aAddr);
            ldsm4(fAl[0], aAddr + bufsz);
            aAddr += 32;
#pragma unroll
            for (int ks = 0; ks < 4; ks++) {
                int cur = ks & 1, nxt = cur ^ 1;
                if (ks < 3) {
                    ldsm4(fAh[nxt], aAddr);
                    ldsm4(fAl[nxt], aAddr + bufsz);
                    aAddr += 32;
                }
#pragma unroll
                for (int ng = 0; ng < 4; ng++) {
                    uint32_t bo = bAddr + (uint32_t)(ng * 32);
                    uint32_t fBh[4], fBl[4];
                    ldsm4t(fBh, bo);
                    ldsm4t(fBl, bo + dWl);
                    mma16816(C[ng * 2],     fAh[cur], fBh);
                    mma16816(C[ng * 2],     fAl[cur], fBh);
                    mma16816(C[ng * 2],     fAh[cur], fBl);
                    mma16816(C[ng * 2 + 1], fAh[cur], fBh + 2);
                    mma16816(C[ng * 2 + 1], fAl[cur], fBh + 2);
                    mma16816(C[ng * 2 + 1], fAh[cur], fBl + 2);
                }
                bAddr += (uint32_t)(16 * 136 * 2);
            }
            __syncthreads();
            if (ch + 2 < 4) {
                uint32_t nb = aA0h + (uint32_t)(ch & 1) * 2 * bufsz;
                stage_chunk(g_hidh, g_hidl, nb, nb + bufsz, tile, ch + 2, n_act, tid);
                CP_COMMIT();
            }
        }
#pragma unroll
        for (int p = 0; p < 2; p++) {
            int eg = tile * 128 + warp_m * 16 + (lane >> 2) + p * 8;
            if (eg < n_act) {
                int ae = act[eg];
                float cc = cutoff[ae];
                float* o = out_lat + (size_t)ae * 128;
#pragma unroll
                for (int n8 = 0; n8 < 8; n8++) {
                    int col = warp_n * 64 + n8 * 8 + (lane & 3) * 2;
                    float2 v;
                    v.x = C[n8][p * 2] * cc;
                    v.y = C[n8][p * 2 + 1] * cc;
                    *(float2*)(o + col) = v;
                }
            }
        }
    }
}

// ===================== launcher =====================
extern "C" void kernel_launch(void* const* d_in, const int* in_sizes, int n_in,
                              void* d_out, int out_size) {
    const float* latents   = (const float*)d_in[0];
    const float* node_feat = (const float*)d_in[1];
    const float* onehot    = (const float*)d_in[2];
    const float* edge_feat = (const float*)d_in[3];
    const float* edge_sh   = (const float*)d_in[4];
    const int*   edge_idx  = (const int*)d_in[5];
    const float* cutoff    = (const float*)d_in[6];
    const int*   act       = (const int*)d_in[7];
    const float* n_gs = (const float*)d_in[8];
    const float* n_bs = (const float*)d_in[9];
    const float* n_gv = (const float*)d_in[10];
    const float* e_gs = (const float*)d_in[11];
    const float* e_bs = (const float*)d_in[12];
    const float* e_gv = (const float*)d_in[13];
    const float* lg   = (const float*)d_in[14];
    const float* lb   = (const float*)d_in[15];
    const float* Wa   = (const float*)d_in[16];
    const float* Wb   = (const float*)d_in[17];
    const float* Wc   = (const float*)d_in[18];
    const float* Wd   = (const float*)d_in[19];
    const float* Wps  = (const float*)d_in[20];
    const float* Wpv  = (const float*)d_in[21];
    const float* We   = (const float*)d_in[22];
    const float* W1   = (const float*)d_in[23];
    const float* W2   = (const float*)d_in[24];
    const float* Wrs  = (const float*)d_in[25];
    const float* Wrv  = (const float*)d_in[26];

    int n_nodes = in_sizes[1] / DIMX;
    int n_act   = in_sizes[7];
    int n_edges = in_sizes[6];

    float* out_edge = (float*)d_out;
    float* out_lat  = out_edge + (size_t)n_act * DIMX;

    cudaFuncSetAttribute(k_edge_a, cudaFuncAttributeMaxDynamicSharedMemorySize, SMEM_A);
    cudaFuncSetAttribute(k_edge_b, cudaFuncAttributeMaxDynamicSharedMemorySize, SMEM_B);
    cudaFuncSetAttribute(k_mma1,   cudaFuncAttributeMaxDynamicSharedMemorySize, M1_SMEM);
    cudaFuncSetAttribute(k_mma2,   cudaFuncAttributeMaxDynamicSharedMemorySize, M2_SMEM);

    cudaMemcpyAsync(out_lat, latents, (size_t)n_edges * 128 * sizeof(float),
                    cudaMemcpyDeviceToDevice, 0);

    int nb1 = (n_nodes * 32 + 255) / 256;
    k_node_norm<<<nb1, 256>>>(node_feat, n_gs, n_bs, n_gv, n_nodes);

    k_edge_a<<<148, EA_T, SMEM_A>>>(edge_feat, edge_sh, edge_idx, act, onehot,
                                    e_gs, e_bs, e_gv, Wa, Wb, Wc, Wd, n_act, n_edges);

    k_edge_b<<<148, EB_T, SMEM_B>>>(latents, edge_feat, act, lg, lb,
                                    We, Wps, Wpv, Wrs, Wrv, out_edge, n_act);

    k_mma1<<<dim3(148, 2), 512, M1_SMEM>>>(W1, n_act);

    k_mma2<<<148, 512, M2_SMEM>>>(W2, act, cutoff, out_lat, n_act);
}

// round 16
// speedup vs baseline: 1.1962x; 1.0050x over previous
#include <cuda_runtime.h>
#include <cuda_bf16.h>
#include <math.h>
#include <stdint.h>

#define DIMX 160
#define EPSF 1e-5f
#define INV_SQ3 0.57735026918962576451f
#define MAX_NODES 50000
#define MAX_ACT 200000

typedef unsigned long long u64;

__device__ float g_nf[MAX_NODES * DIMX];
__device__ float g_ms[MAX_ACT * 64];
__device__ float g_mv[MAX_ACT * 96];
__device__ __align__(16) __nv_bfloat16 g_liah[(size_t)MAX_ACT * 256];
__device__ __align__(16) __nv_bfloat16 g_lial[(size_t)MAX_ACT * 256];
__device__ __align__(16) __nv_bfloat16 g_hidh[(size_t)MAX_ACT * 256];
__device__ __align__(16) __nv_bfloat16 g_hidl[(size_t)MAX_ACT * 256];

__device__ __forceinline__ float wsum(float v) {
#pragma unroll
    for (int o = 16; o > 0; o >>= 1) v += __shfl_xor_sync(0xffffffffu, v, o);
    return v;
}
__device__ __forceinline__ float sigm(float x) { return 1.f / (1.f + expf(-x)); }
__device__ __forceinline__ void ffma2(u64& a, u64 x, u64 w) {
    asm("fma.rn.f32x2 %0, %1, %2, %0;" : "+l"(a) : "l"(x), "l"(w));
}
__device__ __forceinline__ float hadd2(u64 a) {
    return __uint_as_float((unsigned)a) + __uint_as_float((unsigned)(a >> 32));
}
__device__ __forceinline__ ulonglong2 ld2(const float* p) {
    return *reinterpret_cast<const ulonglong2*>(p);
}
__device__ __forceinline__ uint32_t s2u(const void* p) {
    uint32_t a;
    asm("{ .reg .u64 t; cvta.to.shared.u64 t, %1; cvt.u32.u64 %0, t; }" : "=r"(a) : "l"(p));
    return a;
}
__device__ __forceinline__ void pf_l2(const void* p) {
    asm volatile("prefetch.global.L2 [%0];" :: "l"(p));
}
__device__ __forceinline__ void cp16(uint32_t d, const void* s) {
    asm volatile("cp.async.cg.shared.global [%0], [%1], 16;" :: "r"(d), "l"(s));
}
#define CP_COMMIT() asm volatile("cp.async.commit_group;" ::: "memory")
#define CP_WAIT1() asm volatile("cp.async.wait_group 1;" ::: "memory")
#define CP_WAIT0() asm volatile("cp.async.wait_group 0;" ::: "memory")
__device__ __forceinline__ void mma16816(float* c, const uint32_t* a, const uint32_t* b) {
    asm volatile("mma.sync.aligned.m16n8k16.row.col.f32.bf16.bf16.f32 "
        "{%0,%1,%2,%3}, {%4,%5,%6,%7}, {%8,%9}, {%0,%1,%2,%3};"
        : "+f"(c[0]), "+f"(c[1]), "+f"(c[2]), "+f"(c[3])
        : "r"(a[0]), "r"(a[1]), "r"(a[2]), "r"(a[3]), "r"(b[0]), "r"(b[1]));
}
__device__ __forceinline__ void ldsm4(uint32_t* r, uint32_t a) {
    asm volatile("ldmatrix.sync.aligned.m8n8.x4.shared.b16 {%0,%1,%2,%3}, [%4];"
        : "=r"(r[0]), "=r"(r[1]), "=r"(r[2]), "=r"(r[3]) : "r"(a));
}
__device__ __forceinline__ void ldsm4t(uint32_t* r, uint32_t a) {
    asm volatile("ldmatrix.sync.aligned.m8n8.x4.trans.shared.b16 {%0,%1,%2,%3}, [%4];"
        : "=r"(r[0]), "=r"(r[1]), "=r"(r[2]), "=r"(r[3]) : "r"(a));
}
__device__ __forceinline__ void split2(float v0, float v1, uint32_t& hi, uint32_t& lo) {
    float h0 = __bfloat162float(__float2bfloat16(v0));
    float h1 = __bfloat162float(__float2bfloat16(v1));
    asm("cvt.rn.bf16x2.f32 %0, %1, %2;" : "=r"(hi) : "f"(v1), "f"(v0));
    float r0 = v0 - h0, r1 = v1 - h1;
    asm("cvt.rn.bf16x2.f32 %0, %1, %2;" : "=r"(lo) : "f"(r1), "f"(r0));
}
__device__ __forceinline__ void wsplit(__nv_bfloat16* ph, __nv_bfloat16* pl, float v) {
    __nv_bfloat16 h = __float2bfloat16(v);
    *ph = h;
    *pl = __float2bfloat16(v - __bfloat162float(h));
}

// ===================== K1: node SLN =====================
__global__ void k_node_norm(const float* __restrict__ nf, const float* __restrict__ gs,
                            const float* __restrict__ bs, const float* __restrict__ gv,
                            int n_nodes) {
    int w = (blockIdx.x * 256 + threadIdx.x) >> 5;
    int l = threadIdx.x & 31;
    if (w >= n_nodes) return;
    const float* r = nf + (size_t)w * DIMX;
    float s0 = r[l], s1 = r[32 + l];
    float mu = wsum(s0 + s1) * (1.f / 64.f);
    float m2 = wsum(s0 * s0 + s1 * s1) * (1.f / 64.f);
    float rsv = rsqrtf(m2 - mu * mu + EPSF);
    float v0 = r[64 + 3 * l], v1 = r[65 + 3 * l], v2 = r[66 + 3 * l];
    float rmi = rsqrtf(wsum(v0 * v0 + v1 * v1 + v2 * v2) * (1.f / 32.f) + EPSF);
    float* o = g_nf + (size_t)w * DIMX;
    o[l] = (s0 - mu) * rsv * gs[l] + bs[l];
    o[32 + l] = (s1 - mu) * rsv * gs[32 + l] + bs[32 + l];
    float gk = gv[l] * rmi;
    o[64 + 3 * l] = v0 * gk; o[65 + 3 * l] = v1 * gk; o[66 + 3 * l] = v2 * gk;
}

// ===================== K2a: gather + edge SLN + tensor product =====================
#define EA_T 256
#define EA_W 8
#define EA_E 4
#define SMEM_A ((96*196 + 96*100 + 32*196 + 32*100 + EA_W*EA_E*576) * 4)
__global__ __launch_bounds__(EA_T, 1) void k_edge_a(
    const float* __restrict__ ef, const float* __restrict__ esh,
    const int* __restrict__ eidx, const int* __restrict__ act,
    const float* __restrict__ onehot,
    const float* __restrict__ egs, const float* __restrict__ ebs, const float* __restrict__ egv,
    const float* __restrict__ Wa, const float* __restrict__ Wb,
    const float* __restrict__ Wc, const float* __restrict__ Wd,
    int n_act, int n_edges) {
    extern __shared__ float sm[];
    float* WaT = sm;
    float* WbT = WaT + 96 * 196;
    float* WcT = WbT + 96 * 100;
    float* WdT = WcT + 32 * 196;
    float* STG = WdT + 32 * 100;
    int tid = threadIdx.x;
    for (int i = tid; i < 192 * 96; i += EA_T) WaT[(i % 96) * 196 + i / 96] = Wa[i];
    for (int i = tid; i < 96 * 96; i += EA_T)  WbT[(i % 96) * 100 + i / 96] = Wb[i];
    for (int i = tid; i < 192 * 32; i += EA_T) WcT[(i % 32) * 196 + i / 32] = Wc[i];
    for (int i = tid; i < 96 * 32; i += EA_T)  WdT[(i % 32) * 100 + i / 32] = Wd[i];
    __syncthreads();
    int wq = tid >> 5, l = tid & 31;
    float* ST = STG + wq * (EA_E * 576);
    int gw = blockIdx.x * EA_W + wq;
    int stride = gridDim.x * EA_W * EA_E;
    for (int eb = gw * EA_E; eb < n_act; eb += stride) {
        int ecs[EA_E], aes[EA_E], iis[EA_E], jjs[EA_E];
#pragma unroll
        for (int e = 0; e < EA_E; e++) { int ec = eb + e; ecs[e] = ec < n_act ? ec : n_act - 1; }
#pragma unroll
        for (int e = 0; e < EA_E; e++) aes[e] = act[ecs[e]];
#pragma unroll
        for (int e = 0; e < EA_E; e++) { iis[e] = eidx[aes[e]]; jjs[e] = eidx[n_edges + aes[e]]; }
        float4 shp[EA_E];
        float is0[EA_E], is1[EA_E], iv0[EA_E], iv1[EA_E], iv2[EA_E];
        float js0[EA_E], js1[EA_E], jv0[EA_E], jv1[EA_E], jv2[EA_E];
        float es0[EA_E], es1[EA_E], ev0[EA_E], ev1[EA_E], ev2[EA_E];
#pragma unroll
        for (int e = 0; e < EA_E; e++) {
            const float* ri = g_nf + (size_t)iis[e] * DIMX;
            is0[e] = ri[l]; is1[e] = ri[32 + l];
            iv0[e] = ri[64 + 3 * l]; iv1[e] = ri[65 + 3 * l]; iv2[e] = ri[66 + 3 * l];
            const float* rj = g_nf + (size_t)jjs[e] * DIMX;
            js0[e] = rj[l]; js1[e] = rj[32 + l];
            jv0[e] = rj[64 + 3 * l]; jv1[e] = rj[65 + 3 * l]; jv2[e] = rj[66 + 3 * l];
            const float* re = ef + (size_t)ecs[e] * DIMX;
            es0[e] = re[l]; es1[e] = re[32 + l];
            ev0[e] = re[64 + 3 * l]; ev1[e] = re[65 + 3 * l]; ev2[e] = re[66 + 3 * l];
            shp[e] = *(const float4*)(esh + (size_t)ecs[e] * 4);
        }
        float sh0r[EA_E], s10[EA_E], s11[EA_E], s12[EA_E];
#pragma unroll
        for (int e = 0; e < EA_E; e++) {
            float* sA = ST + e * 576;
            float* vA = sA + 192;
            float* u = sA + 480;
            sA[l] = is0[e]; sA[32 + l] = is1[e];
            vA[l] = iv0[e]; vA[96 + l] = iv1[e]; vA[192 + l] = iv2[e];
            sA[128 + l] = js0[e]; sA[160 + l] = js1[e];
            vA[64 + l] = jv0[e]; vA[160 + l] = jv1[e]; vA[256 + l] = jv2[e];
            float s0 = es0[e], s1 = es1[e];
            float mu = wsum(s0 + s1) * (1.f / 64.f);
            float m2 = wsum(s0 * s0 + s1 * s1) * (1.f / 64.f);
            float rsv = rsqrtf(m2 - mu * mu + EPSF);
            sA[64 + l] = (s0 - mu) * rsv * egs[l] + ebs[l];
            sA[96 + l] = (s1 - mu) * rsv * egs[32 + l] + ebs[32 + l];
            float rmi = rsqrtf(wsum(ev0[e] * ev0[e] + ev1[e] * ev1[e] + ev2[e] * ev2[e]) * (1.f / 32.f) + EPSF);
            float gk = egv[l] * rmi;
            float e0 = ev0[e] * gk, e1 = ev1[e] * gk, e2 = ev2[e] * gk;
            vA[32 + l] = e0; vA[128 + l] = e1; vA[224 + l] = e2;
            sh0r[e] = shp[e].x; s10[e] = shp[e].y; s11[e] = shp[e].z; s12[e] = shp[e].w;
            u[l]      = (iv0[e] * s10[e] + iv1[e] * s11[e] + iv2[e] * s12[e]) * INV_SQ3;
            u[32 + l] = (e0 * s10[e] + e1 * s11[e] + e2 * s12[e]) * INV_SQ3;
            u[64 + l] = (jv0[e] * s10[e] + jv1[e] * s11[e] + jv2[e] * s12[e]) * INV_SQ3;
        }
        __syncwarp();
        u64 aA[3][EA_E], swc[EA_E];
#pragma unroll
        for (int j = 0; j < 3; j++)
#pragma unroll
            for (int e = 0; e < EA_E; e++) aA[j][e] = 0ull;
#pragma unroll
        for (int e = 0; e < EA_E; e++) swc[e] = 0ull;
        for (int k = 0; k < 192; k += 4) {
            ulonglong2 w0 = ld2(&WaT[l * 196 + k]);
            ulonglong2 w1 = ld2(&WaT[(l + 32) * 196 + k]);
            ulonglong2 w2 = ld2(&WaT[(l + 64) * 196 + k]);
            ulonglong2 wc = ld2(&WcT[l * 196 + k]);
#pragma unroll
            for (int e = 0; e < EA_E; e++) {
                ulonglong2 x = ld2(&ST[e * 576 + k]);
                ffma2(aA[0][e], x.x, w0.x); ffma2(aA[0][e], x.y, w0.y);
                ffma2(aA[1][e], x.x, w1.x); ffma2(aA[1][e], x.y, w1.y);
                ffma2(aA[2][e], x.x, w2.x); ffma2(aA[2][e], x.y, w2.y);
                ffma2(swc[e],   x.x, wc.x); ffma2(swc[e],   x.y, wc.y);
            }
        }
        float fA[3][EA_E];
#pragma unroll
        for (int j = 0; j < 3; j++)
#pragma unroll
            for (int e = 0; e < EA_E; e++) fA[j][e] = hadd2(aA[j][e]);
        u64 aB[3][EA_E];
#pragma unroll
        for (int j = 0; j < 3; j++)
#pragma unroll
            for (int e = 0; e < EA_E; e++) aB[j][e] = 0ull;
        for (int k = 0; k < 96; k += 4) {
            ulonglong2 w0 = ld2(&WbT[l * 100 + k]);
            ulonglong2 w1 = ld2(&WbT[(l + 32) * 100 + k]);
            ulonglong2 w2 = ld2(&WbT[(l + 64) * 100 + k]);
#pragma unroll
            for (int e = 0; e < EA_E; e++) {
                ulonglong2 x = ld2(&ST[e * 576 + 480 + k]);
                ffma2(aB[0][e], x.x, w0.x); ffma2(aB[0][e], x.y, w0.y);
                ffma2(aB[1][e], x.x, w1.x); ffma2(aB[1][e], x.y, w1.y);
                ffma2(aB[2][e], x.x, w2.x); ffma2(aB[2][e], x.y, w2.y);
            }
        }
        float os[3][EA_E];
#pragma unroll
        for (int j = 0; j < 3; j++)
#pragma unroll
            for (int e = 0; e < EA_E; e++) os[j][e] = fmaf(sh0r[e], fA[j][e], hadd2(aB[j][e]));
        u64 wd[3][EA_E];
#pragma unroll
        for (int e = 0; e < EA_E; e++) { wd[0][e] = 0ull; wd[1][e] = 0ull; wd[2][e] = 0ull; }
        for (int k = 0; k < 96; k += 4) {
            ulonglong2 w = ld2(&WdT[l * 100 + k]);
#pragma unroll
            for (int e = 0; e < EA_E; e++) {
#pragma unroll
                for (int c = 0; c < 3; c++) {
                    ulonglong2 x = ld2(&ST[e * 576 + 192 + 96 * c + k]);
                    ffma2(wd[c][e], x.x, w.x); ffma2(wd[c][e], x.y, w.y);
                }
            }
        }
#pragma unroll
        for (int e = 0; e < EA_E; e++) {
            int eg = eb + e;
            if (eg < n_act) {
                float gate = sigm(os[2][e]);
                g_ms[(size_t)eg * 64 + l] = os[0][e] * sigm(os[0][e]);
                g_ms[(size_t)eg * 64 + 32 + l] = os[1][e] * sigm(os[1][e]);
                float s1c[3] = { s10[e], s11[e], s12[e] };
                float sw = hadd2(swc[e]);
#pragma unroll
                for (int c = 0; c < 3; c++) {
                    float ov = fmaf(sw, s1c[c], hadd2(wd[c][e]) * sh0r[e]);
                    g_mv[(size_t)eg * 96 + 3 * l + c] = ov * gate;
                }
                size_t lb8 = (size_t)eg * 256;
                wsplit(&g_liah[lb8 + 132 + l], &g_lial[lb8 + 132 + l], os[0][e]);
                wsplit(&g_liah[lb8 + 164 + l], &g_lial[lb8 + 164 + l], os[1][e]);
                wsplit(&g_liah[lb8 + 196 + l], &g_lial[lb8 + 196 + l], os[2][e]);
                if (l < 4) {
                    wsplit(&g_liah[lb8 + l], &g_lial[lb8 + l], onehot[iis[e] * 4 + l]);
                    wsplit(&g_liah[lb8 + 228 + l], &g_lial[lb8 + 228 + l], onehot[jjs[e] * 4 + l]);
                }
                if (l < 24) {
                    g_liah[lb8 + 232 + l] = __float2bfloat16(0.f);
                    g_lial[lb8 + 232 + l] = __float2bfloat16(0.f);
                }
            }
        }
        __syncwarp();
    }
}

// ===================== K2b: W_edge / Wp / Wres + latent LN + edge_out =====================
#define EB_T 512
#define EB_W 16
#define EB_E 4
#define SMEM_B ((96*132 + 64*68 + 32*36 + 64*68 + 32*36 + EB_W*EB_E*448) * 4)
__global__ __launch_bounds__(EB_T, 1) void k_edge_b(
    const float* __restrict__ latents, const float* __restrict__ ef,
    const int* __restrict__ act,
    const float* __restrict__ lg, const float* __restrict__ lb,
    const float* __restrict__ We, const float* __restrict__ Wps, const float* __restrict__ Wpv,
    const float* __restrict__ Wrs, const float* __restrict__ Wrv,
    float* __restrict__ out_edge, int n_act) {
    extern __shared__ float sm[];
    float* WeT = sm;
    float* WpsT = WeT + 96 * 132;
    float* WpvT = WpsT + 64 * 68;
    float* WrsT = WpvT + 32 * 36;
    float* WrvT = WrsT + 64 * 68;
    float* STG = WrvT + 32 * 36;
    int tid = threadIdx.x;
    for (int i = tid; i < 128 * 96; i += EB_T) WeT[(i % 96) * 132 + i / 96] = We[i];
    for (int i = tid; i < 64 * 64; i += EB_T)  WpsT[(i % 64) * 68 + i / 64] = Wps[i];
    for (int i = tid; i < 32 * 32; i += EB_T)  WpvT[(i % 32) * 36 + i / 32] = Wpv[i];
    for (int i = tid; i < 64 * 64; i += EB_T)  WrsT[(i % 64) * 68 + i / 64] = Wrs[i];
    for (int i = tid; i < 32 * 32; i += EB_T)  WrvT[(i % 32) * 36 + i / 32] = Wrv[i];
    __syncthreads();
    int wq = tid >> 5, l = tid & 31;
    float* ST = STG + wq * (EB_E * 448);
    int gw = blockIdx.x * EB_W + wq;
    int stride = gridDim.x * EB_W * EB_E;
    for (int eb = gw * EB_E; eb < n_act; eb += stride) {
#pragma unroll
        for (int half = 0; half < 2; half++) {
            int ecs[2], aes[2];
            float lx[2][4], msr[2][2], mvr[2][3], res[2][2], rev[2][3];
#pragma unroll
            for (int q = 0; q < 2; q++) {
                int ec = eb + half * 2 + q;
                ecs[q] = ec < n_act ? ec : n_act - 1;
            }
#pragma unroll
            for (int q = 0; q < 2; q++) aes[q] = act[ecs[q]];
#pragma unroll
            for (int q = 0; q < 2; q++) {
                const float* la = latents + (size_t)aes[q] * 128;
                lx[q][0] = la[l]; lx[q][1] = la[32 + l]; lx[q][2] = la[64 + l]; lx[q][3] = la[96 + l];
                const float* ms = g_ms + (size_t)ecs[q] * 64;
                msr[q][0] = ms[l]; msr[q][1] = ms[32 + l];
                const float* mv = g_mv + (size_t)ecs[q] * 96;
                mvr[q][0] = mv[3 * l]; mvr[q][1] = mv[3 * l + 1]; mvr[q][2] = mv[3 * l + 2];
                const float* re = ef + (size_t)ecs[q] * DIMX;
                res[q][0] = re[l]; res[q][1] = re[32 + l];
                rev[q][0] = re[64 + 3 * l]; rev[q][1] = re[65 + 3 * l]; rev[q][2] = re[66 + 3 * l];
            }
#pragma unroll
            for (int q = 0; q < 2; q++) {
                int e = half * 2 + q;
                float* S = ST + e * 448;
                float x0 = lx[q][0], x1 = lx[q][1], x2 = lx[q][2], x3 = lx[q][3];
                S[l] = x0; S[32 + l] = x1; S[64 + l] = x2; S[96 + l] = x3;
                float mu = wsum(x0 + x1 + x2 + x3) * (1.f / 128.f);
                float m2 = wsum(x0 * x0 + x1 * x1 + x2 * x2 + x3 * x3) * (1.f / 128.f);
                float rsv = rsqrtf(m2 - mu * mu + EPSF);
                int eg = eb + e;
                if (eg < n_act) {
                    size_t lb8 = (size_t)eg * 256 + 4;
                    wsplit(&g_liah[lb8 + l], &g_lial[lb8 + l], (x0 - mu) * rsv * lg[l] + lb[l]);
                    wsplit(&g_liah[lb8 + 32 + l], &g_lial[lb8 + 32 + l], (x1 - mu) * rsv * lg[32 + l] + lb[32 + l]);
                    wsplit(&g_liah[lb8 + 64 + l], &g_lial[lb8 + 64 + l], (x2 - mu) * rsv * lg[64 + l] + lb[64 + l]);
                    wsplit(&g_liah[lb8 + 96 + l], &g_lial[lb8 + 96 + l], (x3 - mu) * rsv * lg[96 + l] + lb[96 + l]);
                }
                S[128 + l] = msr[q][0]; S[160 + l] = msr[q][1];
                S[192 + l] = mvr[q][0]; S[224 + l] = mvr[q][1]; S[256 + l] = mvr[q][2];
                S[288 + l] = res[q][0]; S[320 + l] = res[q][1];
                S[352 + l] = rev[q][0]; S[384 + l] = rev[q][1]; S[416 + l] = rev[q][2];
            }
        }
        __syncwarp();
        u64 ww[3][EB_E];
#pragma unroll
        for (int j = 0; j < 3; j++)
#pragma unroll
            for (int e = 0; e < EB_E; e++) ww[j][e] = 0ull;
        for (int k = 0; k < 128; k += 4) {
            ulonglong2 w0 = ld2(&WeT[l * 132 + k]);
            ulonglong2 w1 = ld2(&WeT[(l + 32) * 132 + k]);
            ulonglong2 w2 = ld2(&WeT[(l + 64) * 132 + k]);
#pragma unroll
            for (int e = 0; e < EB_E; e++) {
                ulonglong2 x = ld2(&ST[e * 448 + k]);
                ffma2(ww[0][e], x.x, w0.x); ffma2(ww[0][e], x.y, w0.y);
                ffma2(ww[1][e], x.x, w1.x); ffma2(ww[1][e], x.y, w1.y);
                ffma2(ww[2][e], x.x, w2.x); ffma2(ww[2][e], x.y, w2.y);
            }
        }
        float fw[3][EB_E];
#pragma unroll
        for (int j = 0; j < 3; j++)
#pragma unroll
            for (int e = 0; e < EB_E; e++) fw[j][e] = hadd2(ww[j][e]);
        u64 ps[2][EB_E], rs[2][EB_E];
#pragma unroll
        for (int e = 0; e < EB_E; e++) { ps[0][e] = ps[1][e] = rs[0][e] = rs[1][e] = 0ull; }
        for (int k = 0; k < 64; k += 4) {
            ulonglong2 p0 = ld2(&WpsT[l * 68 + k]);
            ulonglong2 p1 = ld2(&WpsT[(l + 32) * 68 + k]);
            ulonglong2 r0 = ld2(&WrsT[l * 68 + k]);
            ulonglong2 r1 = ld2(&WrsT[(l + 32) * 68 + k]);
#pragma unroll
            for (int e = 0; e < EB_E; e++) {
                ulonglong2 xm = ld2(&ST[e * 448 + 128 + k]);
                ulonglong2 xr = ld2(&ST[e * 448 + 288 + k]);
                ffma2(ps[0][e], xm.x, p0.x); ffma2(ps[0][e], xm.y, p0.y);
                ffma2(ps[1][e], xm.x, p1.x); ffma2(ps[1][e], xm.y, p1.y);
                ffma2(rs[0][e], xr.x, r0.x); ffma2(rs[0][e], xr.y, r0.y);
                ffma2(rs[1][e], xr.x, r1.x); ffma2(rs[1][e], xr.y, r1.y);
            }
        }
        float fps[2][EB_E], frs[2][EB_E];
#pragma unroll
        for (int j = 0; j < 2; j++)
#pragma unroll
            for (int e = 0; e < EB_E; e++) { fps[j][e] = hadd2(ps[j][e]); frs[j][e] = hadd2(rs[j][e]); }
        u64 pv[3][EB_E], rv[3][EB_E];
#pragma unroll
        for (int c = 0; c < 3; c++)
#pragma unroll
            for (int e = 0; e < EB_E; e++) { pv[c][e] = 0ull; rv[c][e] = 0ull; }
        for (int k = 0; k < 32; k += 4) {
            ulonglong2 pw = ld2(&WpvT[l * 36 + k]);
            ulonglong2 rw = ld2(&WrvT[l * 36 + k]);
#pragma unroll
            for (int e = 0; e < EB_E; e++) {
#pragma unroll
                for (int c = 0; c < 3; c++) {
                    ulonglong2 xm = ld2(&ST[e * 448 + 192 + 32 * c + k]);
                    ulonglong2 xr = ld2(&ST[e * 448 + 352 + 32 * c + k]);
                    ffma2(pv[c][e], xm.x, pw.x); ffma2(pv[c][e], xm.y, pw.y);
                    ffma2(rv[c][e], xr.x, rw.x); ffma2(rv[c][e], xr.y, rw.y);
                }
            }
        }
#pragma unroll
        for (int e = 0; e < EB_E; e++) {
            int eg = eb + e;
            if (eg < n_act) {
                float* oe = out_edge + (size_t)eg * DIMX;
                oe[l] = fmaf(fps[0][e], fw[0][e], frs[0][e]);
                oe[32 + l] = fmaf(fps[1][e], fw[1][e], frs[1][e]);
#pragma unroll
                for (int c = 0; c < 3; c++)
                    oe[64 + 3 * l + c] = fmaf(hadd2(pv[c][e]), fw[2][e], hadd2(rv[c][e]));
            }
        }
        __syncwarp();
    }
}

// ===================== cp.async A-chunk stage =====================
__device__ __forceinline__ void stage_chunk(
    const __nv_bfloat16* __restrict__ srch, const __nv_bfloat16* __restrict__ srcl,
    uint32_t dsth, uint32_t dstl, int tile, int chunk, int n_act, int tid) {
#pragma unroll
    for (int i = 0; i < 4; i++) {
        int idx = tid + i * 512;
        int part = idx >> 10;
        int rem = idx & 1023;
        int row = rem >> 3;
        int seg = rem & 7;
        int eg = tile * 128 + row;
        int ec = eg < n_act ? eg : n_act - 1;
        const __nv_bfloat16* s = (part ? srcl : srch) + (size_t)ec * 256 + chunk * 64 + seg * 8;
        uint32_t d = (part ? dstl : dsth) + (uint32_t)(row * 72 + seg * 8) * 2;
        cp16(d, s);
    }
}

// ===================== pipelined 64-K chunk compute (shared by mma1/mma2) =====================
__device__ __forceinline__ void chunk_mma(
    float C[8][4], uint32_t bh, uint32_t bufsz, uint32_t aBaseW,
    uint32_t bChunkBase, uint32_t dWl) {
    uint32_t fAh[2][4], fAl[2][4], fBh[2][4], fBl[2][4];
    uint32_t a0 = bh + aBaseW;
    ldsm4(fAh[0], a0);
    ldsm4(fAl[0], a0 + bufsz);
    ldsm4t(fBh[0], bChunkBase);
    ldsm4t(fBl[0], bChunkBase + dWl);
#pragma unroll
    for (int s = 0; s < 16; s++) {
        int ac = (s >> 2) & 1, bc = s & 1;
        int ng = s & 3;
        if (s + 1 < 16) {
            int ns = s + 1;
            if ((ns & 3) == 0) {
                uint32_t na = a0 + (uint32_t)((ns >> 2) * 32);
                ldsm4(fAh[(ns >> 2) & 1], na);
                ldsm4(fAl[(ns >> 2) & 1], na + bufsz);
            }
            uint32_t nb = bChunkBase + (uint32_t)((ns >> 2) * (16 * 136 * 2) + (ns & 3) * 32);
            ldsm4t(fBh[ns & 1], nb);
            ldsm4t(fBl[ns & 1], nb + dWl);
        }
        float* C0 = C[ng * 2];
        float* C1 = C[ng * 2 + 1];
        mma16816(C0, fAh[ac], fBh[bc]);
        mma16816(C1, fAh[ac], fBh[bc] + 2);
        mma16816(C0, fAl[ac], fBh[bc]);
        mma16816(C1, fAl[ac], fBh[bc] + 2);
        mma16816(C0, fAh[ac], fBl[bc]);
        mma16816(C1, fAh[ac], fBl[bc] + 2);
    }
}

// ===================== K3: GEMM1 hid = silu(lat_in @ W1) =====================
#define M1_SMEM ((2 * 256 * 136 + 4 * 128 * 72) * 2)
__global__ __launch_bounds__(512, 1) void k_mma1(const float* __restrict__ W1, int n_act) {
    extern __shared__ __nv_bfloat16 sb[];
    __nv_bfloat16* Wh = sb;
    __nv_bfloat16* Wl = Wh + 256 * 136;
    __nv_bfloat16* AB = Wl + 256 * 136;
    int tid = threadIdx.x, wid = tid >> 5, lane = tid & 31;
    int base = blockIdx.y * 128;
    for (int i = tid; i < 256 * 128; i += 512) {
        int k = i >> 7, n = i & 127;
        float w = (k < 232) ? W1[k * 256 + base + n] : 0.f;
        __nv_bfloat16 h = __float2bfloat16(w);
        Wh[k * 136 + n] = h;
        Wl[k * 136 + n] = __float2bfloat16(w - __bfloat162float(h));
    }
    uint32_t aWh = s2u(Wh);
    uint32_t dWl = (uint32_t)(256 * 136 * 2);
    uint32_t aA0h = s2u(AB);
    uint32_t bufsz = (uint32_t)(128 * 72 * 2);
    int warp_m = wid & 7, warp_n = wid >> 3;
    int ntile = (n_act + 127) >> 7;
    int arow = warp_m * 16 + (lane & 15);
    int acolb = (lane >> 4) << 3;
    uint32_t aBaseW = (uint32_t)((arow * 72 + acolb) * 2);
    uint32_t bBaseW = (uint32_t)(((lane & 15) * 136 + warp_n * 64 + acolb) * 2);
    __syncthreads();
    for (int tile = blockIdx.x; tile < ntile; tile += gridDim.x) {
        int nt = tile + gridDim.x;
        if (nt < ntile) {
            const char* p = (const char*)(g_liah + (size_t)nt * 128 * 256);
            const char* q = (const char*)(g_lial + (size_t)nt * 128 * 256);
            pf_l2(p + (size_t)tid * 128); pf_l2(q + (size_t)tid * 128);
        }
        float C[8][4];
#pragma unroll
        for (int b = 0; b < 8; b++)
#pragma unroll
            for (int c = 0; c < 4; c++) C[b][c] = 0.f;
        stage_chunk(g_liah, g_lial, aA0h, aA0h + bufsz, tile, 0, n_act, tid); CP_COMMIT();
        stage_chunk(g_liah, g_lial, aA0h + 2 * bufsz, aA0h + 3 * bufsz, tile, 1, n_act, tid); CP_COMMIT();
#pragma unroll 1
        for (int ch = 0; ch < 4; ch++) {
            if (ch < 3) CP_WAIT1(); else CP_WAIT0();
            __syncthreads();
            uint32_t bh = aA0h + (uint32_t)(ch & 1) * 2 * bufsz;
            chunk_mma(C, bh, bufsz, aBaseW, aWh + bBaseW + (uint32_t)(ch * 64 * 136 * 2), dWl);
            __syncthreads();
            if (ch + 2 < 4) {
                uint32_t nb = aA0h + (uint32_t)(ch & 1) * 2 * bufsz;
                stage_chunk(g_liah, g_lial, nb, nb + bufsz, tile, ch + 2, n_act, tid);
                CP_COMMIT();
            }
        }
#pragma unroll
        for (int p = 0; p < 2; p++) {
            int row = tile * 128 + warp_m * 16 + (lane >> 2) + p * 8;
            if (row < n_act) {
#pragma unroll
                for (int n8 = 0; n8 < 8; n8++) {
                    float v0 = C[n8][p * 2], v1 = C[n8][p * 2 + 1];
                    v0 = v0 * sigm(v0); v1 = v1 * sigm(v1);
                    uint32_t hw, lw;
                    split2(v0, v1, hw, lw);
                    int col = base + warp_n * 64 + n8 * 8 + (lane & 3) * 2;
                    *(uint32_t*)&g_hidh[(size_t)row * 256 + col] = hw;
                    *(uint32_t*)&g_hidl[(size_t)row * 256 + col] = lw;
                }
            }
        }
    }
}

// ===================== K4: GEMM2 out = (hid @ W2) * cutoff =====================
#define M2_SMEM ((2 * 256 * 136 + 4 * 128 * 72) * 2)
__global__ __launch_bounds__(512, 1) void k_mma2(
    const float* __restrict__ W2, const int* __restrict__ act,
    const float* __restrict__ cutoff, float* __restrict__ out_lat, int n_act) {
    extern __shared__ __nv_bfloat16 sb[];
    __nv_bfloat16* Wh = sb;
    __nv_bfloat16* Wl = Wh + 256 * 136;
    __nv_bfloat16* AB = Wl + 256 * 136;
    int tid = threadIdx.x, wid = tid >> 5, lane = tid & 31;
    for (int i = tid; i < 256 * 128; i += 512) {
        int k = i >> 7, n = i & 127;
        float w = W2[k * 128 + n];
        __nv_bfloat16 h = __float2bfloat16(w);
        Wh[k * 136 + n] = h;
        Wl[k * 136 + n] = __float2bfloat16(w - __bfloat162float(h));
    }
    uint32_t aWh = s2u(Wh);
    uint32_t dWl = (uint32_t)(256 * 136 * 2);
    uint32_t aA0h = s2u(AB);
    uint32_t bufsz = (uint32_t)(128 * 72 * 2);
    int warp_m = wid & 7, warp_n = wid >> 3;
    int ntile = (n_act + 127) >> 7;
    int arow = warp_m * 16 + (lane & 15);
    int acolb = (lane >> 4) << 3;
    uint32_t aBaseW = (uint32_t)((arow * 72 + acolb) * 2);
    uint32_t bBaseW = (uint32_t)(((lane & 15) * 136 + warp_n * 64 + acolb) * 2);
    __syncthreads();
    for (int tile = blockIdx.x; tile < ntile; tile += gridDim.x) {
        int nt = tile + gridDim.x;
        if (nt < ntile) {
            const char* ph = (const char*)(g_hidh + (size_t)nt * 128 * 256);
            const char* pl = (const char*)(g_hidl + (size_t)nt * 128 * 256);
            pf_l2(ph + (size_t)tid * 128); pf_l2(pl + (size_t)tid * 128);
        }
        float C[8][4];
#pragma unroll
        for (int b = 0; b < 8; b++)
#pragma unroll
            for (int c = 0; c < 4; c++) C[b][c] = 0.f;
        stage_chunk(g_hidh, g_hidl, aA0h, aA0h + bufsz, tile, 0, n_act, tid); CP_COMMIT();
        stage_chunk(g_hidh, g_hidl, aA0h + 2 * bufsz, aA0h + 3 * bufsz, tile, 1, n_act, tid); CP_COMMIT();
#pragma unroll 1
        for (int ch = 0; ch < 4; ch++) {
            if (ch < 3) CP_WAIT1(); else CP_WAIT0();
            __syncthreads();
            uint32_t bh = aA0h + (uint32_t)(ch & 1) * 2 * bufsz;
            chunk_mma(C, bh, bufsz, aBaseW, aWh + bBaseW + (uint32_t)(ch * 64 * 136 * 2), dWl);
            __syncthreads();
            if (ch + 2 < 4) {
                uint32_t nb = aA0h + (uint32_t)(ch & 1) * 2 * bufsz;
                stage_chunk(g_hidh, g_hidl, nb, nb + bufsz, tile, ch + 2, n_act, tid);
                CP_COMMIT();
            }
        }
#pragma unroll
        for (int p = 0; p < 2; p++) {
            int eg = tile * 128 + warp_m * 16 + (lane >> 2) + p * 8;
            if (eg < n_act) {
                int ae = act[eg];
                float cc = cutoff[ae];
                float* o = out_lat + (size_t)ae * 128;
#pragma unroll
                for (int n8 = 0; n8 < 8; n8++) {
                    int col = warp_n * 64 + n8 * 8 + (lane & 3) * 2;
                    float2 v;
                    v.x = C[n8][p * 2] * cc;
                    v.y = C[n8][p * 2 + 1] * cc;
                    *(float2*)(o + col) = v;
                }
            }
        }
    }
}

// ===================== launcher =====================
extern "C" void kernel_launch(void* const* d_in, const int* in_sizes, int n_in,
                              void* d_out, int out_size) {
    const float* latents   = (const float*)d_in[0];
    const float* node_feat = (const float*)d_in[1];
    const float* onehot    = (const float*)d_in[2];
    const float* edge_feat = (const float*)d_in[3];
    const float* edge_sh   = (const float*)d_in[4];
    const int*   edge_idx  = (const int*)d_in[5];
    const float* cutoff    = (const float*)d_in[6];
    const int*   act       = (const int*)d_in[7];
    const float* n_gs = (const float*)d_in[8];
    const float* n_bs = (const float*)d_in[9];
    const float* n_gv = (const float*)d_in[10];
    const float* e_gs = (const float*)d_in[11];
    const float* e_bs = (const float*)d_in[12];
    const float* e_gv = (const float*)d_in[13];
    const float* lg   = (const float*)d_in[14];
    const float* lb   = (const float*)d_in[15];
    const float* Wa   = (const float*)d_in[16];
    const float* Wb   = (const float*)d_in[17];
    const float* Wc   = (const float*)d_in[18];
    const float* Wd   = (const float*)d_in[19];
    const float* Wps  = (const float*)d_in[20];
    const float* Wpv  = (const float*)d_in[21];
    const float* We   = (const float*)d_in[22];
    const float* W1   = (const float*)d_in[23];
    const float* W2   = (const float*)d_in[24];
    const float* Wrs  = (const float*)d_in[25];
    const float* Wrv  = (const float*)d_in[26];

    int n_nodes = in_sizes[1] / DIMX;
    int n_act   = in_sizes[7];
    int n_edges = in_sizes[6];

    float* out_edge = (float*)d_out;
    float* out_lat  = out_edge + (size_t)n_act * DIMX;

    cudaFuncSetAttribute(k_edge_a, cudaFuncAttributeMaxDynamicSharedMemorySize, SMEM_A);
    cudaFuncSetAttribute(k_edge_b, cudaFuncAttributeMaxDynamicSharedMemorySize, SMEM_B);
    cudaFuncSetAttribute(k_mma1,   cudaFuncAttributeMaxDynamicSharedMemorySize, M1_SMEM);
    cudaFuncSetAttribute(k_mma2,   cudaFuncAttributeMaxDynamicSharedMemorySize, M2_SMEM);

    cudaMemcpyAsync(out_lat, latents, (size_t)n_edges * 128 * sizeof(float),
                    cudaMemcpyDeviceToDevice, 0);

    int nb1 = (n_nodes * 32 + 255) / 256;
    k_node_norm<<<nb1, 256>>>(node_feat, n_gs, n_bs, n_gv, n_nodes);

    k_edge_a<<<148, EA_T, SMEM_A>>>(edge_feat, edge_sh, edge_idx, act, onehot,
                                    e_gs, e_bs, e_gv, Wa, Wb, Wc, Wd, n_act, n_edges);

    k_edge_b<<<148, EB_T, SMEM_B>>>(latents, edge_feat, act, lg, lb,
                                    We, Wps, Wpv, Wrs, Wrv, out_edge, n_act);

    k_mma1<<<dim3(148, 2), 512, M1_SMEM>>>(W1, n_act);

    k_mma2<<<148, 512, M2_SMEM>>>(W2, act, cutoff, out_lat, n_act);
}